// round 1
// baseline (speedup 1.0000x reference)
#include <cuda_runtime.h>
#include <math.h>

#define BB 8
#define SS 1024
#define DD 1024
#define HH 16
#define HD 64

// Scratch (device globals: allocation-free rule workaround)
__device__ float g_q[(size_t)BB * SS * DD];
__device__ float g_k[(size_t)BB * SS * DD];
__device__ float g_v[(size_t)BB * SS * DD];
__device__ float g_ao[(size_t)BB * SS * DD];

// ---------------------------------------------------------------------------
// C[M,N] = A[M,K] @ W[N,K]^T + bias[N]
// head_layout=1: write C in (b, h, s, hd) layout (b = m>>10, s = m&1023,
//                h = n>>6, hd = n&63)
// Tiles: 128x128 block, 16-wide K slices, 8x8 per thread, 256 threads.
// ---------------------------------------------------------------------------
__global__ __launch_bounds__(256) void sgemm_bias(
    const float* __restrict__ A, const float* __restrict__ W,
    const float* __restrict__ bias, float* __restrict__ C,
    int M, int N, int K, int head_layout)
{
    __shared__ float As[16][132];
    __shared__ float Ws[16][132];

    const int tid = threadIdx.x;
    const int ml = (tid >> 4) * 8;   // local row
    const int nl = (tid & 15) * 8;   // local col

    const float* Ab = A + (size_t)(blockIdx.y * 128) * K;
    const float* Wb = W + (size_t)(blockIdx.x * 128) * K;

    float acc[8][8];
#pragma unroll
    for (int i = 0; i < 8; i++)
#pragma unroll
        for (int j = 0; j < 8; j++) acc[i][j] = 0.0f;

    for (int kt = 0; kt < K; kt += 16) {
        // Load 128x16 tiles of A and W, transposed into smem ([k][m]).
#pragma unroll
        for (int i = 0; i < 2; i++) {
            int idx = tid + i * 256;            // float4 index, 512 total
            int r = idx >> 2;
            int c4 = (idx & 3) * 4;
            float4 ta = *(const float4*)(Ab + (size_t)r * K + kt + c4);
            float4 tw = *(const float4*)(Wb + (size_t)r * K + kt + c4);
            As[c4 + 0][r] = ta.x; As[c4 + 1][r] = ta.y;
            As[c4 + 2][r] = ta.z; As[c4 + 3][r] = ta.w;
            Ws[c4 + 0][r] = tw.x; Ws[c4 + 1][r] = tw.y;
            Ws[c4 + 2][r] = tw.z; Ws[c4 + 3][r] = tw.w;
        }
        __syncthreads();

#pragma unroll
        for (int k = 0; k < 16; k++) {
            float4 a0 = *(float4*)&As[k][ml];
            float4 a1 = *(float4*)&As[k][ml + 4];
            float4 b0 = *(float4*)&Ws[k][nl];
            float4 b1 = *(float4*)&Ws[k][nl + 4];
            float av[8] = {a0.x, a0.y, a0.z, a0.w, a1.x, a1.y, a1.z, a1.w};
            float bv[8] = {b0.x, b0.y, b0.z, b0.w, b1.x, b1.y, b1.z, b1.w};
#pragma unroll
            for (int i = 0; i < 8; i++)
#pragma unroll
                for (int j = 0; j < 8; j++)
                    acc[i][j] = fmaf(av[i], bv[j], acc[i][j]);
        }
        __syncthreads();
    }

    // Epilogue
    const int m0 = blockIdx.y * 128 + ml;
    const int n0 = blockIdx.x * 128 + nl;
    float4 bb0 = *(const float4*)(bias + n0);
    float4 bb1 = *(const float4*)(bias + n0 + 4);

#pragma unroll
    for (int i = 0; i < 8; i++) {
        int m = m0 + i;
        float4 o0 = make_float4(acc[i][0] + bb0.x, acc[i][1] + bb0.y,
                                acc[i][2] + bb0.z, acc[i][3] + bb0.w);
        float4 o1 = make_float4(acc[i][4] + bb1.x, acc[i][5] + bb1.y,
                                acc[i][6] + bb1.z, acc[i][7] + bb1.w);
        size_t base;
        if (head_layout) {
            int bI = m >> 10, sI = m & 1023;
            int hI = n0 >> 6, hd = n0 & 63;     // n0..n0+7 stay in one head
            base = (((size_t)(bI * HH + hI) * SS + sI) * HD + hd);
        } else {
            base = (size_t)m * N + n0;
        }
        *(float4*)(C + base) = o0;
        *(float4*)(C + base + 4) = o1;
    }
}

// ---------------------------------------------------------------------------
// Flash attention with adapter merge.
//   merged = alpha * (q.k / 8) + (1-alpha) * syn[h,q,k];  mask==0 -> -1e9
// Q tile 64 rows x K tile 64 cols per iteration, online softmax.
// 256 threads as 16x16; thread owns 4 q-rows x 4 k-cols (scores) and
// 4 q-rows x 4 hd-cols (output accumulator).
// ---------------------------------------------------------------------------
__global__ __launch_bounds__(256) void attn_kernel(
    const float* __restrict__ gq, const float* __restrict__ gk,
    const float* __restrict__ gv, const int* __restrict__ mask,
    const float* __restrict__ syn, const float* __restrict__ alpha_param,
    float* __restrict__ out)
{
    extern __shared__ float sm[];
    float (*Qs)[68] = (float(*)[68])sm;
    float (*Ks)[68] = (float(*)[68])(sm + 64 * 68);
    float (*Vs)[68] = (float(*)[68])(sm + 2 * 64 * 68);
    float (*Ps)[68] = (float(*)[68])(sm + 3 * 64 * 68);

    const int tid = threadIdx.x;
    const int tx = tid & 15;
    const int ty = tid >> 4;
    const int b = blockIdx.y >> 4;
    const int h = blockIdx.y & 15;
    const int qbase = blockIdx.x * 64;

    const float alpha = 1.0f / (1.0f + __expf(-alpha_param[0]));
    const float sA = alpha * 0.125f;     // alpha / sqrt(HD)
    const float beta = 1.0f - alpha;

    const float* qptr = gq + ((size_t)(b * HH + h) * SS + qbase) * HD;
    const float* kptr = gk + (size_t)(b * HH + h) * SS * HD;
    const float* vptr = gv + (size_t)(b * HH + h) * SS * HD;

#pragma unroll
    for (int i = 0; i < 4; i++) {
        int idx = tid + i * 256;
        int r = idx >> 4, c = (idx & 15) * 4;
        *(float4*)&Qs[r][c] = *(const float4*)(qptr + r * HD + c);
    }

    float m_i[4] = {-INFINITY, -INFINITY, -INFINITY, -INFINITY};
    float l_i[4] = {0.f, 0.f, 0.f, 0.f};
    float O[4][4];
#pragma unroll
    for (int r = 0; r < 4; r++)
#pragma unroll
        for (int c = 0; c < 4; c++) O[r][c] = 0.f;

    for (int kb = 0; kb < SS; kb += 64) {
#pragma unroll
        for (int i = 0; i < 4; i++) {
            int idx = tid + i * 256;
            int r = idx >> 4, c = (idx & 15) * 4;
            *(float4*)&Ks[r][c] = *(const float4*)(kptr + (size_t)(kb + r) * HD + c);
            *(float4*)&Vs[r][c] = *(const float4*)(vptr + (size_t)(kb + r) * HD + c);
        }
        __syncthreads();

        // scores: s[r][c] = Q[ty4+r] . K[tx4+c]
        float s[4][4];
#pragma unroll
        for (int r = 0; r < 4; r++)
#pragma unroll
            for (int c = 0; c < 4; c++) s[r][c] = 0.f;

#pragma unroll
        for (int d = 0; d < 64; d += 4) {
            float4 a0 = *(float4*)&Qs[ty * 4 + 0][d];
            float4 a1 = *(float4*)&Qs[ty * 4 + 1][d];
            float4 a2 = *(float4*)&Qs[ty * 4 + 2][d];
            float4 a3 = *(float4*)&Qs[ty * 4 + 3][d];
            float4 c0 = *(float4*)&Ks[tx * 4 + 0][d];
            float4 c1 = *(float4*)&Ks[tx * 4 + 1][d];
            float4 c2 = *(float4*)&Ks[tx * 4 + 2][d];
            float4 c3 = *(float4*)&Ks[tx * 4 + 3][d];
#define DOT4(sv, A, C) \
            sv = fmaf(A.x, C.x, sv); sv = fmaf(A.y, C.y, sv); \
            sv = fmaf(A.z, C.z, sv); sv = fmaf(A.w, C.w, sv);
            DOT4(s[0][0], a0, c0) DOT4(s[0][1], a0, c1) DOT4(s[0][2], a0, c2) DOT4(s[0][3], a0, c3)
            DOT4(s[1][0], a1, c0) DOT4(s[1][1], a1, c1) DOT4(s[1][2], a1, c2) DOT4(s[1][3], a1, c3)
            DOT4(s[2][0], a2, c0) DOT4(s[2][1], a2, c1) DOT4(s[2][2], a2, c2) DOT4(s[2][3], a2, c3)
            DOT4(s[3][0], a3, c0) DOT4(s[3][1], a3, c1) DOT4(s[3][2], a3, c2) DOT4(s[3][3], a3, c3)
#undef DOT4
        }

        // merge adapter + mask, online softmax update
#pragma unroll
        for (int r = 0; r < 4; r++) {
            int qr = qbase + ty * 4 + r;
            float4 sy = *(const float4*)(syn + ((size_t)h * SS + qr) * SS + kb + tx * 4);
            int4 mk = *(const int4*)(mask + ((size_t)b * SS + qr) * SS + kb + tx * 4);
            s[r][0] = mk.x ? fmaf(s[r][0], sA, beta * sy.x) : -1.0e9f;
            s[r][1] = mk.y ? fmaf(s[r][1], sA, beta * sy.y) : -1.0e9f;
            s[r][2] = mk.z ? fmaf(s[r][2], sA, beta * sy.z) : -1.0e9f;
            s[r][3] = mk.w ? fmaf(s[r][3], sA, beta * sy.w) : -1.0e9f;

            float mx = fmaxf(fmaxf(s[r][0], s[r][1]), fmaxf(s[r][2], s[r][3]));
#pragma unroll
            for (int off = 8; off; off >>= 1)
                mx = fmaxf(mx, __shfl_xor_sync(0xffffffffu, mx, off));
            float mnew = fmaxf(m_i[r], mx);
            float scale = __expf(m_i[r] - mnew);   // 0 when m_i == -inf
            m_i[r] = mnew;

            float rs = 0.f;
#pragma unroll
            for (int c = 0; c < 4; c++) {
                s[r][c] = __expf(s[r][c] - mnew);
                rs += s[r][c];
            }
#pragma unroll
            for (int off = 8; off; off >>= 1)
                rs += __shfl_xor_sync(0xffffffffu, rs, off);
            l_i[r] = l_i[r] * scale + rs;
#pragma unroll
            for (int c = 0; c < 4; c++) O[r][c] *= scale;

            *(float4*)&Ps[ty * 4 + r][tx * 4] =
                make_float4(s[r][0], s[r][1], s[r][2], s[r][3]);
        }
        __syncthreads();

        // O += P @ V   (thread: 4 q-rows x 4 hd-cols at tx*4)
#pragma unroll
        for (int k2 = 0; k2 < 64; k2 += 4) {
            float4 p0 = *(float4*)&Ps[ty * 4 + 0][k2];
            float4 p1 = *(float4*)&Ps[ty * 4 + 1][k2];
            float4 p2 = *(float4*)&Ps[ty * 4 + 2][k2];
            float4 p3 = *(float4*)&Ps[ty * 4 + 3][k2];
            float4 v0 = *(float4*)&Vs[k2 + 0][tx * 4];
            float4 v1 = *(float4*)&Vs[k2 + 1][tx * 4];
            float4 v2 = *(float4*)&Vs[k2 + 2][tx * 4];
            float4 v3 = *(float4*)&Vs[k2 + 3][tx * 4];
#define PVROW(r, P) \
            O[r][0] = fmaf(P.x, v0.x, O[r][0]); O[r][1] = fmaf(P.x, v0.y, O[r][1]); \
            O[r][2] = fmaf(P.x, v0.z, O[r][2]); O[r][3] = fmaf(P.x, v0.w, O[r][3]); \
            O[r][0] = fmaf(P.y, v1.x, O[r][0]); O[r][1] = fmaf(P.y, v1.y, O[r][1]); \
            O[r][2] = fmaf(P.y, v1.z, O[r][2]); O[r][3] = fmaf(P.y, v1.w, O[r][3]); \
            O[r][0] = fmaf(P.z, v2.x, O[r][0]); O[r][1] = fmaf(P.z, v2.y, O[r][1]); \
            O[r][2] = fmaf(P.z, v2.z, O[r][2]); O[r][3] = fmaf(P.z, v2.w, O[r][3]); \
            O[r][0] = fmaf(P.w, v3.x, O[r][0]); O[r][1] = fmaf(P.w, v3.y, O[r][1]); \
            O[r][2] = fmaf(P.w, v3.z, O[r][2]); O[r][3] = fmaf(P.w, v3.w, O[r][3]);
            PVROW(0, p0) PVROW(1, p1) PVROW(2, p2) PVROW(3, p3)
#undef PVROW
        }
        __syncthreads();
    }

    // epilogue: normalize and write in (b, s, h*64+hd) layout
#pragma unroll
    for (int r = 0; r < 4; r++) {
        float inv = 1.0f / l_i[r];
        int qr = qbase + ty * 4 + r;
        float4 o4 = make_float4(O[r][0] * inv, O[r][1] * inv,
                                O[r][2] * inv, O[r][3] * inv);
        *(float4*)(out + ((size_t)b * SS + qr) * DD + h * HD + tx * 4) = o4;
    }
}

// ---------------------------------------------------------------------------
extern "C" void kernel_launch(void* const* d_in, const int* in_sizes, int n_in,
                              void* d_out, int out_size)
{
    const float* query  = (const float*)d_in[0];
    const float* key_in = (const float*)d_in[1];
    const float* value  = (const float*)d_in[2];
    const int*   mask   = (const int*)d_in[3];
    const float* Wq = (const float*)d_in[4];
    const float* bq = (const float*)d_in[5];
    const float* Wk = (const float*)d_in[6];
    const float* bk = (const float*)d_in[7];
    const float* Wv = (const float*)d_in[8];
    const float* bv = (const float*)d_in[9];
    const float* Wo = (const float*)d_in[10];
    const float* bo = (const float*)d_in[11];
    const float* syn = (const float*)d_in[12];
    const float* alpha_param = (const float*)d_in[13];
    float* out = (float*)d_out;

    float *pq, *pk, *pv, *pao;
    cudaGetSymbolAddress((void**)&pq, g_q);
    cudaGetSymbolAddress((void**)&pk, g_k);
    cudaGetSymbolAddress((void**)&pv, g_v);
    cudaGetSymbolAddress((void**)&pao, g_ao);

    const int M = BB * SS, N = DD, K = DD;
    dim3 gg(N / 128, M / 128);   // (8, 64)

    sgemm_bias<<<gg, 256>>>(query,  Wq, bq, pq, M, N, K, 1);
    sgemm_bias<<<gg, 256>>>(key_in, Wk, bk, pk, M, N, K, 1);
    sgemm_bias<<<gg, 256>>>(value,  Wv, bv, pv, M, N, K, 1);

    const int smem_bytes = 4 * 64 * 68 * (int)sizeof(float);   // 69632
    cudaFuncSetAttribute(attn_kernel,
                         cudaFuncAttributeMaxDynamicSharedMemorySize, smem_bytes);
    attn_kernel<<<dim3(SS / 64, BB * HH), 256, smem_bytes>>>(
        pq, pk, pv, mask, syn, alpha_param, pao);

    sgemm_bias<<<gg, 256>>>(pao, Wo, bo, out, M, N, K, 0);
}

// round 2
// speedup vs baseline: 1.7589x; 1.7589x over previous
#include <cuda_runtime.h>
#include <math.h>
#include <stdint.h>

#define BB 8
#define SS 1024
#define DD 1024
#define HH 16
#define HD 64

// Scratch (device globals: allocation-free rule workaround)
__device__ float g_q[(size_t)BB * SS * DD];
__device__ float g_k[(size_t)BB * SS * DD];
__device__ float g_v[(size_t)BB * SS * DD];
__device__ float g_ao[(size_t)BB * SS * DD];

__device__ __forceinline__ uint32_t f2tf(float x) {
    uint32_t y;
    asm("cvt.rna.tf32.f32 %0, %1;" : "=r"(y) : "f"(x));
    return y;
}

// D += A(m16k8) * B(k8n8), tf32 in, f32 accum
__device__ __forceinline__ void mma8(float* d, const uint32_t* a, const uint32_t* b) {
    asm volatile(
        "mma.sync.aligned.m16n8k8.row.col.f32.tf32.tf32.f32 "
        "{%0,%1,%2,%3}, {%4,%5,%6,%7}, {%8,%9}, {%0,%1,%2,%3};"
        : "+f"(d[0]), "+f"(d[1]), "+f"(d[2]), "+f"(d[3])
        : "r"(a[0]), "r"(a[1]), "r"(a[2]), "r"(a[3]), "r"(b[0]), "r"(b[1]));
}

// ---------------------------------------------------------------------------
// C[M,N] = A[M,K] @ W[N,K]^T + bias[N]   (tf32 tensor-core version)
// Block 128x128, 8 warps (2x4), warp tile 64x32, k-slice 16.
// head_layout=1: write C in (b,h,s,hd) layout.
// ---------------------------------------------------------------------------
__global__ __launch_bounds__(256) void gemm_tf32(
    const float* __restrict__ A, const float* __restrict__ W,
    const float* __restrict__ bias, float* __restrict__ C,
    int M, int N, int K, int head_layout)
{
    __shared__ uint32_t As[128 * 20];   // [m][k], stride 20 (conflict-free frags)
    __shared__ uint32_t Ws[128 * 20];   // [n][k]

    const int tid  = threadIdx.x;
    const int lane = tid & 31;
    const int warp = tid >> 5;
    const int wm   = warp >> 2;     // 0..1
    const int wn   = warp & 3;      // 0..3
    const int lr   = lane >> 2;     // 0..7
    const int lc   = lane & 3;      // 0..3

    const float* Ab = A + (size_t)(blockIdx.y * 128) * K;
    const float* Wb = W + (size_t)(blockIdx.x * 128) * K;

    float acc[4][4][4];
#pragma unroll
    for (int mt = 0; mt < 4; mt++)
#pragma unroll
        for (int nt = 0; nt < 4; nt++)
#pragma unroll
            for (int r = 0; r < 4; r++) acc[mt][nt][r] = 0.0f;

    for (int kt = 0; kt < K; kt += 16) {
#pragma unroll
        for (int i = 0; i < 2; i++) {
            int id = tid + i * 256;          // 0..511 float4 slots
            int r  = id >> 2;
            int c4 = (id & 3) * 4;
            float4 ta = *(const float4*)(Ab + (size_t)r * K + kt + c4);
            float4 tw = *(const float4*)(Wb + (size_t)r * K + kt + c4);
            uint4 ua = make_uint4(f2tf(ta.x), f2tf(ta.y), f2tf(ta.z), f2tf(ta.w));
            uint4 uw = make_uint4(f2tf(tw.x), f2tf(tw.y), f2tf(tw.z), f2tf(tw.w));
            *(uint4*)&As[r * 20 + c4] = ua;
            *(uint4*)&Ws[r * 20 + c4] = uw;
        }
        __syncthreads();

#pragma unroll
        for (int ks = 0; ks < 2; ks++) {
            uint32_t af[4][4], bf[4][2];
#pragma unroll
            for (int mt = 0; mt < 4; mt++) {
                int rb = wm * 64 + mt * 16;
                af[mt][0] = As[(rb + lr)     * 20 + ks * 8 + lc];
                af[mt][1] = As[(rb + lr + 8) * 20 + ks * 8 + lc];
                af[mt][2] = As[(rb + lr)     * 20 + ks * 8 + lc + 4];
                af[mt][3] = As[(rb + lr + 8) * 20 + ks * 8 + lc + 4];
            }
#pragma unroll
            for (int nt = 0; nt < 4; nt++) {
                int nb = wn * 32 + nt * 8;
                bf[nt][0] = Ws[(nb + lr) * 20 + ks * 8 + lc];
                bf[nt][1] = Ws[(nb + lr) * 20 + ks * 8 + lc + 4];
            }
#pragma unroll
            for (int mt = 0; mt < 4; mt++)
#pragma unroll
                for (int nt = 0; nt < 4; nt++)
                    mma8(acc[mt][nt], af[mt], bf[nt]);
        }
        __syncthreads();
    }

    // Epilogue: D frag (row lr / lr+8, cols 2lc / 2lc+1)
#pragma unroll
    for (int mt = 0; mt < 4; mt++) {
#pragma unroll
        for (int nt = 0; nt < 4; nt++) {
            int m0 = blockIdx.y * 128 + wm * 64 + mt * 16 + lr;
            int n0 = blockIdx.x * 128 + wn * 32 + nt * 8 + 2 * lc;
            float bx = bias[n0], by = bias[n0 + 1];
            float2 r0 = make_float2(acc[mt][nt][0] + bx, acc[mt][nt][1] + by);
            float2 r1 = make_float2(acc[mt][nt][2] + bx, acc[mt][nt][3] + by);
            if (head_layout) {
                int hI = n0 >> 6, hd = n0 & 63;
                int bI0 = m0 >> 10, sI0 = m0 & 1023;
                int m1 = m0 + 8;
                int bI1 = m1 >> 10, sI1 = m1 & 1023;
                *(float2*)(C + (((size_t)(bI0 * HH + hI) * SS + sI0) * HD + hd)) = r0;
                *(float2*)(C + (((size_t)(bI1 * HH + hI) * SS + sI1) * HD + hd)) = r1;
            } else {
                *(float2*)(C + (size_t)m0 * N + n0) = r0;
                *(float2*)(C + (size_t)(m0 + 8) * N + n0) = r1;
            }
        }
    }
}

// ---------------------------------------------------------------------------
// Flash attention with adapter merge, tf32 tensor cores.
// Block: 256 threads = 8 warps; q-tile 128 rows (16/warp); kv-tile 64.
// Q fragments live in registers for the whole kernel.
// merged = alpha*(q.k/8) + (1-alpha)*syn ; mask==0 -> -1e9 ; online softmax.
// ---------------------------------------------------------------------------
__global__ __launch_bounds__(256) void attn_tf32(
    const float* __restrict__ gq, const float* __restrict__ gk,
    const float* __restrict__ gv, const int* __restrict__ mask,
    const float* __restrict__ syn, const float* __restrict__ alpha_param,
    float* __restrict__ out)
{
    extern __shared__ uint32_t sm[];
    uint32_t* Ks = sm;                        // [64][68]
    uint32_t* Vs = sm + 64 * 68;              // [64][72]
    uint32_t* Ps = sm + 64 * 68 + 64 * 72;    // [128][68] (warp w owns rows w*16..)

    const int tid  = threadIdx.x;
    const int lane = tid & 31;
    const int warp = tid >> 5;
    const int lr   = lane >> 2;
    const int lc   = lane & 3;
    const int b = blockIdx.y >> 4;
    const int h = blockIdx.y & 15;
    const int qbase = blockIdx.x * 128;

    const float alpha = 1.0f / (1.0f + __expf(-alpha_param[0]));
    const float sA = alpha * 0.125f;
    const float beta = 1.0f - alpha;

    const float* qptr = gq + ((size_t)(b * HH + h) * SS + qbase) * HD;
    const float* kptr = gk + (size_t)(b * HH + h) * SS * HD;
    const float* vptr = gv + (size_t)(b * HH + h) * SS * HD;

    // Stage Q (128x64) through Ps, extract per-warp fragments into registers.
#pragma unroll
    for (int i = 0; i < 8; i++) {
        int id = tid + i * 256;           // 0..2047 float4 slots
        int r  = id >> 4;
        int c4 = (id & 15) * 4;
        float4 t = *(const float4*)(qptr + (size_t)r * HD + c4);
        *(uint4*)&Ps[r * 68 + c4] = make_uint4(f2tf(t.x), f2tf(t.y), f2tf(t.z), f2tf(t.w));
    }
    __syncthreads();

    uint32_t qf[8][4];
    {
        int rb = warp * 16;
#pragma unroll
        for (int kk = 0; kk < 8; kk++) {
            qf[kk][0] = Ps[(rb + lr)     * 68 + kk * 8 + lc];
            qf[kk][1] = Ps[(rb + lr + 8) * 68 + kk * 8 + lc];
            qf[kk][2] = Ps[(rb + lr)     * 68 + kk * 8 + lc + 4];
            qf[kk][3] = Ps[(rb + lr + 8) * 68 + kk * 8 + lc + 4];
        }
    }

    float O[8][4];
#pragma unroll
    for (int nt = 0; nt < 8; nt++)
#pragma unroll
        for (int r = 0; r < 4; r++) O[nt][r] = 0.0f;
    float m0r = -INFINITY, m1r = -INFINITY, l0 = 0.0f, l1 = 0.0f;

    const int qr0 = qbase + warp * 16 + lr;
    const int qr1 = qr0 + 8;
    const float* syn0 = syn + ((size_t)h * SS + qr0) * SS;
    const float* syn1 = syn + ((size_t)h * SS + qr1) * SS;
    const int* mk0 = mask + ((size_t)b * SS + qr0) * SS;
    const int* mk1 = mask + ((size_t)b * SS + qr1) * SS;

    for (int kb = 0; kb < SS; kb += 64) {
        // Load K,V tiles (64x64) as tf32
#pragma unroll
        for (int i = 0; i < 4; i++) {
            int id = tid + i * 256;        // 0..1023 float4 slots
            int r  = id >> 4;
            int c4 = (id & 15) * 4;
            float4 tk = *(const float4*)(kptr + (size_t)(kb + r) * HD + c4);
            float4 tv = *(const float4*)(vptr + (size_t)(kb + r) * HD + c4);
            *(uint4*)&Ks[r * 68 + c4] = make_uint4(f2tf(tk.x), f2tf(tk.y), f2tf(tk.z), f2tf(tk.w));
            *(uint4*)&Vs[r * 72 + c4] = make_uint4(f2tf(tv.x), f2tf(tv.y), f2tf(tv.z), f2tf(tv.w));
        }
        __syncthreads();

        // S = Q @ K^T  (8 n8-tiles of kv)
        float sacc[8][4];
#pragma unroll
        for (int nt = 0; nt < 8; nt++) {
            sacc[nt][0] = sacc[nt][1] = sacc[nt][2] = sacc[nt][3] = 0.0f;
#pragma unroll
            for (int kk = 0; kk < 8; kk++) {
                uint32_t bfr[2];
                bfr[0] = Ks[(nt * 8 + lr) * 68 + kk * 8 + lc];
                bfr[1] = Ks[(nt * 8 + lr) * 68 + kk * 8 + lc + 4];
                mma8(sacc[nt], qf[kk], bfr);
            }
        }

        // Merge adapter + mask; running row max
        float mx0 = -INFINITY, mx1 = -INFINITY;
#pragma unroll
        for (int nt = 0; nt < 8; nt++) {
            int cb = kb + nt * 8 + 2 * lc;
            float2 sy0 = *(const float2*)(syn0 + cb);
            float2 sy1 = *(const float2*)(syn1 + cb);
            int2 mm0 = *(const int2*)(mk0 + cb);
            int2 mm1 = *(const int2*)(mk1 + cb);
            sacc[nt][0] = mm0.x ? fmaf(sacc[nt][0], sA, beta * sy0.x) : -1.0e9f;
            sacc[nt][1] = mm0.y ? fmaf(sacc[nt][1], sA, beta * sy0.y) : -1.0e9f;
            sacc[nt][2] = mm1.x ? fmaf(sacc[nt][2], sA, beta * sy1.x) : -1.0e9f;
            sacc[nt][3] = mm1.y ? fmaf(sacc[nt][3], sA, beta * sy1.y) : -1.0e9f;
            mx0 = fmaxf(mx0, fmaxf(sacc[nt][0], sacc[nt][1]));
            mx1 = fmaxf(mx1, fmaxf(sacc[nt][2], sacc[nt][3]));
        }
        mx0 = fmaxf(mx0, __shfl_xor_sync(0xffffffffu, mx0, 1));
        mx0 = fmaxf(mx0, __shfl_xor_sync(0xffffffffu, mx0, 2));
        mx1 = fmaxf(mx1, __shfl_xor_sync(0xffffffffu, mx1, 1));
        mx1 = fmaxf(mx1, __shfl_xor_sync(0xffffffffu, mx1, 2));

        float mn0 = fmaxf(m0r, mx0), mn1 = fmaxf(m1r, mx1);
        float sc0 = __expf(m0r - mn0), sc1 = __expf(m1r - mn1);
        m0r = mn0; m1r = mn1;

        float rs0 = 0.0f, rs1 = 0.0f;
        {
            int rb = warp * 16;
#pragma unroll
            for (int nt = 0; nt < 8; nt++) {
                float p0 = __expf(sacc[nt][0] - mn0);
                float p1 = __expf(sacc[nt][1] - mn0);
                float p2 = __expf(sacc[nt][2] - mn1);
                float p3 = __expf(sacc[nt][3] - mn1);
                rs0 += p0 + p1;
                rs1 += p2 + p3;
                *(uint2*)&Ps[(rb + lr)     * 68 + nt * 8 + 2 * lc] = make_uint2(f2tf(p0), f2tf(p1));
                *(uint2*)&Ps[(rb + lr + 8) * 68 + nt * 8 + 2 * lc] = make_uint2(f2tf(p2), f2tf(p3));
            }
        }
        rs0 += __shfl_xor_sync(0xffffffffu, rs0, 1);
        rs0 += __shfl_xor_sync(0xffffffffu, rs0, 2);
        rs1 += __shfl_xor_sync(0xffffffffu, rs1, 1);
        rs1 += __shfl_xor_sync(0xffffffffu, rs1, 2);
        l0 = l0 * sc0 + rs0;
        l1 = l1 * sc1 + rs1;

#pragma unroll
        for (int nt = 0; nt < 8; nt++) {
            O[nt][0] *= sc0; O[nt][1] *= sc0;
            O[nt][2] *= sc1; O[nt][3] *= sc1;
        }

        __syncwarp();   // make P stores visible across lanes of this warp

        // O += P @ V
        uint32_t pf[8][4];
        {
            int rb = warp * 16;
#pragma unroll
            for (int kk = 0; kk < 8; kk++) {
                pf[kk][0] = Ps[(rb + lr)     * 68 + kk * 8 + lc];
                pf[kk][1] = Ps[(rb + lr + 8) * 68 + kk * 8 + lc];
                pf[kk][2] = Ps[(rb + lr)     * 68 + kk * 8 + lc + 4];
                pf[kk][3] = Ps[(rb + lr + 8) * 68 + kk * 8 + lc + 4];
            }
        }
#pragma unroll
        for (int nt = 0; nt < 8; nt++) {
#pragma unroll
            for (int kk = 0; kk < 8; kk++) {
                uint32_t bfr[2];
                bfr[0] = Vs[(kk * 8 + lc)     * 72 + nt * 8 + lr];
                bfr[1] = Vs[(kk * 8 + lc + 4) * 72 + nt * 8 + lr];
                mma8(O[nt], pf[kk], bfr);
            }
        }
        __syncthreads();
    }

    // Epilogue: normalize, write (b, s, h*64+hd)
    float inv0 = 1.0f / l0, inv1 = 1.0f / l1;
    float* o0 = out + ((size_t)b * SS + qr0) * DD + h * HD;
    float* o1 = out + ((size_t)b * SS + qr1) * DD + h * HD;
#pragma unroll
    for (int nt = 0; nt < 8; nt++) {
        int c = nt * 8 + 2 * lc;
        *(float2*)(o0 + c) = make_float2(O[nt][0] * inv0, O[nt][1] * inv0);
        *(float2*)(o1 + c) = make_float2(O[nt][2] * inv1, O[nt][3] * inv1);
    }
}

// ---------------------------------------------------------------------------
extern "C" void kernel_launch(void* const* d_in, const int* in_sizes, int n_in,
                              void* d_out, int out_size)
{
    const float* query  = (const float*)d_in[0];
    const float* key_in = (const float*)d_in[1];
    const float* value  = (const float*)d_in[2];
    const int*   mask   = (const int*)d_in[3];
    const float* Wq = (const float*)d_in[4];
    const float* bq = (const float*)d_in[5];
    const float* Wk = (const float*)d_in[6];
    const float* bk = (const float*)d_in[7];
    const float* Wv = (const float*)d_in[8];
    const float* bv = (const float*)d_in[9];
    const float* Wo = (const float*)d_in[10];
    const float* bo = (const float*)d_in[11];
    const float* syn = (const float*)d_in[12];
    const float* alpha_param = (const float*)d_in[13];
    float* out = (float*)d_out;

    float *pq, *pk, *pv, *pao;
    cudaGetSymbolAddress((void**)&pq, g_q);
    cudaGetSymbolAddress((void**)&pk, g_k);
    cudaGetSymbolAddress((void**)&pv, g_v);
    cudaGetSymbolAddress((void**)&pao, g_ao);

    const int M = BB * SS, N = DD, K = DD;
    dim3 gg(N / 128, M / 128);   // (8, 64)

    gemm_tf32<<<gg, 256>>>(query,  Wq, bq, pq, M, N, K, 1);
    gemm_tf32<<<gg, 256>>>(key_in, Wk, bk, pk, M, N, K, 1);
    gemm_tf32<<<gg, 256>>>(value,  Wv, bv, pv, M, N, K, 1);

    const int smem_bytes = (64 * 68 + 64 * 72 + 128 * 68) * (int)sizeof(uint32_t); // 70656
    cudaFuncSetAttribute(attn_tf32,
                         cudaFuncAttributeMaxDynamicSharedMemorySize, smem_bytes);
    attn_tf32<<<dim3(SS / 128, BB * HH), 256, smem_bytes>>>(
        pq, pk, pv, mask, syn, alpha_param, pao);

    gemm_tf32<<<gg, 256>>>(pao, Wo, bo, out, M, N, K, 0);
}

// round 3
// speedup vs baseline: 2.4926x; 1.4171x over previous
#include <cuda_runtime.h>
#include <math.h>
#include <stdint.h>

#define BB 8
#define SS 1024
#define DD 1024
#define HH 16
#define HD 64

// Scratch (device globals: allocation-free rule workaround)
__device__ float g_q[(size_t)BB * SS * DD];
__device__ float g_k[(size_t)BB * SS * DD];
__device__ float g_v[(size_t)BB * SS * DD];
__device__ float g_ao[(size_t)BB * SS * DD];

__device__ __forceinline__ uint32_t f2tf(float x) {
    uint32_t y;
    asm("cvt.rna.tf32.f32 %0, %1;" : "=r"(y) : "f"(x));
    return y;
}
__device__ __forceinline__ uint4 f2tf4(float4 t) {
    return make_uint4(f2tf(t.x), f2tf(t.y), f2tf(t.z), f2tf(t.w));
}

// D += A(m16k8) * B(k8n8), tf32 in, f32 accum
__device__ __forceinline__ void mma8(float* d, const uint32_t* a, const uint32_t* b) {
    asm volatile(
        "mma.sync.aligned.m16n8k8.row.col.f32.tf32.tf32.f32 "
        "{%0,%1,%2,%3}, {%4,%5,%6,%7}, {%8,%9}, {%0,%1,%2,%3};"
        : "+f"(d[0]), "+f"(d[1]), "+f"(d[2]), "+f"(d[3])
        : "r"(a[0]), "r"(a[1]), "r"(a[2]), "r"(a[3]), "r"(b[0]), "r"(b[1]));
}

// ---------------------------------------------------------------------------
// C[M,N] = A[M,K] @ W[N,K]^T + bias[N]   (tf32, register-prefetch pipelined)
// Block 128x128, 8 warps (2x4), warp tile 64x32, k-slice 16, 2 CTAs/SM.
// ---------------------------------------------------------------------------
__global__ __launch_bounds__(256, 2) void gemm_tf32(
    const float* __restrict__ A, const float* __restrict__ W,
    const float* __restrict__ bias, float* __restrict__ C,
    int M, int N, int K, int head_layout)
{
    __shared__ uint32_t As[128 * 20];   // [m][k], stride 20
    __shared__ uint32_t Ws[128 * 20];   // [n][k]

    const int tid  = threadIdx.x;
    const int lane = tid & 31;
    const int warp = tid >> 5;
    const int wm   = warp >> 2;
    const int wn   = warp & 3;
    const int lr   = lane >> 2;
    const int lc   = lane & 3;

    const int r0 = tid >> 2;            // 0..63
    const int c4 = (tid & 3) * 4;       // 0,4,8,12

    const float* Ab = A + (size_t)(blockIdx.y * 128) * K;
    const float* Wb = W + (size_t)(blockIdx.x * 128) * K;

    float acc[4][4][4];
#pragma unroll
    for (int mt = 0; mt < 4; mt++)
#pragma unroll
        for (int nt = 0; nt < 4; nt++)
#pragma unroll
            for (int r = 0; r < 4; r++) acc[mt][nt][r] = 0.0f;

    float4 pa0, pa1, pw0, pw1;
#define LDTILE(kt) { \
        pa0 = *(const float4*)(Ab + (size_t)r0        * K + (kt) + c4); \
        pa1 = *(const float4*)(Ab + (size_t)(r0 + 64) * K + (kt) + c4); \
        pw0 = *(const float4*)(Wb + (size_t)r0        * K + (kt) + c4); \
        pw1 = *(const float4*)(Wb + (size_t)(r0 + 64) * K + (kt) + c4); }
#define STTILE() { \
        *(uint4*)&As[r0 * 20 + c4]        = f2tf4(pa0); \
        *(uint4*)&As[(r0 + 64) * 20 + c4] = f2tf4(pa1); \
        *(uint4*)&Ws[r0 * 20 + c4]        = f2tf4(pw0); \
        *(uint4*)&Ws[(r0 + 64) * 20 + c4] = f2tf4(pw1); }

    LDTILE(0);
    STTILE();
    __syncthreads();

    for (int kt = 0; kt < K; kt += 16) {
        const bool more = (kt + 16) < K;
        if (more) LDTILE(kt + 16);

#pragma unroll
        for (int ks = 0; ks < 2; ks++) {
            uint32_t af[4][4], bf[4][2];
#pragma unroll
            for (int mt = 0; mt < 4; mt++) {
                int rb = wm * 64 + mt * 16;
                af[mt][0] = As[(rb + lr)     * 20 + ks * 8 + lc];
                af[mt][1] = As[(rb + lr + 8) * 20 + ks * 8 + lc];
                af[mt][2] = As[(rb + lr)     * 20 + ks * 8 + lc + 4];
                af[mt][3] = As[(rb + lr + 8) * 20 + ks * 8 + lc + 4];
            }
#pragma unroll
            for (int nt = 0; nt < 4; nt++) {
                int nb = wn * 32 + nt * 8;
                bf[nt][0] = Ws[(nb + lr) * 20 + ks * 8 + lc];
                bf[nt][1] = Ws[(nb + lr) * 20 + ks * 8 + lc + 4];
            }
#pragma unroll
            for (int mt = 0; mt < 4; mt++)
#pragma unroll
                for (int nt = 0; nt < 4; nt++)
                    mma8(acc[mt][nt], af[mt], bf[nt]);
        }
        __syncthreads();
        if (more) {
            STTILE();
            __syncthreads();
        }
    }
#undef LDTILE
#undef STTILE

    // Epilogue
#pragma unroll
    for (int mt = 0; mt < 4; mt++) {
#pragma unroll
        for (int nt = 0; nt < 4; nt++) {
            int m0 = blockIdx.y * 128 + wm * 64 + mt * 16 + lr;
            int n0 = blockIdx.x * 128 + wn * 32 + nt * 8 + 2 * lc;
            float bx = bias[n0], by = bias[n0 + 1];
            float2 rr0 = make_float2(acc[mt][nt][0] + bx, acc[mt][nt][1] + by);
            float2 rr1 = make_float2(acc[mt][nt][2] + bx, acc[mt][nt][3] + by);
            if (head_layout) {
                int hI = n0 >> 6, hd = n0 & 63;
                int bI0 = m0 >> 10, sI0 = m0 & 1023;
                int m1 = m0 + 8;
                int bI1 = m1 >> 10, sI1 = m1 & 1023;
                *(float2*)(C + (((size_t)(bI0 * HH + hI) * SS + sI0) * HD + hd)) = rr0;
                *(float2*)(C + (((size_t)(bI1 * HH + hI) * SS + sI1) * HD + hd)) = rr1;
            } else {
                *(float2*)(C + (size_t)m0 * N + n0) = rr0;
                *(float2*)(C + (size_t)(m0 + 8) * N + n0) = rr1;
            }
        }
    }
}

// ---------------------------------------------------------------------------
// Flash attention with adapter merge, tf32 tensor cores, 2 CTAs/SM.
// Block: 256 threads = 8 warps; q-tile 128 rows (16/warp); kv-tile 64.
// ---------------------------------------------------------------------------
__global__ __launch_bounds__(256, 2) void attn_tf32(
    const float* __restrict__ gq, const float* __restrict__ gk,
    const float* __restrict__ gv, const int* __restrict__ mask,
    const float* __restrict__ syn, const float* __restrict__ alpha_param,
    float* __restrict__ out)
{
    extern __shared__ uint32_t sm[];
    uint32_t* Ks = sm;                        // [64][68]
    uint32_t* Vs = sm + 64 * 68;              // [64][72]
    uint32_t* Ps = sm + 64 * 68 + 64 * 72;    // [128][68]

    const int tid  = threadIdx.x;
    const int lane = tid & 31;
    const int warp = tid >> 5;
    const int lr   = lane >> 2;
    const int lc   = lane & 3;
    const int b = blockIdx.y >> 4;
    const int h = blockIdx.y & 15;
    const int qbase = blockIdx.x * 128;

    const float alpha = 1.0f / (1.0f + __expf(-alpha_param[0]));
    const float sA = alpha * 0.125f;
    const float beta = 1.0f - alpha;

    const float* qptr = gq + ((size_t)(b * HH + h) * SS + qbase) * HD;
    const float* kptr = gk + (size_t)(b * HH + h) * SS * HD;
    const float* vptr = gv + (size_t)(b * HH + h) * SS * HD;

    // Stage Q (128x64) through Ps, extract per-warp fragments into registers.
#pragma unroll
    for (int i = 0; i < 8; i++) {
        int id = tid + i * 256;
        int r  = id >> 4;
        int c4 = (id & 15) * 4;
        float4 t = *(const float4*)(qptr + (size_t)r * HD + c4);
        *(uint4*)&Ps[r * 68 + c4] = f2tf4(t);
    }
    __syncthreads();

    uint32_t qf[8][4];
    {
        int rb = warp * 16;
#pragma unroll
        for (int kk = 0; kk < 8; kk++) {
            qf[kk][0] = Ps[(rb + lr)     * 68 + kk * 8 + lc];
            qf[kk][1] = Ps[(rb + lr + 8) * 68 + kk * 8 + lc];
            qf[kk][2] = Ps[(rb + lr)     * 68 + kk * 8 + lc + 4];
            qf[kk][3] = Ps[(rb + lr + 8) * 68 + kk * 8 + lc + 4];
        }
    }
    __syncthreads();

    float O[8][4];
#pragma unroll
    for (int nt = 0; nt < 8; nt++)
#pragma unroll
        for (int r = 0; r < 4; r++) O[nt][r] = 0.0f;
    float m0r = -INFINITY, m1r = -INFINITY, l0 = 0.0f, l1 = 0.0f;

    const int qr0 = qbase + warp * 16 + lr;
    const int qr1 = qr0 + 8;
    const float* syn0 = syn + ((size_t)h * SS + qr0) * SS;
    const float* syn1 = syn + ((size_t)h * SS + qr1) * SS;
    const int* mk0 = mask + ((size_t)b * SS + qr0) * SS;
    const int* mk1 = mask + ((size_t)b * SS + qr1) * SS;

    for (int kb = 0; kb < SS; kb += 64) {
        // Load K,V tiles (64x64) as tf32
#pragma unroll
        for (int i = 0; i < 4; i++) {
            int id = tid + i * 256;
            int r  = id >> 4;
            int c4 = (id & 15) * 4;
            float4 tk = *(const float4*)(kptr + (size_t)(kb + r) * HD + c4);
            float4 tv = *(const float4*)(vptr + (size_t)(kb + r) * HD + c4);
            *(uint4*)&Ks[r * 68 + c4] = f2tf4(tk);
            *(uint4*)&Vs[r * 72 + c4] = f2tf4(tv);
        }
        __syncthreads();

        // S = Q @ K^T
        float sacc[8][4];
#pragma unroll
        for (int nt = 0; nt < 8; nt++) {
            sacc[nt][0] = sacc[nt][1] = sacc[nt][2] = sacc[nt][3] = 0.0f;
#pragma unroll
            for (int kk = 0; kk < 8; kk++) {
                uint32_t bfr[2];
                bfr[0] = Ks[(nt * 8 + lr) * 68 + kk * 8 + lc];
                bfr[1] = Ks[(nt * 8 + lr) * 68 + kk * 8 + lc + 4];
                mma8(sacc[nt], qf[kk], bfr);
            }
        }

        // Merge adapter + mask; running row max
        float mx0 = -INFINITY, mx1 = -INFINITY;
#pragma unroll
        for (int nt = 0; nt < 8; nt++) {
            int cb = kb + nt * 8 + 2 * lc;
            float2 sy0 = *(const float2*)(syn0 + cb);
            float2 sy1 = *(const float2*)(syn1 + cb);
            int2 mm0 = *(const int2*)(mk0 + cb);
            int2 mm1 = *(const int2*)(mk1 + cb);
            sacc[nt][0] = mm0.x ? fmaf(sacc[nt][0], sA, beta * sy0.x) : -1.0e9f;
            sacc[nt][1] = mm0.y ? fmaf(sacc[nt][1], sA, beta * sy0.y) : -1.0e9f;
            sacc[nt][2] = mm1.x ? fmaf(sacc[nt][2], sA, beta * sy1.x) : -1.0e9f;
            sacc[nt][3] = mm1.y ? fmaf(sacc[nt][3], sA, beta * sy1.y) : -1.0e9f;
            mx0 = fmaxf(mx0, fmaxf(sacc[nt][0], sacc[nt][1]));
            mx1 = fmaxf(mx1, fmaxf(sacc[nt][2], sacc[nt][3]));
        }
        mx0 = fmaxf(mx0, __shfl_xor_sync(0xffffffffu, mx0, 1));
        mx0 = fmaxf(mx0, __shfl_xor_sync(0xffffffffu, mx0, 2));
        mx1 = fmaxf(mx1, __shfl_xor_sync(0xffffffffu, mx1, 1));
        mx1 = fmaxf(mx1, __shfl_xor_sync(0xffffffffu, mx1, 2));

        float mn0 = fmaxf(m0r, mx0), mn1 = fmaxf(m1r, mx1);
        float sc0 = __expf(m0r - mn0), sc1 = __expf(m1r - mn1);
        m0r = mn0; m1r = mn1;

        float rs0 = 0.0f, rs1 = 0.0f;
        {
            int rb = warp * 16;
#pragma unroll
            for (int nt = 0; nt < 8; nt++) {
                float p0 = __expf(sacc[nt][0] - mn0);
                float p1 = __expf(sacc[nt][1] - mn0);
                float p2 = __expf(sacc[nt][2] - mn1);
                float p3 = __expf(sacc[nt][3] - mn1);
                rs0 += p0 + p1;
                rs1 += p2 + p3;
                *(uint2*)&Ps[(rb + lr)     * 68 + nt * 8 + 2 * lc] = make_uint2(f2tf(p0), f2tf(p1));
                *(uint2*)&Ps[(rb + lr + 8) * 68 + nt * 8 + 2 * lc] = make_uint2(f2tf(p2), f2tf(p3));
            }
        }
        rs0 += __shfl_xor_sync(0xffffffffu, rs0, 1);
        rs0 += __shfl_xor_sync(0xffffffffu, rs0, 2);
        rs1 += __shfl_xor_sync(0xffffffffu, rs1, 1);
        rs1 += __shfl_xor_sync(0xffffffffu, rs1, 2);
        l0 = l0 * sc0 + rs0;
        l1 = l1 * sc1 + rs1;

#pragma unroll
        for (int nt = 0; nt < 8; nt++) {
            O[nt][0] *= sc0; O[nt][1] *= sc0;
            O[nt][2] *= sc1; O[nt][3] *= sc1;
        }

        __syncwarp();   // P stores visible within warp

        // O += P @ V   (kk-outer: only 4 live P-frag regs)
        {
            int rb = warp * 16;
#pragma unroll
            for (int kk = 0; kk < 8; kk++) {
                uint32_t pf[4];
                pf[0] = Ps[(rb + lr)     * 68 + kk * 8 + lc];
                pf[1] = Ps[(rb + lr + 8) * 68 + kk * 8 + lc];
                pf[2] = Ps[(rb + lr)     * 68 + kk * 8 + lc + 4];
                pf[3] = Ps[(rb + lr + 8) * 68 + kk * 8 + lc + 4];
#pragma unroll
                for (int nt = 0; nt < 8; nt++) {
                    uint32_t bfr[2];
                    bfr[0] = Vs[(kk * 8 + lc)     * 72 + nt * 8 + lr];
                    bfr[1] = Vs[(kk * 8 + lc + 4) * 72 + nt * 8 + lr];
                    mma8(O[nt], pf, bfr);
                }
            }
        }
        __syncthreads();
    }

    // Epilogue: normalize, write (b, s, h*64+hd)
    float inv0 = 1.0f / l0, inv1 = 1.0f / l1;
    float* o0 = out + ((size_t)b * SS + qr0) * DD + h * HD;
    float* o1 = out + ((size_t)b * SS + qr1) * DD + h * HD;
#pragma unroll
    for (int nt = 0; nt < 8; nt++) {
        int c = nt * 8 + 2 * lc;
        *(float2*)(o0 + c) = make_float2(O[nt][0] * inv0, O[nt][1] * inv0);
        *(float2*)(o1 + c) = make_float2(O[nt][2] * inv1, O[nt][3] * inv1);
    }
}

// ---------------------------------------------------------------------------
extern "C" void kernel_launch(void* const* d_in, const int* in_sizes, int n_in,
                              void* d_out, int out_size)
{
    const float* query  = (const float*)d_in[0];
    const float* key_in = (const float*)d_in[1];
    const float* value  = (const float*)d_in[2];
    const int*   mask   = (const int*)d_in[3];
    const float* Wq = (const float*)d_in[4];
    const float* bq = (const float*)d_in[5];
    const float* Wk = (const float*)d_in[6];
    const float* bk = (const float*)d_in[7];
    const float* Wv = (const float*)d_in[8];
    const float* bv = (const float*)d_in[9];
    const float* Wo = (const float*)d_in[10];
    const float* bo = (const float*)d_in[11];
    const float* syn = (const float*)d_in[12];
    const float* alpha_param = (const float*)d_in[13];
    float* out = (float*)d_out;

    float *pq, *pk, *pv, *pao;
    cudaGetSymbolAddress((void**)&pq, g_q);
    cudaGetSymbolAddress((void**)&pk, g_k);
    cudaGetSymbolAddress((void**)&pv, g_v);
    cudaGetSymbolAddress((void**)&pao, g_ao);

    const int M = BB * SS, N = DD, K = DD;
    dim3 gg(N / 128, M / 128);

    gemm_tf32<<<gg, 256>>>(query,  Wq, bq, pq, M, N, K, 1);
    gemm_tf32<<<gg, 256>>>(key_in, Wk, bk, pk, M, N, K, 1);
    gemm_tf32<<<gg, 256>>>(value,  Wv, bv, pv, M, N, K, 1);

    const int smem_bytes = (64 * 68 + 64 * 72 + 128 * 68) * (int)sizeof(uint32_t); // 70656
    cudaFuncSetAttribute(attn_tf32,
                         cudaFuncAttributeMaxDynamicSharedMemorySize, smem_bytes);
    attn_tf32<<<dim3(SS / 128, BB * HH), 256, smem_bytes>>>(
        pq, pk, pv, mask, syn, alpha_param, pao);

    gemm_tf32<<<gg, 256>>>(pao, Wo, bo, out, M, N, K, 0);
}

// round 4
// speedup vs baseline: 2.7719x; 1.1120x over previous
#include <cuda_runtime.h>
#include <math.h>
#include <stdint.h>

#define BB 8
#define SS 1024
#define DD 1024
#define HH 16
#define HD 64

// Scratch (device globals: allocation-free rule workaround)
__device__ float g_q[(size_t)BB * SS * DD];
__device__ float g_k[(size_t)BB * SS * DD];
__device__ float g_v[(size_t)BB * SS * DD];
__device__ float g_ao[(size_t)BB * SS * DD];

__device__ __forceinline__ uint32_t f2tf(float x) {
    uint32_t y;
    asm("cvt.rna.tf32.f32 %0, %1;" : "=r"(y) : "f"(x));
    return y;
}
__device__ __forceinline__ uint4 f2tf4(float4 t) {
    return make_uint4(f2tf(t.x), f2tf(t.y), f2tf(t.z), f2tf(t.w));
}

// D += A(m16k8) * B(k8n8), tf32 in, f32 accum
__device__ __forceinline__ void mma8(float* d, const uint32_t* a, const uint32_t* b) {
    asm volatile(
        "mma.sync.aligned.m16n8k8.row.col.f32.tf32.tf32.f32 "
        "{%0,%1,%2,%3}, {%4,%5,%6,%7}, {%8,%9}, {%0,%1,%2,%3};"
        : "+f"(d[0]), "+f"(d[1]), "+f"(d[2]), "+f"(d[3])
        : "r"(a[0]), "r"(a[1]), "r"(a[2]), "r"(a[3]), "r"(b[0]), "r"(b[1]));
}

// ---------------------------------------------------------------------------
// C[M,N] = A[M,K] @ W[N,K]^T + bias[N]   (tf32, double-buffered smem)
// Block 128x128, 8 warps (2x4), warp tile 64x32, k-slice 16, 2 CTAs/SM.
// ---------------------------------------------------------------------------
__global__ __launch_bounds__(256, 2) void gemm_tf32(
    const float* __restrict__ A, const float* __restrict__ W,
    const float* __restrict__ bias, float* __restrict__ C,
    int M, int N, int K, int head_layout)
{
    __shared__ uint32_t As[2][128 * 20];   // [m][k], stride 20
    __shared__ uint32_t Ws[2][128 * 20];   // [n][k]

    const int tid  = threadIdx.x;
    const int lane = tid & 31;
    const int warp = tid >> 5;
    const int wm   = warp >> 2;
    const int wn   = warp & 3;
    const int lr   = lane >> 2;
    const int lc   = lane & 3;

    const int r0 = tid >> 2;            // 0..63
    const int c4 = (tid & 3) * 4;       // 0,4,8,12

    const float* Ab = A + (size_t)(blockIdx.y * 128) * K;
    const float* Wb = W + (size_t)(blockIdx.x * 128) * K;

    float acc[4][4][4];
#pragma unroll
    for (int mt = 0; mt < 4; mt++)
#pragma unroll
        for (int nt = 0; nt < 4; nt++)
#pragma unroll
            for (int r = 0; r < 4; r++) acc[mt][nt][r] = 0.0f;

    float4 pa0, pa1, pw0, pw1;
#define LDTILE(kt) { \
        pa0 = *(const float4*)(Ab + (size_t)r0        * K + (kt) + c4); \
        pa1 = *(const float4*)(Ab + (size_t)(r0 + 64) * K + (kt) + c4); \
        pw0 = *(const float4*)(Wb + (size_t)r0        * K + (kt) + c4); \
        pw1 = *(const float4*)(Wb + (size_t)(r0 + 64) * K + (kt) + c4); }
#define STTILE(buf) { \
        *(uint4*)&As[buf][r0 * 20 + c4]        = f2tf4(pa0); \
        *(uint4*)&As[buf][(r0 + 64) * 20 + c4] = f2tf4(pa1); \
        *(uint4*)&Ws[buf][r0 * 20 + c4]        = f2tf4(pw0); \
        *(uint4*)&Ws[buf][(r0 + 64) * 20 + c4] = f2tf4(pw1); }

    LDTILE(0);
    STTILE(0);
    __syncthreads();

    int cur = 0;
    for (int kt = 0; kt < K; kt += 16) {
        const bool more = (kt + 16) < K;
        if (more) LDTILE(kt + 16);

#pragma unroll
        for (int ks = 0; ks < 2; ks++) {
            uint32_t af[4][4], bf[4][2];
#pragma unroll
            for (int mt = 0; mt < 4; mt++) {
                int rb = wm * 64 + mt * 16;
                af[mt][0] = As[cur][(rb + lr)     * 20 + ks * 8 + lc];
                af[mt][1] = As[cur][(rb + lr + 8) * 20 + ks * 8 + lc];
                af[mt][2] = As[cur][(rb + lr)     * 20 + ks * 8 + lc + 4];
                af[mt][3] = As[cur][(rb + lr + 8) * 20 + ks * 8 + lc + 4];
            }
#pragma unroll
            for (int nt = 0; nt < 4; nt++) {
                int nb = wn * 32 + nt * 8;
                bf[nt][0] = Ws[cur][(nb + lr) * 20 + ks * 8 + lc];
                bf[nt][1] = Ws[cur][(nb + lr) * 20 + ks * 8 + lc + 4];
            }
#pragma unroll
            for (int mt = 0; mt < 4; mt++)
#pragma unroll
                for (int nt = 0; nt < 4; nt++)
                    mma8(acc[mt][nt], af[mt], bf[nt]);
        }

        if (more) {
            STTILE(cur ^ 1);
            __syncthreads();
        }
        cur ^= 1;
    }
#undef LDTILE
#undef STTILE

    // Epilogue
#pragma unroll
    for (int mt = 0; mt < 4; mt++) {
#pragma unroll
        for (int nt = 0; nt < 4; nt++) {
            int m0 = blockIdx.y * 128 + wm * 64 + mt * 16 + lr;
            int n0 = blockIdx.x * 128 + wn * 32 + nt * 8 + 2 * lc;
            float bx = bias[n0], by = bias[n0 + 1];
            float2 rr0 = make_float2(acc[mt][nt][0] + bx, acc[mt][nt][1] + by);
            float2 rr1 = make_float2(acc[mt][nt][2] + bx, acc[mt][nt][3] + by);
            if (head_layout) {
                int hI = n0 >> 6, hd = n0 & 63;
                int bI0 = m0 >> 10, sI0 = m0 & 1023;
                int m1 = m0 + 8;
                int bI1 = m1 >> 10, sI1 = m1 & 1023;
                *(float2*)(C + (((size_t)(bI0 * HH + hI) * SS + sI0) * HD + hd)) = rr0;
                *(float2*)(C + (((size_t)(bI1 * HH + hI) * SS + sI1) * HD + hd)) = rr1;
            } else {
                *(float2*)(C + (size_t)m0 * N + n0) = rr0;
                *(float2*)(C + (size_t)(m0 + 8) * N + n0) = rr1;
            }
        }
    }
}

// ---------------------------------------------------------------------------
// Flash attention with adapter merge, tf32, double-buffered K/V, 2 CTAs/SM.
// Block: 256 threads = 8 warps; q-tile 128 rows (16/warp); kv-tile 64.
// Staging schedule keeps <=16 extra live registers:
//   LDG K' | S-mma | STS K' + LDG V' | softmax/P | PV-mma | STS V' | sync
// ---------------------------------------------------------------------------
__global__ __launch_bounds__(256, 2) void attn_tf32(
    const float* __restrict__ gq, const float* __restrict__ gk,
    const float* __restrict__ gv, const int* __restrict__ mask,
    const float* __restrict__ syn, const float* __restrict__ alpha_param,
    float* __restrict__ out)
{
    extern __shared__ uint32_t sm[];
    uint32_t* Ks0 = sm;                               // [64][68]
    uint32_t* Ks1 = Ks0 + 64 * 68;
    uint32_t* Vs0 = Ks1 + 64 * 68;                    // [64][72]
    uint32_t* Vs1 = Vs0 + 64 * 72;
    uint32_t* Ps  = Vs1 + 64 * 72;                    // [128][68]

    const int tid  = threadIdx.x;
    const int lane = tid & 31;
    const int warp = tid >> 5;
    const int lr   = lane >> 2;
    const int lc   = lane & 3;
    const int b = blockIdx.y >> 4;
    const int h = blockIdx.y & 15;
    const int qbase = blockIdx.x * 128;

    const float alpha = 1.0f / (1.0f + __expf(-alpha_param[0]));
    const float sA = alpha * 0.125f;
    const float beta = 1.0f - alpha;

    const float* qptr = gq + ((size_t)(b * HH + h) * SS + qbase) * HD;
    const float* kptr = gk + (size_t)(b * HH + h) * SS * HD;
    const float* vptr = gv + (size_t)(b * HH + h) * SS * HD;

    // per-thread tile load geometry: 4 rows apart, one float4 each
    const int tr = tid >> 4;            // 0..15 base row
    const int tc = (tid & 15) * 4;      // 0..60 col

    // Stage Q (128x64) through Ps, extract per-warp fragments into registers.
#pragma unroll
    for (int i = 0; i < 8; i++) {
        int id = tid + i * 256;
        int r  = id >> 4;
        int c4 = (id & 15) * 4;
        float4 t = *(const float4*)(qptr + (size_t)r * HD + c4);
        *(uint4*)&Ps[r * 68 + c4] = f2tf4(t);
    }
    __syncthreads();

    uint32_t qf[8][4];
    {
        int rb = warp * 16;
#pragma unroll
        for (int kk = 0; kk < 8; kk++) {
            qf[kk][0] = Ps[(rb + lr)     * 68 + kk * 8 + lc];
            qf[kk][1] = Ps[(rb + lr + 8) * 68 + kk * 8 + lc];
            qf[kk][2] = Ps[(rb + lr)     * 68 + kk * 8 + lc + 4];
            qf[kk][3] = Ps[(rb + lr + 8) * 68 + kk * 8 + lc + 4];
        }
    }
    __syncthreads();

    // Preload tile 0 into buffer 0
    {
#pragma unroll
        for (int i = 0; i < 4; i++) {
            int r = tr + i * 16;
            float4 tk = *(const float4*)(kptr + (size_t)r * HD + tc);
            float4 tv = *(const float4*)(vptr + (size_t)r * HD + tc);
            *(uint4*)&Ks0[r * 68 + tc] = f2tf4(tk);
            *(uint4*)&Vs0[r * 72 + tc] = f2tf4(tv);
        }
    }
    __syncthreads();

    float O[8][4];
#pragma unroll
    for (int nt = 0; nt < 8; nt++)
#pragma unroll
        for (int r = 0; r < 4; r++) O[nt][r] = 0.0f;
    float m0r = -INFINITY, m1r = -INFINITY, l0 = 0.0f, l1 = 0.0f;

    const int qr0 = qbase + warp * 16 + lr;
    const int qr1 = qr0 + 8;
    const float* syn0 = syn + ((size_t)h * SS + qr0) * SS;
    const float* syn1 = syn + ((size_t)h * SS + qr1) * SS;
    const int* mk0 = mask + ((size_t)b * SS + qr0) * SS;
    const int* mk1 = mask + ((size_t)b * SS + qr1) * SS;

    int cur = 0;
    for (int kb = 0; kb < SS; kb += 64) {
        const bool more = (kb + 64) < SS;
        uint32_t* Kc = cur ? Ks1 : Ks0;
        uint32_t* Vc = cur ? Vs1 : Vs0;
        uint32_t* Kn = cur ? Ks0 : Ks1;
        uint32_t* Vn = cur ? Vs0 : Vs1;

        // Prefetch next K tile (registers)
        float4 st0, st1, st2, st3;
        if (more) {
            const float* kp = kptr + (size_t)(kb + 64) * HD;
            st0 = *(const float4*)(kp + (size_t)(tr)      * HD + tc);
            st1 = *(const float4*)(kp + (size_t)(tr + 16) * HD + tc);
            st2 = *(const float4*)(kp + (size_t)(tr + 32) * HD + tc);
            st3 = *(const float4*)(kp + (size_t)(tr + 48) * HD + tc);
        }

        // S = Q @ K^T
        float sacc[8][4];
#pragma unroll
        for (int nt = 0; nt < 8; nt++) {
            sacc[nt][0] = sacc[nt][1] = sacc[nt][2] = sacc[nt][3] = 0.0f;
#pragma unroll
            for (int kk = 0; kk < 8; kk++) {
                uint32_t bfr[2];
                bfr[0] = Kc[(nt * 8 + lr) * 68 + kk * 8 + lc];
                bfr[1] = Kc[(nt * 8 + lr) * 68 + kk * 8 + lc + 4];
                mma8(sacc[nt], qf[kk], bfr);
            }
        }

        // Store prefetched K, then prefetch next V (reuse staging regs)
        if (more) {
            *(uint4*)&Kn[(tr)      * 68 + tc] = f2tf4(st0);
            *(uint4*)&Kn[(tr + 16) * 68 + tc] = f2tf4(st1);
            *(uint4*)&Kn[(tr + 32) * 68 + tc] = f2tf4(st2);
            *(uint4*)&Kn[(tr + 48) * 68 + tc] = f2tf4(st3);
            const float* vp = vptr + (size_t)(kb + 64) * HD;
            st0 = *(const float4*)(vp + (size_t)(tr)      * HD + tc);
            st1 = *(const float4*)(vp + (size_t)(tr + 16) * HD + tc);
            st2 = *(const float4*)(vp + (size_t)(tr + 32) * HD + tc);
            st3 = *(const float4*)(vp + (size_t)(tr + 48) * HD + tc);
        }

        // Merge adapter + mask; running row max
        float mx0 = -INFINITY, mx1 = -INFINITY;
#pragma unroll
        for (int nt = 0; nt < 8; nt++) {
            int cb = kb + nt * 8 + 2 * lc;
            float2 sy0 = *(const float2*)(syn0 + cb);
            float2 sy1 = *(const float2*)(syn1 + cb);
            int2 mm0 = *(const int2*)(mk0 + cb);
            int2 mm1 = *(const int2*)(mk1 + cb);
            sacc[nt][0] = mm0.x ? fmaf(sacc[nt][0], sA, beta * sy0.x) : -1.0e9f;
            sacc[nt][1] = mm0.y ? fmaf(sacc[nt][1], sA, beta * sy0.y) : -1.0e9f;
            sacc[nt][2] = mm1.x ? fmaf(sacc[nt][2], sA, beta * sy1.x) : -1.0e9f;
            sacc[nt][3] = mm1.y ? fmaf(sacc[nt][3], sA, beta * sy1.y) : -1.0e9f;
            mx0 = fmaxf(mx0, fmaxf(sacc[nt][0], sacc[nt][1]));
            mx1 = fmaxf(mx1, fmaxf(sacc[nt][2], sacc[nt][3]));
        }
        mx0 = fmaxf(mx0, __shfl_xor_sync(0xffffffffu, mx0, 1));
        mx0 = fmaxf(mx0, __shfl_xor_sync(0xffffffffu, mx0, 2));
        mx1 = fmaxf(mx1, __shfl_xor_sync(0xffffffffu, mx1, 1));
        mx1 = fmaxf(mx1, __shfl_xor_sync(0xffffffffu, mx1, 2));

        float mn0 = fmaxf(m0r, mx0), mn1 = fmaxf(m1r, mx1);
        float sc0 = __expf(m0r - mn0), sc1 = __expf(m1r - mn1);
        m0r = mn0; m1r = mn1;

        float rs0 = 0.0f, rs1 = 0.0f;
        {
            int rb = warp * 16;
#pragma unroll
            for (int nt = 0; nt < 8; nt++) {
                float p0 = __expf(sacc[nt][0] - mn0);
                float p1 = __expf(sacc[nt][1] - mn0);
                float p2 = __expf(sacc[nt][2] - mn1);
                float p3 = __expf(sacc[nt][3] - mn1);
                rs0 += p0 + p1;
                rs1 += p2 + p3;
                *(uint2*)&Ps[(rb + lr)     * 68 + nt * 8 + 2 * lc] = make_uint2(f2tf(p0), f2tf(p1));
                *(uint2*)&Ps[(rb + lr + 8) * 68 + nt * 8 + 2 * lc] = make_uint2(f2tf(p2), f2tf(p3));
            }
        }
        rs0 += __shfl_xor_sync(0xffffffffu, rs0, 1);
        rs0 += __shfl_xor_sync(0xffffffffu, rs0, 2);
        rs1 += __shfl_xor_sync(0xffffffffu, rs1, 1);
        rs1 += __shfl_xor_sync(0xffffffffu, rs1, 2);
        l0 = l0 * sc0 + rs0;
        l1 = l1 * sc1 + rs1;

#pragma unroll
        for (int nt = 0; nt < 8; nt++) {
            O[nt][0] *= sc0; O[nt][1] *= sc0;
            O[nt][2] *= sc1; O[nt][3] *= sc1;
        }

        __syncwarp();   // P stores visible within warp

        // O += P @ V   (kk-outer: only 4 live P-frag regs)
        {
            int rb = warp * 16;
#pragma unroll
            for (int kk = 0; kk < 8; kk++) {
                uint32_t pf[4];
                pf[0] = Ps[(rb + lr)     * 68 + kk * 8 + lc];
                pf[1] = Ps[(rb + lr + 8) * 68 + kk * 8 + lc];
                pf[2] = Ps[(rb + lr)     * 68 + kk * 8 + lc + 4];
                pf[3] = Ps[(rb + lr + 8) * 68 + kk * 8 + lc + 4];
#pragma unroll
                for (int nt = 0; nt < 8; nt++) {
                    uint32_t bfr[2];
                    bfr[0] = Vc[(kk * 8 + lc)     * 72 + nt * 8 + lr];
                    bfr[1] = Vc[(kk * 8 + lc + 4) * 72 + nt * 8 + lr];
                    mma8(O[nt], pf, bfr);
                }
            }
        }

        // Store prefetched V
        if (more) {
            *(uint4*)&Vn[(tr)      * 72 + tc] = f2tf4(st0);
            *(uint4*)&Vn[(tr + 16) * 72 + tc] = f2tf4(st1);
            *(uint4*)&Vn[(tr + 32) * 72 + tc] = f2tf4(st2);
            *(uint4*)&Vn[(tr + 48) * 72 + tc] = f2tf4(st3);
        }
        __syncthreads();
        cur ^= 1;
    }

    // Epilogue: normalize, write (b, s, h*64+hd)
    float inv0 = 1.0f / l0, inv1 = 1.0f / l1;
    float* o0 = out + ((size_t)b * SS + qr0) * DD + h * HD;
    float* o1 = out + ((size_t)b * SS + qr1) * DD + h * HD;
#pragma unroll
    for (int nt = 0; nt < 8; nt++) {
        int c = nt * 8 + 2 * lc;
        *(float2*)(o0 + c) = make_float2(O[nt][0] * inv0, O[nt][1] * inv0);
        *(float2*)(o1 + c) = make_float2(O[nt][2] * inv1, O[nt][3] * inv1);
    }
}

// ---------------------------------------------------------------------------
extern "C" void kernel_launch(void* const* d_in, const int* in_sizes, int n_in,
                              void* d_out, int out_size)
{
    const float* query  = (const float*)d_in[0];
    const float* key_in = (const float*)d_in[1];
    const float* value  = (const float*)d_in[2];
    const int*   mask   = (const int*)d_in[3];
    const float* Wq = (const float*)d_in[4];
    const float* bq = (const float*)d_in[5];
    const float* Wk = (const float*)d_in[6];
    const float* bk = (const float*)d_in[7];
    const float* Wv = (const float*)d_in[8];
    const float* bv = (const float*)d_in[9];
    const float* Wo = (const float*)d_in[10];
    const float* bo = (const float*)d_in[11];
    const float* syn = (const float*)d_in[12];
    const float* alpha_param = (const float*)d_in[13];
    float* out = (float*)d_out;

    float *pq, *pk, *pv, *pao;
    cudaGetSymbolAddress((void**)&pq, g_q);
    cudaGetSymbolAddress((void**)&pk, g_k);
    cudaGetSymbolAddress((void**)&pv, g_v);
    cudaGetSymbolAddress((void**)&pao, g_ao);

    const int M = BB * SS, N = DD, K = DD;
    dim3 gg(N / 128, M / 128);

    gemm_tf32<<<gg, 256>>>(query,  Wq, bq, pq, M, N, K, 1);
    gemm_tf32<<<gg, 256>>>(key_in, Wk, bk, pk, M, N, K, 1);
    gemm_tf32<<<gg, 256>>>(value,  Wv, bv, pv, M, N, K, 1);

    const int smem_bytes = (2 * 64 * 68 + 2 * 64 * 72 + 128 * 68) * (int)sizeof(uint32_t); // 106496
    cudaFuncSetAttribute(attn_tf32,
                         cudaFuncAttributeMaxDynamicSharedMemorySize, smem_bytes);
    attn_tf32<<<dim3(SS / 128, BB * HH), 256, smem_bytes>>>(
        pq, pk, pv, mask, syn, alpha_param, pao);

    gemm_tf32<<<gg, 256>>>(pao, Wo, bo, out, M, N, K, 0);
}

// round 6
// speedup vs baseline: 4.0116x; 1.4473x over previous
#include <cuda_runtime.h>
#include <cuda_fp16.h>
#include <math.h>
#include <stdint.h>

#define BB 8
#define SS 1024
#define DD 1024
#define HH 16
#define HD 64

// Scratch (device globals: allocation-free rule workaround)
__device__ float g_q[(size_t)BB * SS * DD];
__device__ float g_k[(size_t)BB * SS * DD];
__device__ float g_v[(size_t)BB * SS * DD];
__device__ float g_ao[(size_t)BB * SS * DD];

__device__ __forceinline__ uint32_t smem_u32(const void* p) {
    uint32_t a;
    asm("{ .reg .u64 t; cvta.to.shared.u64 t, %1; cvt.u32.u64 %0, t; }" : "=r"(a) : "l"(p));
    return a;
}
__device__ __forceinline__ uint32_t f2h2(float lo, float hi) {
    __half2 h = __floats2half2_rn(lo, hi);   // x = lo (low half), y = hi
    return *(uint32_t*)&h;
}
__device__ __forceinline__ uint2 f4h(float4 t) {
    return make_uint2(f2h2(t.x, t.y), f2h2(t.z, t.w));
}

// D += A(m16k16) * B(k16n8), fp16 in, fp32 accum
__device__ __forceinline__ void mma16(float* d, const uint32_t* a, const uint32_t* b) {
    asm volatile(
        "mma.sync.aligned.m16n8k16.row.col.f32.f16.f16.f32 "
        "{%0,%1,%2,%3}, {%4,%5,%6,%7}, {%8,%9}, {%0,%1,%2,%3};"
        : "+f"(d[0]), "+f"(d[1]), "+f"(d[2]), "+f"(d[3])
        : "r"(a[0]), "r"(a[1]), "r"(a[2]), "r"(a[3]), "r"(b[0]), "r"(b[1]));
}
__device__ __forceinline__ void ldsm_x4(uint32_t* r, uint32_t addr) {
    asm volatile("ldmatrix.sync.aligned.m8n8.x4.shared.b16 {%0,%1,%2,%3}, [%4];"
                 : "=r"(r[0]), "=r"(r[1]), "=r"(r[2]), "=r"(r[3]) : "r"(addr));
}
__device__ __forceinline__ void ldsm_x2(uint32_t* r, uint32_t addr) {
    asm volatile("ldmatrix.sync.aligned.m8n8.x2.shared.b16 {%0,%1}, [%2];"
                 : "=r"(r[0]), "=r"(r[1]) : "r"(addr));
}
__device__ __forceinline__ void ldsm_x2t(uint32_t* r, uint32_t addr) {
    asm volatile("ldmatrix.sync.aligned.m8n8.x2.trans.shared.b16 {%0,%1}, [%2];"
                 : "=r"(r[0]), "=r"(r[1]) : "r"(addr));
}

// ---------------------------------------------------------------------------
// C[M,N] = A[M,K] @ W[N,K]^T + bias[N]   (fp16 mma, ldmatrix, double buffer)
// Block 128x128, 8 warps (2x4), warp tile 64x32, k-slice 16, 2 CTAs/SM.
// smem tiles [128][24] halves (stride 24h = 48B, LDSM conflict-free).
// ---------------------------------------------------------------------------
__global__ __launch_bounds__(256, 2) void gemm_f16(
    const float* __restrict__ A, const float* __restrict__ W,
    const float* __restrict__ bias, float* __restrict__ C, int head_layout)
{
    __shared__ __align__(16) __half As[2][128 * 24];
    __shared__ __align__(16) __half Ws[2][128 * 24];

    const int tid  = threadIdx.x;
    const int lane = tid & 31;
    const int warp = tid >> 5;
    const int wm   = warp >> 2;
    const int wn   = warp & 3;
    const int lr   = lane >> 2;
    const int lc   = lane & 3;
    const int aRow = lane & 15;
    const int aK   = (lane >> 4) * 8;
    const int bRow = lane & 7;
    const int bK   = ((lane >> 3) & 1) * 8;

    // staging: 128 rows x 16 cols per matrix = 512 float4 slots, 2/thread
    const int sr = tid >> 2;            // 0..63 (and +64)
    const int sc = (tid & 3) * 4;       // 0,4,8,12

    const float* Ab = A + (size_t)(blockIdx.y * 128) * DD;
    const float* Wb = W + (size_t)(blockIdx.x * 128) * DD;

    const uint32_t baseA[2] = { smem_u32(As[0]), smem_u32(As[1]) };
    const uint32_t baseW[2] = { smem_u32(Ws[0]), smem_u32(Ws[1]) };

    float acc[4][4][4];
#pragma unroll
    for (int mt = 0; mt < 4; mt++)
#pragma unroll
        for (int nt = 0; nt < 4; nt++)
#pragma unroll
            for (int r = 0; r < 4; r++) acc[mt][nt][r] = 0.0f;

    float4 pa0, pa1, pw0, pw1;
#define LDTILE(kt) { \
        pa0 = *(const float4*)(Ab + (size_t)sr        * DD + (kt) + sc); \
        pa1 = *(const float4*)(Ab + (size_t)(sr + 64) * DD + (kt) + sc); \
        pw0 = *(const float4*)(Wb + (size_t)sr        * DD + (kt) + sc); \
        pw1 = *(const float4*)(Wb + (size_t)(sr + 64) * DD + (kt) + sc); }
#define STTILE(buf) { \
        *(uint2*)&As[buf][sr * 24 + sc]        = f4h(pa0); \
        *(uint2*)&As[buf][(sr + 64) * 24 + sc] = f4h(pa1); \
        *(uint2*)&Ws[buf][sr * 24 + sc]        = f4h(pw0); \
        *(uint2*)&Ws[buf][(sr + 64) * 24 + sc] = f4h(pw1); }

    LDTILE(0);
    STTILE(0);
    __syncthreads();

    int cur = 0;
    for (int kt = 0; kt < DD; kt += 16) {
        const bool more = (kt + 16) < DD;
        if (more) LDTILE(kt + 16);

        uint32_t af[4][4], bf[4][2];
#pragma unroll
        for (int mt = 0; mt < 4; mt++)
            ldsm_x4(af[mt], baseA[cur] +
                    ((uint32_t)((wm * 64 + mt * 16 + aRow) * 24 + aK) << 1));
#pragma unroll
        for (int nt = 0; nt < 4; nt++)
            ldsm_x2(bf[nt], baseW[cur] +
                    ((uint32_t)((wn * 32 + nt * 8 + bRow) * 24 + bK) << 1));
#pragma unroll
        for (int mt = 0; mt < 4; mt++)
#pragma unroll
            for (int nt = 0; nt < 4; nt++)
                mma16(acc[mt][nt], af[mt], bf[nt]);

        if (more) {
            STTILE(cur ^ 1);
            __syncthreads();
        }
        cur ^= 1;
    }
#undef LDTILE
#undef STTILE

    // Epilogue (same frag layout as tf32 m16n8: rows lr/lr+8, cols 2lc/2lc+1)
#pragma unroll
    for (int mt = 0; mt < 4; mt++) {
#pragma unroll
        for (int nt = 0; nt < 4; nt++) {
            int m0 = blockIdx.y * 128 + wm * 64 + mt * 16 + lr;
            int n0 = blockIdx.x * 128 + wn * 32 + nt * 8 + 2 * lc;
            float bx = bias[n0], by = bias[n0 + 1];
            float2 rr0 = make_float2(acc[mt][nt][0] + bx, acc[mt][nt][1] + by);
            float2 rr1 = make_float2(acc[mt][nt][2] + bx, acc[mt][nt][3] + by);
            if (head_layout) {
                int hI = n0 >> 6, hd = n0 & 63;
                int bI0 = m0 >> 10, sI0 = m0 & 1023;
                int m1 = m0 + 8;
                int bI1 = m1 >> 10, sI1 = m1 & 1023;
                *(float2*)(C + (((size_t)(bI0 * HH + hI) * SS + sI0) * HD + hd)) = rr0;
                *(float2*)(C + (((size_t)(bI1 * HH + hI) * SS + sI1) * HD + hd)) = rr1;
            } else {
                *(float2*)(C + (size_t)m0 * DD + n0) = rr0;
                *(float2*)(C + (size_t)(m0 + 8) * DD + n0) = rr1;
            }
        }
    }
}

// ---------------------------------------------------------------------------
// Flash attention with adapter merge, fp16 mma + ldmatrix, double-buffered K/V.
// Block 256 threads = 8 warps; q-tile 128 (16 rows/warp); kv-tile 64.
// All smem tiles stride 72 halves (144B, LDSM conflict-free).
// ---------------------------------------------------------------------------
__global__ __launch_bounds__(256, 2) void attn_f16(
    const float* __restrict__ gq, const float* __restrict__ gk,
    const float* __restrict__ gv, const int* __restrict__ mask,
    const float* __restrict__ syn, const float* __restrict__ alpha_param,
    float* __restrict__ out)
{
    extern __shared__ __half smh[];
    __half* Ks0 = smh;                 // [64][72]
    __half* Ks1 = Ks0 + 64 * 72;
    __half* Vs0 = Ks1 + 64 * 72;       // [64][72]
    __half* Vs1 = Vs0 + 64 * 72;
    __half* Ps  = Vs1 + 64 * 72;       // [128][72]

    const int tid  = threadIdx.x;
    const int lane = tid & 31;
    const int warp = tid >> 5;
    const int lr   = lane >> 2;
    const int lc   = lane & 3;
    const int aRow = lane & 15;
    const int aK   = (lane >> 4) * 8;
    const int bRow = lane & 7;
    const int bK   = ((lane >> 3) & 1) * 8;
    const int b = blockIdx.y >> 4;
    const int h = blockIdx.y & 15;
    const int qbase = blockIdx.x * 128;
    const int rb = warp * 16;

    const uint32_t KsA[2] = { smem_u32(Ks0), smem_u32(Ks1) };
    const uint32_t VsA[2] = { smem_u32(Vs0), smem_u32(Vs1) };
    const uint32_t PsA    = smem_u32(Ps);

    const float alpha = 1.0f / (1.0f + __expf(-alpha_param[0]));
    const float sA = alpha * 0.125f;
    const float beta = 1.0f - alpha;

    const float* qptr = gq + ((size_t)(b * HH + h) * SS + qbase) * HD;
    const float* kptr = gk + (size_t)(b * HH + h) * SS * HD;
    const float* vptr = gv + (size_t)(b * HH + h) * SS * HD;

    const int tr = tid >> 4;            // 0..15
    const int tc = (tid & 15) * 4;      // 0..60

    // Stage Q (128x64) into Ps, extract per-warp fragments via ldmatrix.
#pragma unroll
    for (int i = 0; i < 8; i++) {
        int id = tid + i * 256;
        int r  = id >> 4;
        int c4 = (id & 15) * 4;
        float4 t = *(const float4*)(qptr + (size_t)r * HD + c4);
        *(uint2*)&Ps[r * 72 + c4] = f4h(t);
    }
    __syncthreads();

    uint32_t qf[4][4];
#pragma unroll
    for (int kk = 0; kk < 4; kk++)
        ldsm_x4(qf[kk], PsA + ((uint32_t)((rb + aRow) * 72 + kk * 16 + aK) << 1));
    __syncthreads();

    // Preload KV tile 0 into buffer 0
#pragma unroll
    for (int i = 0; i < 4; i++) {
        int r = tr + i * 16;
        float4 tk = *(const float4*)(kptr + (size_t)r * HD + tc);
        float4 tv = *(const float4*)(vptr + (size_t)r * HD + tc);
        *(uint2*)&Ks0[r * 72 + tc] = f4h(tk);
        *(uint2*)&Vs0[r * 72 + tc] = f4h(tv);
    }
    __syncthreads();

    float O[8][4];
#pragma unroll
    for (int nt = 0; nt < 8; nt++)
#pragma unroll
        for (int r = 0; r < 4; r++) O[nt][r] = 0.0f;
    float m0r = -INFINITY, m1r = -INFINITY, l0 = 0.0f, l1 = 0.0f;

    const int qr0 = qbase + rb + lr;
    const int qr1 = qr0 + 8;
    const float* syn0 = syn + ((size_t)h * SS + qr0) * SS;
    const float* syn1 = syn + ((size_t)h * SS + qr1) * SS;
    const int* mk0 = mask + ((size_t)b * SS + qr0) * SS;
    const int* mk1 = mask + ((size_t)b * SS + qr1) * SS;

    int cur = 0;
    for (int kb = 0; kb < SS; kb += 64) {
        const bool more = (kb + 64) < SS;
        __half* Kn = cur ? Ks0 : Ks1;
        __half* Vn = cur ? Vs0 : Vs1;

        // Prefetch next K tile (registers)
        float4 st0, st1, st2, st3;
        if (more) {
            const float* kp = kptr + (size_t)(kb + 64) * HD;
            st0 = *(const float4*)(kp + (size_t)(tr)      * HD + tc);
            st1 = *(const float4*)(kp + (size_t)(tr + 16) * HD + tc);
            st2 = *(const float4*)(kp + (size_t)(tr + 32) * HD + tc);
            st3 = *(const float4*)(kp + (size_t)(tr + 48) * HD + tc);
        }

        // S = Q @ K^T
        float sacc[8][4];
#pragma unroll
        for (int nt = 0; nt < 8; nt++) {
            sacc[nt][0] = sacc[nt][1] = sacc[nt][2] = sacc[nt][3] = 0.0f;
#pragma unroll
            for (int kk = 0; kk < 4; kk++) {
                uint32_t bfr[2];
                ldsm_x2(bfr, KsA[cur] +
                        ((uint32_t)((nt * 8 + bRow) * 72 + kk * 16 + bK) << 1));
                mma16(sacc[nt], qf[kk], bfr);
            }
        }

        // Store prefetched K, then prefetch next V (reuse staging regs)
        if (more) {
            *(uint2*)&Kn[(tr)      * 72 + tc] = f4h(st0);
            *(uint2*)&Kn[(tr + 16) * 72 + tc] = f4h(st1);
            *(uint2*)&Kn[(tr + 32) * 72 + tc] = f4h(st2);
            *(uint2*)&Kn[(tr + 48) * 72 + tc] = f4h(st3);
            const float* vp = vptr + (size_t)(kb + 64) * HD;
            st0 = *(const float4*)(vp + (size_t)(tr)      * HD + tc);
            st1 = *(const float4*)(vp + (size_t)(tr + 16) * HD + tc);
            st2 = *(const float4*)(vp + (size_t)(tr + 32) * HD + tc);
            st3 = *(const float4*)(vp + (size_t)(tr + 48) * HD + tc);
        }

        // Merge adapter + mask; running row max
        float mx0 = -INFINITY, mx1 = -INFINITY;
#pragma unroll
        for (int nt = 0; nt < 8; nt++) {
            int cb = kb + nt * 8 + 2 * lc;
            float2 sy0 = *(const float2*)(syn0 + cb);
            float2 sy1 = *(const float2*)(syn1 + cb);
            int2 mm0 = *(const int2*)(mk0 + cb);
            int2 mm1 = *(const int2*)(mk1 + cb);
            sacc[nt][0] = mm0.x ? fmaf(sacc[nt][0], sA, beta * sy0.x) : -1.0e9f;
            sacc[nt][1] = mm0.y ? fmaf(sacc[nt][1], sA, beta * sy0.y) : -1.0e9f;
            sacc[nt][2] = mm1.x ? fmaf(sacc[nt][2], sA, beta * sy1.x) : -1.0e9f;
            sacc[nt][3] = mm1.y ? fmaf(sacc[nt][3], sA, beta * sy1.y) : -1.0e9f;
            mx0 = fmaxf(mx0, fmaxf(sacc[nt][0], sacc[nt][1]));
            mx1 = fmaxf(mx1, fmaxf(sacc[nt][2], sacc[nt][3]));
        }
        mx0 = fmaxf(mx0, __shfl_xor_sync(0xffffffffu, mx0, 1));
        mx0 = fmaxf(mx0, __shfl_xor_sync(0xffffffffu, mx0, 2));
        mx1 = fmaxf(mx1, __shfl_xor_sync(0xffffffffu, mx1, 1));
        mx1 = fmaxf(mx1, __shfl_xor_sync(0xffffffffu, mx1, 2));

        float mn0 = fmaxf(m0r, mx0), mn1 = fmaxf(m1r, mx1);
        float sc0 = __expf(m0r - mn0), sc1 = __expf(m1r - mn1);
        m0r = mn0; m1r = mn1;

        float rs0 = 0.0f, rs1 = 0.0f;
#pragma unroll
        for (int nt = 0; nt < 8; nt++) {
            float p0 = __expf(sacc[nt][0] - mn0);
            float p1 = __expf(sacc[nt][1] - mn0);
            float p2 = __expf(sacc[nt][2] - mn1);
            float p3 = __expf(sacc[nt][3] - mn1);
            rs0 += p0 + p1;
            rs1 += p2 + p3;
            *(uint32_t*)&Ps[(rb + lr)     * 72 + nt * 8 + 2 * lc] = f2h2(p0, p1);
            *(uint32_t*)&Ps[(rb + lr + 8) * 72 + nt * 8 + 2 * lc] = f2h2(p2, p3);
        }
        rs0 += __shfl_xor_sync(0xffffffffu, rs0, 1);
        rs0 += __shfl_xor_sync(0xffffffffu, rs0, 2);
        rs1 += __shfl_xor_sync(0xffffffffu, rs1, 1);
        rs1 += __shfl_xor_sync(0xffffffffu, rs1, 2);
        l0 = l0 * sc0 + rs0;
        l1 = l1 * sc1 + rs1;

#pragma unroll
        for (int nt = 0; nt < 8; nt++) {
            O[nt][0] *= sc0; O[nt][1] *= sc0;
            O[nt][2] *= sc1; O[nt][3] *= sc1;
        }

        __syncwarp();   // P stores visible within warp before ldmatrix

        // O += P @ V
#pragma unroll
        for (int kk = 0; kk < 4; kk++) {
            uint32_t pf[4];
            ldsm_x4(pf, PsA + ((uint32_t)((rb + aRow) * 72 + kk * 16 + aK) << 1));
#pragma unroll
            for (int nt = 0; nt < 8; nt++) {
                uint32_t bfr[2];
                ldsm_x2t(bfr, VsA[cur] +
                         ((uint32_t)((kk * 16 + aRow) * 72 + nt * 8) << 1));
                mma16(O[nt], pf, bfr);
            }
        }

        // Store prefetched V
        if (more) {
            *(uint2*)&Vn[(tr)      * 72 + tc] = f4h(st0);
            *(uint2*)&Vn[(tr + 16) * 72 + tc] = f4h(st1);
            *(uint2*)&Vn[(tr + 32) * 72 + tc] = f4h(st2);
            *(uint2*)&Vn[(tr + 48) * 72 + tc] = f4h(st3);
        }
        __syncthreads();
        cur ^= 1;
    }

    // Epilogue: normalize, write (b, s, h*64+hd)
    float inv0 = 1.0f / l0, inv1 = 1.0f / l1;
    float* o0 = out + ((size_t)b * SS + qr0) * DD + h * HD;
    float* o1 = out + ((size_t)b * SS + qr1) * DD + h * HD;
#pragma unroll
    for (int nt = 0; nt < 8; nt++) {
        int c = nt * 8 + 2 * lc;
        *(float2*)(o0 + c) = make_float2(O[nt][0] * inv0, O[nt][1] * inv0);
        *(float2*)(o1 + c) = make_float2(O[nt][2] * inv1, O[nt][3] * inv1);
    }
}

// ---------------------------------------------------------------------------
extern "C" void kernel_launch(void* const* d_in, const int* in_sizes, int n_in,
                              void* d_out, int out_size)
{
    const float* query  = (const float*)d_in[0];
    const float* key_in = (const float*)d_in[1];
    const float* value  = (const float*)d_in[2];
    const int*   mask   = (const int*)d_in[3];
    const float* Wq = (const float*)d_in[4];
    const float* bq = (const float*)d_in[5];
    const float* Wk = (const float*)d_in[6];
    const float* bk = (const float*)d_in[7];
    const float* Wv = (const float*)d_in[8];
    const float* bv = (const float*)d_in[9];
    const float* Wo = (const float*)d_in[10];
    const float* bo = (const float*)d_in[11];
    const float* syn = (const float*)d_in[12];
    const float* alpha_param = (const float*)d_in[13];
    float* out = (float*)d_out;

    float *pq, *pk, *pv, *pao;
    cudaGetSymbolAddress((void**)&pq, g_q);
    cudaGetSymbolAddress((void**)&pk, g_k);
    cudaGetSymbolAddress((void**)&pv, g_v);
    cudaGetSymbolAddress((void**)&pao, g_ao);

    dim3 gg(DD / 128, (BB * SS) / 128);   // (8, 64)

    gemm_f16<<<gg, 256>>>(query,  Wq, bq, pq, 1);
    gemm_f16<<<gg, 256>>>(key_in, Wk, bk, pk, 1);
    gemm_f16<<<gg, 256>>>(value,  Wv, bv, pv, 1);

    const int smem_bytes = (2 * 64 * 72 + 2 * 64 * 72 + 128 * 72) * (int)sizeof(__half); // 55296
    cudaFuncSetAttribute(attn_f16,
                         cudaFuncAttributeMaxDynamicSharedMemorySize, smem_bytes);
    attn_f16<<<dim3(SS / 128, BB * HH), 256, smem_bytes>>>(
        pq, pk, pv, mask, syn, alpha_param, pao);

    gemm_f16<<<gg, 256>>>(pao, Wo, bo, out, 0);
}

// round 7
// speedup vs baseline: 5.1396x; 1.2812x over previous
#include <cuda_runtime.h>
#include <cuda_fp16.h>
#include <math.h>
#include <stdint.h>

#define BB 8
#define SS 1024
#define DD 1024
#define HH 16
#define HD 64

// Scratch (device globals: allocation-free rule workaround)
__device__ __half  g_q[(size_t)BB * SS * DD];
__device__ __half  g_k[(size_t)BB * SS * DD];
__device__ __half  g_v[(size_t)BB * SS * DD];
__device__ float   g_ao[(size_t)BB * SS * DD];
__device__ uint32_t g_maskw[(size_t)BB * SS * (SS / 32)];
__device__ __half  g_synh[(size_t)HH * SS * SS];

__device__ __forceinline__ uint32_t smem_u32(const void* p) {
    uint32_t a;
    asm("{ .reg .u64 t; cvta.to.shared.u64 t, %1; cvt.u32.u64 %0, t; }" : "=r"(a) : "l"(p));
    return a;
}
__device__ __forceinline__ uint32_t f2h2(float lo, float hi) {
    __half2 h = __floats2half2_rn(lo, hi);
    return *(uint32_t*)&h;
}
__device__ __forceinline__ uint2 f4h(float4 t) {
    return make_uint2(f2h2(t.x, t.y), f2h2(t.z, t.w));
}

__device__ __forceinline__ void mma16(float* d, const uint32_t* a, const uint32_t* b) {
    asm volatile(
        "mma.sync.aligned.m16n8k16.row.col.f32.f16.f16.f32 "
        "{%0,%1,%2,%3}, {%4,%5,%6,%7}, {%8,%9}, {%0,%1,%2,%3};"
        : "+f"(d[0]), "+f"(d[1]), "+f"(d[2]), "+f"(d[3])
        : "r"(a[0]), "r"(a[1]), "r"(a[2]), "r"(a[3]), "r"(b[0]), "r"(b[1]));
}
__device__ __forceinline__ void ldsm_x4(uint32_t* r, uint32_t addr) {
    asm volatile("ldmatrix.sync.aligned.m8n8.x4.shared.b16 {%0,%1,%2,%3}, [%4];"
                 : "=r"(r[0]), "=r"(r[1]), "=r"(r[2]), "=r"(r[3]) : "r"(addr));
}
__device__ __forceinline__ void ldsm_x2(uint32_t* r, uint32_t addr) {
    asm volatile("ldmatrix.sync.aligned.m8n8.x2.shared.b16 {%0,%1}, [%2];"
                 : "=r"(r[0]), "=r"(r[1]) : "r"(addr));
}
__device__ __forceinline__ void ldsm_x2t(uint32_t* r, uint32_t addr) {
    asm volatile("ldmatrix.sync.aligned.m8n8.x2.trans.shared.b16 {%0,%1}, [%2];"
                 : "=r"(r[0]), "=r"(r[1]) : "r"(addr));
}

// ---------------------------------------------------------------------------
// Prep kernels: pack mask to bits; convert syn to fp16.
// ---------------------------------------------------------------------------
__global__ __launch_bounds__(256) void pack_mask(const int* __restrict__ mask,
                                                 uint32_t* __restrict__ mw)
{
    const size_t w = (size_t)blockIdx.x * 256 + threadIdx.x;   // word index
    const int4* p = (const int4*)(mask + w * 32);
    uint32_t bits = 0;
#pragma unroll
    for (int i = 0; i < 8; i++) {
        int4 v = p[i];
        bits |= (v.x != 0 ? 1u : 0u) << (i * 4 + 0);
        bits |= (v.y != 0 ? 1u : 0u) << (i * 4 + 1);
        bits |= (v.z != 0 ? 1u : 0u) << (i * 4 + 2);
        bits |= (v.w != 0 ? 1u : 0u) << (i * 4 + 3);
    }
    mw[w] = bits;
}

__global__ __launch_bounds__(256) void syn_to_half(const float* __restrict__ syn,
                                                   __half* __restrict__ synh)
{
    const size_t i = (size_t)blockIdx.x * 256 + threadIdx.x;   // float4 index
    float4 t = *(const float4*)(syn + i * 4);
    *(uint2*)(synh + i * 4) = f4h(t);
}

// ---------------------------------------------------------------------------
// GEMM: C = A[M,K] @ W[N,K]^T + bias.  fp16 mma + ldmatrix, double buffer.
// head_layout=1: C is __half*, (b,h,s,hd) layout.  head_layout=0: float*, row-major.
// ---------------------------------------------------------------------------
__global__ __launch_bounds__(256, 2) void gemm_f16(
    const float* __restrict__ A, const float* __restrict__ W,
    const float* __restrict__ bias, void* __restrict__ Cv, int head_layout)
{
    __shared__ __align__(16) __half As[2][128 * 24];
    __shared__ __align__(16) __half Ws[2][128 * 24];

    const int tid  = threadIdx.x;
    const int lane = tid & 31;
    const int warp = tid >> 5;
    const int wm   = warp >> 2;
    const int wn   = warp & 3;
    const int lr   = lane >> 2;
    const int lc   = lane & 3;
    const int aRow = lane & 15;
    const int aK   = (lane >> 4) * 8;
    const int bRow = lane & 7;
    const int bK   = ((lane >> 3) & 1) * 8;

    const int sr = tid >> 2;
    const int sc = (tid & 3) * 4;

    const float* Ab = A + (size_t)(blockIdx.y * 128) * DD;
    const float* Wb = W + (size_t)(blockIdx.x * 128) * DD;

    const uint32_t baseA[2] = { smem_u32(As[0]), smem_u32(As[1]) };
    const uint32_t baseW[2] = { smem_u32(Ws[0]), smem_u32(Ws[1]) };

    float acc[4][4][4];
#pragma unroll
    for (int mt = 0; mt < 4; mt++)
#pragma unroll
        for (int nt = 0; nt < 4; nt++)
#pragma unroll
            for (int r = 0; r < 4; r++) acc[mt][nt][r] = 0.0f;

    float4 pa0, pa1, pw0, pw1;
#define LDTILE(kt) { \
        pa0 = *(const float4*)(Ab + (size_t)sr        * DD + (kt) + sc); \
        pa1 = *(const float4*)(Ab + (size_t)(sr + 64) * DD + (kt) + sc); \
        pw0 = *(const float4*)(Wb + (size_t)sr        * DD + (kt) + sc); \
        pw1 = *(const float4*)(Wb + (size_t)(sr + 64) * DD + (kt) + sc); }
#define STTILE(buf) { \
        *(uint2*)&As[buf][sr * 24 + sc]        = f4h(pa0); \
        *(uint2*)&As[buf][(sr + 64) * 24 + sc] = f4h(pa1); \
        *(uint2*)&Ws[buf][sr * 24 + sc]        = f4h(pw0); \
        *(uint2*)&Ws[buf][(sr + 64) * 24 + sc] = f4h(pw1); }

    LDTILE(0);
    STTILE(0);
    __syncthreads();

    int cur = 0;
    for (int kt = 0; kt < DD; kt += 16) {
        const bool more = (kt + 16) < DD;
        if (more) LDTILE(kt + 16);

        uint32_t af[4][4], bf[4][2];
#pragma unroll
        for (int mt = 0; mt < 4; mt++)
            ldsm_x4(af[mt], baseA[cur] +
                    ((uint32_t)((wm * 64 + mt * 16 + aRow) * 24 + aK) << 1));
#pragma unroll
        for (int nt = 0; nt < 4; nt++)
            ldsm_x2(bf[nt], baseW[cur] +
                    ((uint32_t)((wn * 32 + nt * 8 + bRow) * 24 + bK) << 1));
#pragma unroll
        for (int mt = 0; mt < 4; mt++)
#pragma unroll
            for (int nt = 0; nt < 4; nt++)
                mma16(acc[mt][nt], af[mt], bf[nt]);

        if (more) {
            STTILE(cur ^ 1);
            __syncthreads();
        }
        cur ^= 1;
    }
#undef LDTILE
#undef STTILE

#pragma unroll
    for (int mt = 0; mt < 4; mt++) {
#pragma unroll
        for (int nt = 0; nt < 4; nt++) {
            int m0 = blockIdx.y * 128 + wm * 64 + mt * 16 + lr;
            int n0 = blockIdx.x * 128 + wn * 32 + nt * 8 + 2 * lc;
            float bx = bias[n0], by = bias[n0 + 1];
            float v00 = acc[mt][nt][0] + bx, v01 = acc[mt][nt][1] + by;
            float v10 = acc[mt][nt][2] + bx, v11 = acc[mt][nt][3] + by;
            if (head_layout) {
                __half* C = (__half*)Cv;
                int hI = n0 >> 6, hd = n0 & 63;
                int bI0 = m0 >> 10, sI0 = m0 & 1023;
                int m1 = m0 + 8;
                int bI1 = m1 >> 10, sI1 = m1 & 1023;
                *(uint32_t*)(C + (((size_t)(bI0 * HH + hI) * SS + sI0) * HD + hd)) = f2h2(v00, v01);
                *(uint32_t*)(C + (((size_t)(bI1 * HH + hI) * SS + sI1) * HD + hd)) = f2h2(v10, v11);
            } else {
                float* C = (float*)Cv;
                *(float2*)(C + (size_t)m0 * DD + n0) = make_float2(v00, v01);
                *(float2*)(C + (size_t)(m0 + 8) * DD + n0) = make_float2(v10, v11);
            }
        }
    }
}

// ---------------------------------------------------------------------------
// Flash attention, fp16 mma, register-resident P, exp2 softmax,
// fp16 inputs, packed mask bits + fp16 syn. Static smem 36KB, 2 CTAs/SM.
// ---------------------------------------------------------------------------
__global__ __launch_bounds__(256, 2) void attn_f16(
    const __half* __restrict__ gq, const __half* __restrict__ gk,
    const __half* __restrict__ gv, const uint32_t* __restrict__ maskw,
    const __half* __restrict__ synh, const float* __restrict__ alpha_param,
    float* __restrict__ out)
{
    __shared__ __align__(16) __half KV[4][64 * 72];   // K0, K1, V0, V1
    __half* Ks0 = KV[0];
    __half* Ks1 = KV[1];
    __half* Vs0 = KV[2];
    __half* Vs1 = KV[3];

    const int tid  = threadIdx.x;
    const int lane = tid & 31;
    const int warp = tid >> 5;
    const int lr   = lane >> 2;
    const int lc   = lane & 3;
    const int aRow = lane & 15;
    const int aK   = (lane >> 4) * 8;
    const int bRow = lane & 7;
    const int bK   = ((lane >> 3) & 1) * 8;
    const int b = blockIdx.y >> 4;
    const int h = blockIdx.y & 15;
    const int qbase = blockIdx.x * 128;
    const int rb = warp * 16;

    const uint32_t KsA[2] = { smem_u32(Ks0), smem_u32(Ks1) };
    const uint32_t VsA[2] = { smem_u32(Vs0), smem_u32(Vs1) };

    const float alpha = 1.0f / (1.0f + __expf(-alpha_param[0]));
    const float LOG2E = 1.4426950408889634f;
    const float sA2   = alpha * 0.125f * LOG2E;
    const float beta2 = (1.0f - alpha) * LOG2E;

    const __half* qptr = gq + ((size_t)(b * HH + h) * SS + qbase) * HD;
    const __half* kptr = gk + (size_t)(b * HH + h) * SS * HD;
    const __half* vptr = gv + (size_t)(b * HH + h) * SS * HD;

    const int tr = tid >> 4;            // 0..15
    const int tc = (tid & 15) * 4;      // 0..60

    // Stage Q (128x64 half) into Ks0||Ks1 (exactly 128*72 halves), grab frags.
    {
        __half* Qstage = Ks0;
#pragma unroll
        for (int i = 0; i < 8; i++) {
            int id = tid + i * 256;
            int r  = id >> 4;
            int c4 = (id & 15) * 4;
            *(uint2*)&Qstage[r * 72 + c4] = *(const uint2*)(qptr + (size_t)r * HD + c4);
        }
    }
    __syncthreads();

    uint32_t qf[4][4];
#pragma unroll
    for (int kk = 0; kk < 4; kk++)
        ldsm_x4(qf[kk], KsA[0] + ((uint32_t)((rb + aRow) * 72 + kk * 16 + aK) << 1));
    __syncthreads();

    // Preload KV tile 0
#pragma unroll
    for (int i = 0; i < 4; i++) {
        int r = tr + i * 16;
        *(uint2*)&Ks0[r * 72 + tc] = *(const uint2*)(kptr + (size_t)r * HD + tc);
        *(uint2*)&Vs0[r * 72 + tc] = *(const uint2*)(vptr + (size_t)r * HD + tc);
    }
    __syncthreads();

    float O[8][4];
#pragma unroll
    for (int nt = 0; nt < 8; nt++)
#pragma unroll
        for (int r = 0; r < 4; r++) O[nt][r] = 0.0f;
    float m0r = -INFINITY, m1r = -INFINITY, l0 = 0.0f, l1 = 0.0f;

    const int qr0 = qbase + rb + lr;
    const int qr1 = qr0 + 8;
    const uint32_t* mw0 = maskw + ((size_t)b * SS + qr0) * 32;
    const uint32_t* mw1 = maskw + ((size_t)b * SS + qr1) * 32;
    const __half* sy0p = synh + ((size_t)h * SS + qr0) * SS;
    const __half* sy1p = synh + ((size_t)h * SS + qr1) * SS;

    int cur = 0;
    for (int kb = 0; kb < SS; kb += 64) {
        const bool more = (kb + 64) < SS;
        __half* Kn = cur ? Ks0 : Ks1;
        __half* Vn = cur ? Vs0 : Vs1;

        // Prefetch next K tile (registers, raw halves)
        uint2 st0, st1, st2, st3;
        if (more) {
            const __half* kp = kptr + (size_t)(kb + 64) * HD;
            st0 = *(const uint2*)(kp + (size_t)(tr)      * HD + tc);
            st1 = *(const uint2*)(kp + (size_t)(tr + 16) * HD + tc);
            st2 = *(const uint2*)(kp + (size_t)(tr + 32) * HD + tc);
            st3 = *(const uint2*)(kp + (size_t)(tr + 48) * HD + tc);
        }

        // S = Q @ K^T
        float sacc[8][4];
#pragma unroll
        for (int nt = 0; nt < 8; nt++) {
            sacc[nt][0] = sacc[nt][1] = sacc[nt][2] = sacc[nt][3] = 0.0f;
#pragma unroll
            for (int kk = 0; kk < 4; kk++) {
                uint32_t bfr[2];
                ldsm_x2(bfr, KsA[cur] +
                        ((uint32_t)((nt * 8 + bRow) * 72 + kk * 16 + bK) << 1));
                mma16(sacc[nt], qf[kk], bfr);
            }
        }

        // Store prefetched K; prefetch next V
        if (more) {
            *(uint2*)&Kn[(tr)      * 72 + tc] = st0;
            *(uint2*)&Kn[(tr + 16) * 72 + tc] = st1;
            *(uint2*)&Kn[(tr + 32) * 72 + tc] = st2;
            *(uint2*)&Kn[(tr + 48) * 72 + tc] = st3;
            const __half* vp = vptr + (size_t)(kb + 64) * HD;
            st0 = *(const uint2*)(vp + (size_t)(tr)      * HD + tc);
            st1 = *(const uint2*)(vp + (size_t)(tr + 16) * HD + tc);
            st2 = *(const uint2*)(vp + (size_t)(tr + 32) * HD + tc);
            st3 = *(const uint2*)(vp + (size_t)(tr + 48) * HD + tc);
        }

        // Merge adapter + mask (log2 domain), running row max
        const uint32_t w0a = mw0[kb >> 5], w0b = mw0[(kb >> 5) + 1];
        const uint32_t w1a = mw1[kb >> 5], w1b = mw1[(kb >> 5) + 1];
        float mx0 = -INFINITY, mx1 = -INFINITY;
#pragma unroll
        for (int nt = 0; nt < 8; nt++) {
            const int pos = nt * 8 + 2 * lc;         // 0..62
            const int sh  = pos & 31;
            const uint32_t wr0 = (nt < 4) ? w0a : w0b;
            const uint32_t wr1 = (nt < 4) ? w1a : w1b;
            float2 sy0 = __half22float2(*(const __half2*)(sy0p + kb + pos));
            float2 sy1 = __half22float2(*(const __half2*)(sy1p + kb + pos));
            sacc[nt][0] = ((wr0 >> sh) & 1u)       ? fmaf(sacc[nt][0], sA2, beta2 * sy0.x) : -1.0e9f;
            sacc[nt][1] = ((wr0 >> (sh + 1)) & 1u) ? fmaf(sacc[nt][1], sA2, beta2 * sy0.y) : -1.0e9f;
            sacc[nt][2] = ((wr1 >> sh) & 1u)       ? fmaf(sacc[nt][2], sA2, beta2 * sy1.x) : -1.0e9f;
            sacc[nt][3] = ((wr1 >> (sh + 1)) & 1u) ? fmaf(sacc[nt][3], sA2, beta2 * sy1.y) : -1.0e9f;
            mx0 = fmaxf(mx0, fmaxf(sacc[nt][0], sacc[nt][1]));
            mx1 = fmaxf(mx1, fmaxf(sacc[nt][2], sacc[nt][3]));
        }
        mx0 = fmaxf(mx0, __shfl_xor_sync(0xffffffffu, mx0, 1));
        mx0 = fmaxf(mx0, __shfl_xor_sync(0xffffffffu, mx0, 2));
        mx1 = fmaxf(mx1, __shfl_xor_sync(0xffffffffu, mx1, 1));
        mx1 = fmaxf(mx1, __shfl_xor_sync(0xffffffffu, mx1, 2));

        float mn0 = fmaxf(m0r, mx0), mn1 = fmaxf(m1r, mx1);
        float sc0 = exp2f(m0r - mn0), sc1 = exp2f(m1r - mn1);
        m0r = mn0; m1r = mn1;

        // exp2 + pack P directly into A-fragments (k-block j = nt>>1)
        uint32_t pf[4][4];
        float rs0 = 0.0f, rs1 = 0.0f;
#pragma unroll
        for (int nt = 0; nt < 8; nt++) {
            float p0 = exp2f(sacc[nt][0] - mn0);
            float p1 = exp2f(sacc[nt][1] - mn0);
            float p2 = exp2f(sacc[nt][2] - mn1);
            float p3 = exp2f(sacc[nt][3] - mn1);
            rs0 += p0 + p1;
            rs1 += p2 + p3;
            pf[nt >> 1][(nt & 1) * 2 + 0] = f2h2(p0, p1);
            pf[nt >> 1][(nt & 1) * 2 + 1] = f2h2(p2, p3);
        }
        rs0 += __shfl_xor_sync(0xffffffffu, rs0, 1);
        rs0 += __shfl_xor_sync(0xffffffffu, rs0, 2);
        rs1 += __shfl_xor_sync(0xffffffffu, rs1, 1);
        rs1 += __shfl_xor_sync(0xffffffffu, rs1, 2);
        l0 = l0 * sc0 + rs0;
        l1 = l1 * sc1 + rs1;

#pragma unroll
        for (int nt = 0; nt < 8; nt++) {
            O[nt][0] *= sc0; O[nt][1] *= sc0;
            O[nt][2] *= sc1; O[nt][3] *= sc1;
        }

        // O += P @ V   (P in registers, V via ldmatrix.trans)
#pragma unroll
        for (int j = 0; j < 4; j++) {
#pragma unroll
            for (int nt = 0; nt < 8; nt++) {
                uint32_t bfr[2];
                ldsm_x2t(bfr, VsA[cur] +
                         ((uint32_t)((j * 16 + aRow) * 72 + nt * 8) << 1));
                mma16(O[nt], pf[j], bfr);
            }
        }

        // Store prefetched V
        if (more) {
            *(uint2*)&Vn[(tr)      * 72 + tc] = st0;
            *(uint2*)&Vn[(tr + 16) * 72 + tc] = st1;
            *(uint2*)&Vn[(tr + 32) * 72 + tc] = st2;
            *(uint2*)&Vn[(tr + 48) * 72 + tc] = st3;
        }
        __syncthreads();
        cur ^= 1;
    }

    // Epilogue: normalize, write (b, s, h*64+hd) in fp32
    float inv0 = 1.0f / l0, inv1 = 1.0f / l1;
    float* o0 = out + ((size_t)b * SS + qr0) * DD + h * HD;
    float* o1 = out + ((size_t)b * SS + qr1) * DD + h * HD;
#pragma unroll
    for (int nt = 0; nt < 8; nt++) {
        int c = nt * 8 + 2 * lc;
        *(float2*)(o0 + c) = make_float2(O[nt][0] * inv0, O[nt][1] * inv0);
        *(float2*)(o1 + c) = make_float2(O[nt][2] * inv1, O[nt][3] * inv1);
    }
}

// ---------------------------------------------------------------------------
extern "C" void kernel_launch(void* const* d_in, const int* in_sizes, int n_in,
                              void* d_out, int out_size)
{
    const float* query  = (const float*)d_in[0];
    const float* key_in = (const float*)d_in[1];
    const float* value  = (const float*)d_in[2];
    const int*   mask   = (const int*)d_in[3];
    const float* Wq = (const float*)d_in[4];
    const float* bq = (const float*)d_in[5];
    const float* Wk = (const float*)d_in[6];
    const float* bk = (const float*)d_in[7];
    const float* Wv = (const float*)d_in[8];
    const float* bv = (const float*)d_in[9];
    const float* Wo = (const float*)d_in[10];
    const float* bo = (const float*)d_in[11];
    const float* syn = (const float*)d_in[12];
    const float* alpha_param = (const float*)d_in[13];
    float* out = (float*)d_out;

    __half *pq, *pk, *pv, *psynh;
    float *pao;
    uint32_t *pmw;
    cudaGetSymbolAddress((void**)&pq, g_q);
    cudaGetSymbolAddress((void**)&pk, g_k);
    cudaGetSymbolAddress((void**)&pv, g_v);
    cudaGetSymbolAddress((void**)&pao, g_ao);
    cudaGetSymbolAddress((void**)&pmw, g_maskw);
    cudaGetSymbolAddress((void**)&psynh, g_synh);

    dim3 gg(DD / 128, (BB * SS) / 128);   // (8, 64)

    // Prep: pack mask bits, convert syn to fp16
    pack_mask<<<(BB * SS * (SS / 32)) / 256, 256>>>(mask, pmw);
    syn_to_half<<<(HH * SS * SS / 4) / 256, 256>>>(syn, psynh);

    gemm_f16<<<gg, 256>>>(query,  Wq, bq, pq, 1);
    gemm_f16<<<gg, 256>>>(key_in, Wk, bk, pk, 1);
    gemm_f16<<<gg, 256>>>(value,  Wv, bv, pv, 1);

    attn_f16<<<dim3(SS / 128, BB * HH), 256>>>(
        pq, pk, pv, pmw, psynh, alpha_param, pao);

    gemm_f16<<<gg, 256>>>(pao, Wo, bo, out, 0);
}

// round 8
// speedup vs baseline: 5.1723x; 1.0064x over previous
#include <cuda_runtime.h>
#include <cuda_fp16.h>
#include <math.h>
#include <stdint.h>

#define BB 8
#define SS 1024
#define DD 1024
#define HH 16
#define HD 64

// Scratch (device globals: allocation-free rule workaround)
__device__ __half   g_q[(size_t)BB * SS * DD];
__device__ __half   g_k[(size_t)BB * SS * DD];
__device__ __half   g_v[(size_t)BB * SS * DD];
__device__ __half   g_aoh[(size_t)BB * SS * DD];
__device__ uint32_t g_maskw[(size_t)BB * SS * (SS / 32)];
__device__ __half   g_synh[(size_t)HH * SS * SS];
__device__ __half   g_qin[(size_t)BB * SS * DD];
__device__ __half   g_kin[(size_t)BB * SS * DD];
__device__ __half   g_vin[(size_t)BB * SS * DD];
__device__ __half   g_wq[(size_t)DD * DD];
__device__ __half   g_wk[(size_t)DD * DD];
__device__ __half   g_wv[(size_t)DD * DD];
__device__ __half   g_wo[(size_t)DD * DD];

__device__ __forceinline__ uint32_t smem_u32(const void* p) {
    uint32_t a;
    asm("{ .reg .u64 t; cvta.to.shared.u64 t, %1; cvt.u32.u64 %0, t; }" : "=r"(a) : "l"(p));
    return a;
}
__device__ __forceinline__ uint32_t f2h2(float lo, float hi) {
    __half2 h = __floats2half2_rn(lo, hi);
    return *(uint32_t*)&h;
}
__device__ __forceinline__ uint2 f4h(float4 t) {
    return make_uint2(f2h2(t.x, t.y), f2h2(t.z, t.w));
}

__device__ __forceinline__ void mma16(float* d, const uint32_t* a, const uint32_t* b) {
    asm volatile(
        "mma.sync.aligned.m16n8k16.row.col.f32.f16.f16.f32 "
        "{%0,%1,%2,%3}, {%4,%5,%6,%7}, {%8,%9}, {%0,%1,%2,%3};"
        : "+f"(d[0]), "+f"(d[1]), "+f"(d[2]), "+f"(d[3])
        : "r"(a[0]), "r"(a[1]), "r"(a[2]), "r"(a[3]), "r"(b[0]), "r"(b[1]));
}
__device__ __forceinline__ void ldsm_x4(uint32_t* r, uint32_t addr) {
    asm volatile("ldmatrix.sync.aligned.m8n8.x4.shared.b16 {%0,%1,%2,%3}, [%4];"
                 : "=r"(r[0]), "=r"(r[1]), "=r"(r[2]), "=r"(r[3]) : "r"(addr));
}
__device__ __forceinline__ void ldsm_x2(uint32_t* r, uint32_t addr) {
    asm volatile("ldmatrix.sync.aligned.m8n8.x2.shared.b16 {%0,%1}, [%2];"
                 : "=r"(r[0]), "=r"(r[1]) : "r"(addr));
}
__device__ __forceinline__ void ldsm_x2t(uint32_t* r, uint32_t addr) {
    asm volatile("ldmatrix.sync.aligned.m8n8.x2.trans.shared.b16 {%0,%1}, [%2];"
                 : "=r"(r[0]), "=r"(r[1]) : "r"(addr));
}
__device__ __forceinline__ void cpa16(uint32_t dst, const void* src) {
    asm volatile("cp.async.cg.shared.global [%0], [%1], 16;"
                 :: "r"(dst), "l"(src) : "memory");
}
__device__ __forceinline__ void cpa_commit() {
    asm volatile("cp.async.commit_group;" ::: "memory");
}
template <int N> __device__ __forceinline__ void cpa_wait() {
    asm volatile("cp.async.wait_group %0;" :: "n"(N) : "memory");
}

// ---------------------------------------------------------------------------
// Prep kernels
// ---------------------------------------------------------------------------
__global__ __launch_bounds__(256) void pack_mask(const int* __restrict__ mask,
                                                 uint32_t* __restrict__ mw)
{
    const size_t w = (size_t)blockIdx.x * 256 + threadIdx.x;
    const int4* p = (const int4*)(mask + w * 32);
    uint32_t bits = 0;
#pragma unroll
    for (int i = 0; i < 8; i++) {
        int4 v = p[i];
        bits |= (v.x != 0 ? 1u : 0u) << (i * 4 + 0);
        bits |= (v.y != 0 ? 1u : 0u) << (i * 4 + 1);
        bits |= (v.z != 0 ? 1u : 0u) << (i * 4 + 2);
        bits |= (v.w != 0 ? 1u : 0u) << (i * 4 + 3);
    }
    mw[w] = bits;
}

__global__ __launch_bounds__(256) void f32_to_f16(const float* __restrict__ in,
                                                  __half* __restrict__ out)
{
    const size_t i = (size_t)blockIdx.x * 256 + threadIdx.x;   // float4 index
    float4 t = *(const float4*)(in + i * 4);
    *(uint2*)(out + i * 4) = f4h(t);
}

// ---------------------------------------------------------------------------
// GEMM (all-fp16 inputs): C = A[M,K] @ W[N,K]^T + bias
// cp.async double-buffered k16 slices; ldmatrix x4 for A and B; fp16/fp32 out.
// Block 128x128, 8 warps (2x4), warp tile 64x32, 2 CTAs/SM.
// ---------------------------------------------------------------------------
__global__ __launch_bounds__(256, 2) void gemm_h(
    const __half* __restrict__ A, const __half* __restrict__ W,
    const float* __restrict__ bias, void* __restrict__ Cv, int head_layout)
{
    __shared__ __align__(16) __half As[2][128 * 24];
    __shared__ __align__(16) __half Ws[2][128 * 24];

    const int tid  = threadIdx.x;
    const int lane = tid & 31;
    const int warp = tid >> 5;
    const int wm   = warp >> 2;
    const int wn   = warp & 3;
    const int lr   = lane >> 2;
    const int lc   = lane & 3;
    const int aRow = lane & 15;
    const int aK   = (lane >> 4) * 8;
    const int bRow16 = (lane >> 4) * 8 + (lane & 7);   // row within 16-row group
    const int bCol   = ((lane >> 3) & 1) * 8;

    // cp.async mapping: 128x16 halves = 256 x 16B chunks; 1 per thread per matrix
    const int sr = tid >> 1;            // 0..127
    const int sc = (tid & 1) * 8;       // 0 or 8 (halves)

    const __half* Ab = A + (size_t)(blockIdx.y * 128) * DD;
    const __half* Wb = W + (size_t)(blockIdx.x * 128) * DD;

    const uint32_t baseA[2] = { smem_u32(As[0]), smem_u32(As[1]) };
    const uint32_t baseW[2] = { smem_u32(Ws[0]), smem_u32(Ws[1]) };
    const uint32_t dstOff = (uint32_t)(sr * 24 + sc) * 2;

    float acc[4][4][4];
#pragma unroll
    for (int mt = 0; mt < 4; mt++)
#pragma unroll
        for (int nt = 0; nt < 4; nt++)
#pragma unroll
            for (int r = 0; r < 4; r++) acc[mt][nt][r] = 0.0f;

#define ISSUE(buf, kh) { \
        cpa16(baseA[buf] + dstOff, Ab + (size_t)sr * DD + (kh) + sc); \
        cpa16(baseW[buf] + dstOff, Wb + (size_t)sr * DD + (kh) + sc); \
        cpa_commit(); }

    ISSUE(0, 0);

    int cur = 0;
    for (int kt = 0; kt < 64; kt++) {           // 64 slices of k=16
        const bool more = (kt + 1) < 64;
        if (more) ISSUE(cur ^ 1, (kt + 1) * 16);

        if (more) cpa_wait<1>(); else cpa_wait<0>();
        __syncthreads();

        uint32_t af[4][4], bf[4][2];
#pragma unroll
        for (int mt = 0; mt < 4; mt++)
            ldsm_x4(af[mt], baseA[cur] +
                    ((uint32_t)((wm * 64 + mt * 16 + aRow) * 24 + aK) << 1));
#pragma unroll
        for (int p = 0; p < 2; p++) {
            uint32_t t4[4];
            ldsm_x4(t4, baseW[cur] +
                    ((uint32_t)((wn * 32 + p * 16 + bRow16) * 24 + bCol) << 1));
            bf[p * 2][0] = t4[0]; bf[p * 2][1] = t4[1];
            bf[p * 2 + 1][0] = t4[2]; bf[p * 2 + 1][1] = t4[3];
        }
#pragma unroll
        for (int mt = 0; mt < 4; mt++)
#pragma unroll
            for (int nt = 0; nt < 4; nt++)
                mma16(acc[mt][nt], af[mt], bf[nt]);

        if (more) __syncthreads();   // protect cur buffer before re-fill
        cur ^= 1;
    }
#undef ISSUE

    // Epilogue
#pragma unroll
    for (int mt = 0; mt < 4; mt++) {
#pragma unroll
        for (int nt = 0; nt < 4; nt++) {
            int m0 = blockIdx.y * 128 + wm * 64 + mt * 16 + lr;
            int n0 = blockIdx.x * 128 + wn * 32 + nt * 8 + 2 * lc;
            float bx = bias[n0], by = bias[n0 + 1];
            float v00 = acc[mt][nt][0] + bx, v01 = acc[mt][nt][1] + by;
            float v10 = acc[mt][nt][2] + bx, v11 = acc[mt][nt][3] + by;
            if (head_layout) {
                __half* C = (__half*)Cv;
                int hI = n0 >> 6, hd = n0 & 63;
                int bI0 = m0 >> 10, sI0 = m0 & 1023;
                int m1 = m0 + 8;
                int bI1 = m1 >> 10, sI1 = m1 & 1023;
                *(uint32_t*)(C + (((size_t)(bI0 * HH + hI) * SS + sI0) * HD + hd)) = f2h2(v00, v01);
                *(uint32_t*)(C + (((size_t)(bI1 * HH + hI) * SS + sI1) * HD + hd)) = f2h2(v10, v11);
            } else {
                float* C = (float*)Cv;
                *(float2*)(C + (size_t)m0 * DD + n0) = make_float2(v00, v01);
                *(float2*)(C + (size_t)(m0 + 8) * DD + n0) = make_float2(v10, v11);
            }
        }
    }
}

// ---------------------------------------------------------------------------
// Flash attention (structure unchanged from R7; fp16 output)
// ---------------------------------------------------------------------------
__global__ __launch_bounds__(256, 2) void attn_f16(
    const __half* __restrict__ gq, const __half* __restrict__ gk,
    const __half* __restrict__ gv, const uint32_t* __restrict__ maskw,
    const __half* __restrict__ synh, const float* __restrict__ alpha_param,
    __half* __restrict__ out)
{
    __shared__ __align__(16) __half KV[4][64 * 72];
    __half* Ks0 = KV[0];
    __half* Ks1 = KV[1];
    __half* Vs0 = KV[2];
    __half* Vs1 = KV[3];

    const int tid  = threadIdx.x;
    const int lane = tid & 31;
    const int warp = tid >> 5;
    const int lr   = lane >> 2;
    const int lc   = lane & 3;
    const int aRow = lane & 15;
    const int aK   = (lane >> 4) * 8;
    const int bRow = lane & 7;
    const int bK   = ((lane >> 3) & 1) * 8;
    const int b = blockIdx.y >> 4;
    const int h = blockIdx.y & 15;
    const int qbase = blockIdx.x * 128;
    const int rb = warp * 16;

    const uint32_t KsA[2] = { smem_u32(Ks0), smem_u32(Ks1) };
    const uint32_t VsA[2] = { smem_u32(Vs0), smem_u32(Vs1) };

    const float alpha = 1.0f / (1.0f + __expf(-alpha_param[0]));
    const float LOG2E = 1.4426950408889634f;
    const float sA2   = alpha * 0.125f * LOG2E;
    const float beta2 = (1.0f - alpha) * LOG2E;

    const __half* qptr = gq + ((size_t)(b * HH + h) * SS + qbase) * HD;
    const __half* kptr = gk + (size_t)(b * HH + h) * SS * HD;
    const __half* vptr = gv + (size_t)(b * HH + h) * SS * HD;

    const int tr = tid >> 4;
    const int tc = (tid & 15) * 4;

    // Stage Q through Ks0||Ks1, grab fragments
    {
        __half* Qstage = Ks0;
#pragma unroll
        for (int i = 0; i < 8; i++) {
            int id = tid + i * 256;
            int r  = id >> 4;
            int c4 = (id & 15) * 4;
            *(uint2*)&Qstage[r * 72 + c4] = *(const uint2*)(qptr + (size_t)r * HD + c4);
        }
    }
    __syncthreads();

    uint32_t qf[4][4];
#pragma unroll
    for (int kk = 0; kk < 4; kk++)
        ldsm_x4(qf[kk], KsA[0] + ((uint32_t)((rb + aRow) * 72 + kk * 16 + aK) << 1));
    __syncthreads();

#pragma unroll
    for (int i = 0; i < 4; i++) {
        int r = tr + i * 16;
        *(uint2*)&Ks0[r * 72 + tc] = *(const uint2*)(kptr + (size_t)r * HD + tc);
        *(uint2*)&Vs0[r * 72 + tc] = *(const uint2*)(vptr + (size_t)r * HD + tc);
    }
    __syncthreads();

    float O[8][4];
#pragma unroll
    for (int nt = 0; nt < 8; nt++)
#pragma unroll
        for (int r = 0; r < 4; r++) O[nt][r] = 0.0f;
    float m0r = -INFINITY, m1r = -INFINITY, l0 = 0.0f, l1 = 0.0f;

    const int qr0 = qbase + rb + lr;
    const int qr1 = qr0 + 8;
    const uint32_t* mw0 = maskw + ((size_t)b * SS + qr0) * 32;
    const uint32_t* mw1 = maskw + ((size_t)b * SS + qr1) * 32;
    const __half* sy0p = synh + ((size_t)h * SS + qr0) * SS;
    const __half* sy1p = synh + ((size_t)h * SS + qr1) * SS;

    int cur = 0;
    for (int kb = 0; kb < SS; kb += 64) {
        const bool more = (kb + 64) < SS;
        __half* Kn = cur ? Ks0 : Ks1;
        __half* Vn = cur ? Vs0 : Vs1;

        uint2 st0, st1, st2, st3;
        if (more) {
            const __half* kp = kptr + (size_t)(kb + 64) * HD;
            st0 = *(const uint2*)(kp + (size_t)(tr)      * HD + tc);
            st1 = *(const uint2*)(kp + (size_t)(tr + 16) * HD + tc);
            st2 = *(const uint2*)(kp + (size_t)(tr + 32) * HD + tc);
            st3 = *(const uint2*)(kp + (size_t)(tr + 48) * HD + tc);
        }

        float sacc[8][4];
#pragma unroll
        for (int nt = 0; nt < 8; nt++) {
            sacc[nt][0] = sacc[nt][1] = sacc[nt][2] = sacc[nt][3] = 0.0f;
#pragma unroll
            for (int kk = 0; kk < 4; kk++) {
                uint32_t bfr[2];
                ldsm_x2(bfr, KsA[cur] +
                        ((uint32_t)((nt * 8 + bRow) * 72 + kk * 16 + bK) << 1));
                mma16(sacc[nt], qf[kk], bfr);
            }
        }

        if (more) {
            *(uint2*)&Kn[(tr)      * 72 + tc] = st0;
            *(uint2*)&Kn[(tr + 16) * 72 + tc] = st1;
            *(uint2*)&Kn[(tr + 32) * 72 + tc] = st2;
            *(uint2*)&Kn[(tr + 48) * 72 + tc] = st3;
            const __half* vp = vptr + (size_t)(kb + 64) * HD;
            st0 = *(const uint2*)(vp + (size_t)(tr)      * HD + tc);
            st1 = *(const uint2*)(vp + (size_t)(tr + 16) * HD + tc);
            st2 = *(const uint2*)(vp + (size_t)(tr + 32) * HD + tc);
            st3 = *(const uint2*)(vp + (size_t)(tr + 48) * HD + tc);
        }

        const uint32_t w0a = mw0[kb >> 5], w0b = mw0[(kb >> 5) + 1];
        const uint32_t w1a = mw1[kb >> 5], w1b = mw1[(kb >> 5) + 1];
        float mx0 = -INFINITY, mx1 = -INFINITY;
#pragma unroll
        for (int nt = 0; nt < 8; nt++) {
            const int pos = nt * 8 + 2 * lc;
            const int sh  = pos & 31;
            const uint32_t wr0 = (nt < 4) ? w0a : w0b;
            const uint32_t wr1 = (nt < 4) ? w1a : w1b;
            float2 sy0 = __half22float2(*(const __half2*)(sy0p + kb + pos));
            float2 sy1 = __half22float2(*(const __half2*)(sy1p + kb + pos));
            sacc[nt][0] = ((wr0 >> sh) & 1u)       ? fmaf(sacc[nt][0], sA2, beta2 * sy0.x) : -1.0e9f;
            sacc[nt][1] = ((wr0 >> (sh + 1)) & 1u) ? fmaf(sacc[nt][1], sA2, beta2 * sy0.y) : -1.0e9f;
            sacc[nt][2] = ((wr1 >> sh) & 1u)       ? fmaf(sacc[nt][2], sA2, beta2 * sy1.x) : -1.0e9f;
            sacc[nt][3] = ((wr1 >> (sh + 1)) & 1u) ? fmaf(sacc[nt][3], sA2, beta2 * sy1.y) : -1.0e9f;
            mx0 = fmaxf(mx0, fmaxf(sacc[nt][0], sacc[nt][1]));
            mx1 = fmaxf(mx1, fmaxf(sacc[nt][2], sacc[nt][3]));
        }
        mx0 = fmaxf(mx0, __shfl_xor_sync(0xffffffffu, mx0, 1));
        mx0 = fmaxf(mx0, __shfl_xor_sync(0xffffffffu, mx0, 2));
        mx1 = fmaxf(mx1, __shfl_xor_sync(0xffffffffu, mx1, 1));
        mx1 = fmaxf(mx1, __shfl_xor_sync(0xffffffffu, mx1, 2));

        float mn0 = fmaxf(m0r, mx0), mn1 = fmaxf(m1r, mx1);
        float sc0 = exp2f(m0r - mn0), sc1 = exp2f(m1r - mn1);
        m0r = mn0; m1r = mn1;

        uint32_t pf[4][4];
        float rs0 = 0.0f, rs1 = 0.0f;
#pragma unroll
        for (int nt = 0; nt < 8; nt++) {
            float p0 = exp2f(sacc[nt][0] - mn0);
            float p1 = exp2f(sacc[nt][1] - mn0);
            float p2 = exp2f(sacc[nt][2] - mn1);
            float p3 = exp2f(sacc[nt][3] - mn1);
            rs0 += p0 + p1;
            rs1 += p2 + p3;
            pf[nt >> 1][(nt & 1) * 2 + 0] = f2h2(p0, p1);
            pf[nt >> 1][(nt & 1) * 2 + 1] = f2h2(p2, p3);
        }
        rs0 += __shfl_xor_sync(0xffffffffu, rs0, 1);
        rs0 += __shfl_xor_sync(0xffffffffu, rs0, 2);
        rs1 += __shfl_xor_sync(0xffffffffu, rs1, 1);
        rs1 += __shfl_xor_sync(0xffffffffu, rs1, 2);
        l0 = l0 * sc0 + rs0;
        l1 = l1 * sc1 + rs1;

#pragma unroll
        for (int nt = 0; nt < 8; nt++) {
            O[nt][0] *= sc0; O[nt][1] *= sc0;
            O[nt][2] *= sc1; O[nt][3] *= sc1;
        }

#pragma unroll
        for (int j = 0; j < 4; j++) {
#pragma unroll
            for (int nt = 0; nt < 8; nt++) {
                uint32_t bfr[2];
                ldsm_x2t(bfr, VsA[cur] +
                         ((uint32_t)((j * 16 + aRow) * 72 + nt * 8) << 1));
                mma16(O[nt], pf[j], bfr);
            }
        }

        if (more) {
            *(uint2*)&Vn[(tr)      * 72 + tc] = st0;
            *(uint2*)&Vn[(tr + 16) * 72 + tc] = st1;
            *(uint2*)&Vn[(tr + 32) * 72 + tc] = st2;
            *(uint2*)&Vn[(tr + 48) * 72 + tc] = st3;
        }
        __syncthreads();
        cur ^= 1;
    }

    // Epilogue: normalize, write fp16 (b, s, h*64+hd)
    float inv0 = 1.0f / l0, inv1 = 1.0f / l1;
    __half* o0 = out + ((size_t)b * SS + qr0) * DD + h * HD;
    __half* o1 = out + ((size_t)b * SS + qr1) * DD + h * HD;
#pragma unroll
    for (int nt = 0; nt < 8; nt++) {
        int c = nt * 8 + 2 * lc;
        *(uint32_t*)(o0 + c) = f2h2(O[nt][0] * inv0, O[nt][1] * inv0);
        *(uint32_t*)(o1 + c) = f2h2(O[nt][2] * inv1, O[nt][3] * inv1);
    }
}

// ---------------------------------------------------------------------------
extern "C" void kernel_launch(void* const* d_in, const int* in_sizes, int n_in,
                              void* d_out, int out_size)
{
    const float* query  = (const float*)d_in[0];
    const float* key_in = (const float*)d_in[1];
    const float* value  = (const float*)d_in[2];
    const int*   mask   = (const int*)d_in[3];
    const float* Wq = (const float*)d_in[4];
    const float* bq = (const float*)d_in[5];
    const float* Wk = (const float*)d_in[6];
    const float* bk = (const float*)d_in[7];
    const float* Wv = (const float*)d_in[8];
    const float* bv = (const float*)d_in[9];
    const float* Wo = (const float*)d_in[10];
    const float* bo = (const float*)d_in[11];
    const float* syn = (const float*)d_in[12];
    const float* alpha_param = (const float*)d_in[13];
    float* out = (float*)d_out;

    __half *pq, *pk, *pv, *paoh, *psynh, *pqin, *pkin, *pvin, *pwq, *pwk, *pwv, *pwo;
    uint32_t *pmw;
    cudaGetSymbolAddress((void**)&pq, g_q);
    cudaGetSymbolAddress((void**)&pk, g_k);
    cudaGetSymbolAddress((void**)&pv, g_v);
    cudaGetSymbolAddress((void**)&paoh, g_aoh);
    cudaGetSymbolAddress((void**)&pmw, g_maskw);
    cudaGetSymbolAddress((void**)&psynh, g_synh);
    cudaGetSymbolAddress((void**)&pqin, g_qin);
    cudaGetSymbolAddress((void**)&pkin, g_kin);
    cudaGetSymbolAddress((void**)&pvin, g_vin);
    cudaGetSymbolAddress((void**)&pwq, g_wq);
    cudaGetSymbolAddress((void**)&pwk, g_wk);
    cudaGetSymbolAddress((void**)&pwv, g_wv);
    cudaGetSymbolAddress((void**)&pwo, g_wo);

    const int ACT4 = (BB * SS * DD) / 4 / 256;   // 8192 blocks
    const int W4   = (DD * DD) / 4 / 256;        // 1024 blocks

    // Prep: fp16 conversions + mask packing
    pack_mask<<<(BB * SS * (SS / 32)) / 256, 256>>>(mask, pmw);
    f32_to_f16<<<(HH * SS * SS / 4) / 256, 256>>>(syn, psynh);
    f32_to_f16<<<ACT4, 256>>>(query,  pqin);
    f32_to_f16<<<ACT4, 256>>>(key_in, pkin);
    f32_to_f16<<<ACT4, 256>>>(value,  pvin);
    f32_to_f16<<<W4, 256>>>(Wq, pwq);
    f32_to_f16<<<W4, 256>>>(Wk, pwk);
    f32_to_f16<<<W4, 256>>>(Wv, pwv);
    f32_to_f16<<<W4, 256>>>(Wo, pwo);

    dim3 gg(DD / 128, (BB * SS) / 128);   // (8, 64)

    gemm_h<<<gg, 256>>>(pqin, pwq, bq, pq, 1);
    gemm_h<<<gg, 256>>>(pkin, pwk, bk, pk, 1);
    gemm_h<<<gg, 256>>>(pvin, pwv, bv, pv, 1);

    attn_f16<<<dim3(SS / 128, BB * HH), 256>>>(
        pq, pk, pv, pmw, psynh, alpha_param, paoh);

    gemm_h<<<gg, 256>>>(paoh, pwo, bo, out, 0);
}

// round 9
// speedup vs baseline: 5.7633x; 1.1143x over previous
#include <cuda_runtime.h>
#include <cuda_fp16.h>
#include <math.h>
#include <stdint.h>

#define BB 8
#define SS 1024
#define DD 1024
#define HH 16
#define HD 64

// Scratch (device globals: allocation-free rule workaround)
__device__ __half   g_q[(size_t)BB * SS * DD];
__device__ __half   g_k[(size_t)BB * SS * DD];
__device__ __half   g_v[(size_t)BB * SS * DD];
__device__ __half   g_aoh[(size_t)BB * SS * DD];
__device__ uint32_t g_maskw[(size_t)BB * SS * (SS / 32)];
__device__ __half   g_synh[(size_t)HH * SS * SS];
__device__ __half   g_qin[(size_t)BB * SS * DD];
__device__ __half   g_kin[(size_t)BB * SS * DD];
__device__ __half   g_vin[(size_t)BB * SS * DD];
__device__ __half   g_wq[(size_t)DD * DD];
__device__ __half   g_wk[(size_t)DD * DD];
__device__ __half   g_wv[(size_t)DD * DD];
__device__ __half   g_wo[(size_t)DD * DD];

__device__ __forceinline__ uint32_t smem_u32(const void* p) {
    uint32_t a;
    asm("{ .reg .u64 t; cvta.to.shared.u64 t, %1; cvt.u32.u64 %0, t; }" : "=r"(a) : "l"(p));
    return a;
}
__device__ __forceinline__ uint32_t f2h2(float lo, float hi) {
    __half2 h = __floats2half2_rn(lo, hi);
    return *(uint32_t*)&h;
}
__device__ __forceinline__ uint2 f4h(float4 t) {
    return make_uint2(f2h2(t.x, t.y), f2h2(t.z, t.w));
}

__device__ __forceinline__ void mma16(float* d, const uint32_t* a, const uint32_t* b) {
    asm volatile(
        "mma.sync.aligned.m16n8k16.row.col.f32.f16.f16.f32 "
        "{%0,%1,%2,%3}, {%4,%5,%6,%7}, {%8,%9}, {%0,%1,%2,%3};"
        : "+f"(d[0]), "+f"(d[1]), "+f"(d[2]), "+f"(d[3])
        : "r"(a[0]), "r"(a[1]), "r"(a[2]), "r"(a[3]), "r"(b[0]), "r"(b[1]));
}
__device__ __forceinline__ void ldsm_x4(uint32_t* r, uint32_t addr) {
    asm volatile("ldmatrix.sync.aligned.m8n8.x4.shared.b16 {%0,%1,%2,%3}, [%4];"
                 : "=r"(r[0]), "=r"(r[1]), "=r"(r[2]), "=r"(r[3]) : "r"(addr));
}
__device__ __forceinline__ void ldsm_x2(uint32_t* r, uint32_t addr) {
    asm volatile("ldmatrix.sync.aligned.m8n8.x2.shared.b16 {%0,%1}, [%2];"
                 : "=r"(r[0]), "=r"(r[1]) : "r"(addr));
}
__device__ __forceinline__ void ldsm_x2t(uint32_t* r, uint32_t addr) {
    asm volatile("ldmatrix.sync.aligned.m8n8.x2.trans.shared.b16 {%0,%1}, [%2];"
                 : "=r"(r[0]), "=r"(r[1]) : "r"(addr));
}
__device__ __forceinline__ void cpa16(uint32_t dst, const void* src) {
    asm volatile("cp.async.cg.shared.global [%0], [%1], 16;"
                 :: "r"(dst), "l"(src) : "memory");
}
__device__ __forceinline__ void cpa_commit() {
    asm volatile("cp.async.commit_group;" ::: "memory");
}
template <int N> __device__ __forceinline__ void cpa_wait() {
    asm volatile("cp.async.wait_group %0;" :: "n"(N) : "memory");
}

// ---------------------------------------------------------------------------
// Prep kernels (consolidated)
// ---------------------------------------------------------------------------
__global__ __launch_bounds__(256) void pack_mask(const int* __restrict__ mask,
                                                 uint32_t* __restrict__ mw)
{
    const size_t w = (size_t)blockIdx.x * 256 + threadIdx.x;
    const int4* p = (const int4*)(mask + w * 32);
    uint32_t bits = 0;
#pragma unroll
    for (int i = 0; i < 8; i++) {
        int4 v = p[i];
        bits |= (v.x != 0 ? 1u : 0u) << (i * 4 + 0);
        bits |= (v.y != 0 ? 1u : 0u) << (i * 4 + 1);
        bits |= (v.z != 0 ? 1u : 0u) << (i * 4 + 2);
        bits |= (v.w != 0 ? 1u : 0u) << (i * 4 + 3);
    }
    mw[w] = bits;
}

// syn: convert to fp16 pre-scaled by (1-alpha)*log2(e)
__global__ __launch_bounds__(256) void syn_prep(const float* __restrict__ syn,
                                                const float* __restrict__ alpha_param,
                                                __half* __restrict__ out)
{
    const float alpha = 1.0f / (1.0f + __expf(-alpha_param[0]));
    const float beta2 = (1.0f - alpha) * 1.4426950408889634f;
    const size_t i = (size_t)blockIdx.x * 256 + threadIdx.x;
    float4 t = *(const float4*)(syn + i * 4);
    t.x *= beta2; t.y *= beta2; t.z *= beta2; t.w *= beta2;
    *(uint2*)(out + i * 4) = f4h(t);
}

// activations: blockIdx.y selects q/k/v
__global__ __launch_bounds__(256) void conv_acts(
    const float* __restrict__ q, const float* __restrict__ k, const float* __restrict__ v,
    __half* __restrict__ oq, __half* __restrict__ ok, __half* __restrict__ ov)
{
    const float* src = (blockIdx.y == 0) ? q : (blockIdx.y == 1) ? k : v;
    __half* dst = (blockIdx.y == 0) ? oq : (blockIdx.y == 1) ? ok : ov;
    const size_t i = (size_t)blockIdx.x * 256 + threadIdx.x;
    float4 t = *(const float4*)(src + i * 4);
    *(uint2*)(dst + i * 4) = f4h(t);
}

// weights: blockIdx.y selects Wq/Wk/Wv/Wo
__global__ __launch_bounds__(256) void conv_w(
    const float* __restrict__ wq, const float* __restrict__ wk,
    const float* __restrict__ wv, const float* __restrict__ wo,
    __half* __restrict__ oq, __half* __restrict__ ok,
    __half* __restrict__ ov, __half* __restrict__ oo)
{
    const float* src = (blockIdx.y == 0) ? wq : (blockIdx.y == 1) ? wk
                     : (blockIdx.y == 2) ? wv : wo;
    __half* dst = (blockIdx.y == 0) ? oq : (blockIdx.y == 1) ? ok
                : (blockIdx.y == 2) ? ov : oo;
    const size_t i = (size_t)blockIdx.x * 256 + threadIdx.x;
    float4 t = *(const float4*)(src + i * 4);
    *(uint2*)(dst + i * 4) = f4h(t);
}

// ---------------------------------------------------------------------------
// GEMM: C = A[M,K] @ W[N,K]^T + bias.  fp16 in, 3-stage cp.async, k-slice 32.
// Block 128x128, 8 warps (2x4), warp tile 64x32, 2 CTAs/SM.
// smem per stage: A 128x40h + W 128x40h = 20480B; 3 stages = 61440B dynamic.
// ---------------------------------------------------------------------------
#define GSTRIDE 40
#define GSTAGE_H (128 * GSTRIDE)

__global__ __launch_bounds__(256, 2) void gemm_h(
    const __half* __restrict__ A, const __half* __restrict__ W,
    const float* __restrict__ bias, void* __restrict__ Cv, int head_layout)
{
    extern __shared__ __align__(16) __half smh[];
    // layout: [stage][A(128*40) | W(128*40)]
    const int tid  = threadIdx.x;
    const int lane = tid & 31;
    const int warp = tid >> 5;
    const int wm   = warp >> 2;
    const int wn   = warp & 3;
    const int lr   = lane >> 2;
    const int lc   = lane & 3;
    const int aRow = lane & 15;
    const int aK   = (lane >> 4) * 8;
    const int bRow16 = (lane >> 4) * 8 + (lane & 7);
    const int bCol   = ((lane >> 3) & 1) * 8;

    // cp.async fill geometry: 128x32 halves = 512 x 16B chunks per matrix
    const int fr  = tid >> 2;           // rows 0..63 (+64)
    const int fch = (tid & 3) * 8;      // half col 0,8,16,24

    const __half* Ab = A + (size_t)(blockIdx.y * 128) * DD;
    const __half* Wb = W + (size_t)(blockIdx.x * 128) * DD;

    const uint32_t base = smem_u32(smh);
    uint32_t sA[3], sW[3];
#pragma unroll
    for (int s = 0; s < 3; s++) {
        sA[s] = base + (uint32_t)(s * 2 * GSTAGE_H) * 2;
        sW[s] = base + (uint32_t)((s * 2 + 1) * GSTAGE_H) * 2;
    }
    const uint32_t d0 = (uint32_t)(fr * GSTRIDE + fch) * 2;
    const uint32_t d1 = (uint32_t)((fr + 64) * GSTRIDE + fch) * 2;

    float acc[4][4][4];
#pragma unroll
    for (int mt = 0; mt < 4; mt++)
#pragma unroll
        for (int nt = 0; nt < 4; nt++)
#pragma unroll
            for (int r = 0; r < 4; r++) acc[mt][nt][r] = 0.0f;

#define ISSUE(slice) { \
        int s_ = (slice) % 3; \
        cpa16(sA[s_] + d0, Ab + (size_t)fr        * DD + (slice) * 32 + fch); \
        cpa16(sA[s_] + d1, Ab + (size_t)(fr + 64) * DD + (slice) * 32 + fch); \
        cpa16(sW[s_] + d0, Wb + (size_t)fr        * DD + (slice) * 32 + fch); \
        cpa16(sW[s_] + d1, Wb + (size_t)(fr + 64) * DD + (slice) * 32 + fch); \
        cpa_commit(); }

    ISSUE(0);
    ISSUE(1);

    for (int kt = 0; kt < 32; kt++) {           // 32 slices of k=32
        if (kt < 31) cpa_wait<1>(); else cpa_wait<0>();
        __syncthreads();
        if (kt + 2 < 32) ISSUE(kt + 2);         // refill stage (kt-1)%3 (safe post-sync)

        const int s = kt % 3;
#pragma unroll
        for (int ks = 0; ks < 2; ks++) {
            uint32_t af[4][4], bf[4][2];
#pragma unroll
            for (int mt = 0; mt < 4; mt++)
                ldsm_x4(af[mt], sA[s] +
                        ((uint32_t)((wm * 64 + mt * 16 + aRow) * GSTRIDE + ks * 16 + aK) << 1));
#pragma unroll
            for (int p = 0; p < 2; p++) {
                uint32_t t4[4];
                ldsm_x4(t4, sW[s] +
                        ((uint32_t)((wn * 32 + p * 16 + bRow16) * GSTRIDE + ks * 16 + bCol) << 1));
                bf[p * 2][0] = t4[0]; bf[p * 2][1] = t4[1];
                bf[p * 2 + 1][0] = t4[2]; bf[p * 2 + 1][1] = t4[3];
            }
#pragma unroll
            for (int mt = 0; mt < 4; mt++)
#pragma unroll
                for (int nt = 0; nt < 4; nt++)
                    mma16(acc[mt][nt], af[mt], bf[nt]);
        }
    }
#undef ISSUE

    // Epilogue
#pragma unroll
    for (int mt = 0; mt < 4; mt++) {
#pragma unroll
        for (int nt = 0; nt < 4; nt++) {
            int m0 = blockIdx.y * 128 + wm * 64 + mt * 16 + lr;
            int n0 = blockIdx.x * 128 + wn * 32 + nt * 8 + 2 * lc;
            float bx = bias[n0], by = bias[n0 + 1];
            float v00 = acc[mt][nt][0] + bx, v01 = acc[mt][nt][1] + by;
            float v10 = acc[mt][nt][2] + bx, v11 = acc[mt][nt][3] + by;
            if (head_layout) {
                __half* C = (__half*)Cv;
                int hI = n0 >> 6, hd = n0 & 63;
                int bI0 = m0 >> 10, sI0 = m0 & 1023;
                int m1 = m0 + 8;
                int bI1 = m1 >> 10, sI1 = m1 & 1023;
                *(uint32_t*)(C + (((size_t)(bI0 * HH + hI) * SS + sI0) * HD + hd)) = f2h2(v00, v01);
                *(uint32_t*)(C + (((size_t)(bI1 * HH + hI) * SS + sI1) * HD + hd)) = f2h2(v10, v11);
            } else {
                float* C = (float*)Cv;
                *(float2*)(C + (size_t)m0 * DD + n0) = make_float2(v00, v01);
                *(float2*)(C + (size_t)(m0 + 8) * DD + n0) = make_float2(v10, v11);
            }
        }
    }
}

// ---------------------------------------------------------------------------
// Flash attention (R8 structure; syn pre-scaled by beta2 in prep)
// ---------------------------------------------------------------------------
__global__ __launch_bounds__(256, 2) void attn_f16(
    const __half* __restrict__ gq, const __half* __restrict__ gk,
    const __half* __restrict__ gv, const uint32_t* __restrict__ maskw,
    const __half* __restrict__ synh, const float* __restrict__ alpha_param,
    __half* __restrict__ out)
{
    __shared__ __align__(16) __half KV[4][64 * 72];
    __half* Ks0 = KV[0];
    __half* Ks1 = KV[1];
    __half* Vs0 = KV[2];
    __half* Vs1 = KV[3];

    const int tid  = threadIdx.x;
    const int lane = tid & 31;
    const int warp = tid >> 5;
    const int lr   = lane >> 2;
    const int lc   = lane & 3;
    const int aRow = lane & 15;
    const int aK   = (lane >> 4) * 8;
    const int bRow = lane & 7;
    const int bK   = ((lane >> 3) & 1) * 8;
    const int b = blockIdx.y >> 4;
    const int h = blockIdx.y & 15;
    const int qbase = blockIdx.x * 128;
    const int rb = warp * 16;

    const uint32_t KsA[2] = { smem_u32(Ks0), smem_u32(Ks1) };
    const uint32_t VsA[2] = { smem_u32(Vs0), smem_u32(Vs1) };

    const float alpha = 1.0f / (1.0f + __expf(-alpha_param[0]));
    const float sA2   = alpha * 0.125f * 1.4426950408889634f;

    const __half* qptr = gq + ((size_t)(b * HH + h) * SS + qbase) * HD;
    const __half* kptr = gk + (size_t)(b * HH + h) * SS * HD;
    const __half* vptr = gv + (size_t)(b * HH + h) * SS * HD;

    const int tr = tid >> 4;
    const int tc = (tid & 15) * 4;

    // Stage Q through Ks0||Ks1, grab fragments
    {
        __half* Qstage = Ks0;
#pragma unroll
        for (int i = 0; i < 8; i++) {
            int id = tid + i * 256;
            int r  = id >> 4;
            int c4 = (id & 15) * 4;
            *(uint2*)&Qstage[r * 72 + c4] = *(const uint2*)(qptr + (size_t)r * HD + c4);
        }
    }
    __syncthreads();

    uint32_t qf[4][4];
#pragma unroll
    for (int kk = 0; kk < 4; kk++)
        ldsm_x4(qf[kk], KsA[0] + ((uint32_t)((rb + aRow) * 72 + kk * 16 + aK) << 1));
    __syncthreads();

#pragma unroll
    for (int i = 0; i < 4; i++) {
        int r = tr + i * 16;
        *(uint2*)&Ks0[r * 72 + tc] = *(const uint2*)(kptr + (size_t)r * HD + tc);
        *(uint2*)&Vs0[r * 72 + tc] = *(const uint2*)(vptr + (size_t)r * HD + tc);
    }
    __syncthreads();

    float O[8][4];
#pragma unroll
    for (int nt = 0; nt < 8; nt++)
#pragma unroll
        for (int r = 0; r < 4; r++) O[nt][r] = 0.0f;
    float m0r = -INFINITY, m1r = -INFINITY, l0 = 0.0f, l1 = 0.0f;

    const int qr0 = qbase + rb + lr;
    const int qr1 = qr0 + 8;
    const uint32_t* mw0 = maskw + ((size_t)b * SS + qr0) * 32;
    const uint32_t* mw1 = maskw + ((size_t)b * SS + qr1) * 32;
    const __half* sy0p = synh + ((size_t)h * SS + qr0) * SS;
    const __half* sy1p = synh + ((size_t)h * SS + qr1) * SS;

    int cur = 0;
    for (int kb = 0; kb < SS; kb += 64) {
        const bool more = (kb + 64) < SS;
        __half* Kn = cur ? Ks0 : Ks1;
        __half* Vn = cur ? Vs0 : Vs1;

        uint2 st0, st1, st2, st3;
        if (more) {
            const __half* kp = kptr + (size_t)(kb + 64) * HD;
            st0 = *(const uint2*)(kp + (size_t)(tr)      * HD + tc);
            st1 = *(const uint2*)(kp + (size_t)(tr + 16) * HD + tc);
            st2 = *(const uint2*)(kp + (size_t)(tr + 32) * HD + tc);
            st3 = *(const uint2*)(kp + (size_t)(tr + 48) * HD + tc);
        }

        float sacc[8][4];
#pragma unroll
        for (int nt = 0; nt < 8; nt++) {
            sacc[nt][0] = sacc[nt][1] = sacc[nt][2] = sacc[nt][3] = 0.0f;
#pragma unroll
            for (int kk = 0; kk < 4; kk++) {
                uint32_t bfr[2];
                ldsm_x2(bfr, KsA[cur] +
                        ((uint32_t)((nt * 8 + bRow) * 72 + kk * 16 + bK) << 1));
                mma16(sacc[nt], qf[kk], bfr);
            }
        }

        if (more) {
            *(uint2*)&Kn[(tr)      * 72 + tc] = st0;
            *(uint2*)&Kn[(tr + 16) * 72 + tc] = st1;
            *(uint2*)&Kn[(tr + 32) * 72 + tc] = st2;
            *(uint2*)&Kn[(tr + 48) * 72 + tc] = st3;
            const __half* vp = vptr + (size_t)(kb + 64) * HD;
            st0 = *(const uint2*)(vp + (size_t)(tr)      * HD + tc);
            st1 = *(const uint2*)(vp + (size_t)(tr + 16) * HD + tc);
            st2 = *(const uint2*)(vp + (size_t)(tr + 32) * HD + tc);
            st3 = *(const uint2*)(vp + (size_t)(tr + 48) * HD + tc);
        }

        const uint32_t w0a = mw0[kb >> 5], w0b = mw0[(kb >> 5) + 1];
        const uint32_t w1a = mw1[kb >> 5], w1b = mw1[(kb >> 5) + 1];
        float mx0 = -INFINITY, mx1 = -INFINITY;
#pragma unroll
        for (int nt = 0; nt < 8; nt++) {
            const int pos = nt * 8 + 2 * lc;
            const int sh  = pos & 31;
            const uint32_t wr0 = (nt < 4) ? w0a : w0b;
            const uint32_t wr1 = (nt < 4) ? w1a : w1b;
            float2 sy0 = __half22float2(*(const __half2*)(sy0p + kb + pos));
            float2 sy1 = __half22float2(*(const __half2*)(sy1p + kb + pos));
            sacc[nt][0] = ((wr0 >> sh) & 1u)       ? fmaf(sacc[nt][0], sA2, sy0.x) : -1.0e9f;
            sacc[nt][1] = ((wr0 >> (sh + 1)) & 1u) ? fmaf(sacc[nt][1], sA2, sy0.y) : -1.0e9f;
            sacc[nt][2] = ((wr1 >> sh) & 1u)       ? fmaf(sacc[nt][2], sA2, sy1.x) : -1.0e9f;
            sacc[nt][3] = ((wr1 >> (sh + 1)) & 1u) ? fmaf(sacc[nt][3], sA2, sy1.y) : -1.0e9f;
            mx0 = fmaxf(mx0, fmaxf(sacc[nt][0], sacc[nt][1]));
            mx1 = fmaxf(mx1, fmaxf(sacc[nt][2], sacc[nt][3]));
        }
        mx0 = fmaxf(mx0, __shfl_xor_sync(0xffffffffu, mx0, 1));
        mx0 = fmaxf(mx0, __shfl_xor_sync(0xffffffffu, mx0, 2));
        mx1 = fmaxf(mx1, __shfl_xor_sync(0xffffffffu, mx1, 1));
        mx1 = fmaxf(mx1, __shfl_xor_sync(0xffffffffu, mx1, 2));

        float mn0 = fmaxf(m0r, mx0), mn1 = fmaxf(m1r, mx1);
        float sc0 = exp2f(m0r - mn0), sc1 = exp2f(m1r - mn1);
        m0r = mn0; m1r = mn1;

        uint32_t pf[4][4];
        float rs0 = 0.0f, rs1 = 0.0f;
#pragma unroll
        for (int nt = 0; nt < 8; nt++) {
            float p0 = exp2f(sacc[nt][0] - mn0);
            float p1 = exp2f(sacc[nt][1] - mn0);
            float p2 = exp2f(sacc[nt][2] - mn1);
            float p3 = exp2f(sacc[nt][3] - mn1);
            rs0 += p0 + p1;
            rs1 += p2 + p3;
            pf[nt >> 1][(nt & 1) * 2 + 0] = f2h2(p0, p1);
            pf[nt >> 1][(nt & 1) * 2 + 1] = f2h2(p2, p3);
        }
        rs0 += __shfl_xor_sync(0xffffffffu, rs0, 1);
        rs0 += __shfl_xor_sync(0xffffffffu, rs0, 2);
        rs1 += __shfl_xor_sync(0xffffffffu, rs1, 1);
        rs1 += __shfl_xor_sync(0xffffffffu, rs1, 2);
        l0 = l0 * sc0 + rs0;
        l1 = l1 * sc1 + rs1;

#pragma unroll
        for (int nt = 0; nt < 8; nt++) {
            O[nt][0] *= sc0; O[nt][1] *= sc0;
            O[nt][2] *= sc1; O[nt][3] *= sc1;
        }

#pragma unroll
        for (int j = 0; j < 4; j++) {
#pragma unroll
            for (int nt = 0; nt < 8; nt++) {
                uint32_t bfr[2];
                ldsm_x2t(bfr, VsA[cur] +
                         ((uint32_t)((j * 16 + aRow) * 72 + nt * 8) << 1));
                mma16(O[nt], pf[j], bfr);
            }
        }

        if (more) {
            *(uint2*)&Vn[(tr)      * 72 + tc] = st0;
            *(uint2*)&Vn[(tr + 16) * 72 + tc] = st1;
            *(uint2*)&Vn[(tr + 32) * 72 + tc] = st2;
            *(uint2*)&Vn[(tr + 48) * 72 + tc] = st3;
        }
        __syncthreads();
        cur ^= 1;
    }

    float inv0 = 1.0f / l0, inv1 = 1.0f / l1;
    __half* o0 = out + ((size_t)b * SS + qr0) * DD + h * HD;
    __half* o1 = out + ((size_t)b * SS + qr1) * DD + h * HD;
#pragma unroll
    for (int nt = 0; nt < 8; nt++) {
        int c = nt * 8 + 2 * lc;
        *(uint32_t*)(o0 + c) = f2h2(O[nt][0] * inv0, O[nt][1] * inv0);
        *(uint32_t*)(o1 + c) = f2h2(O[nt][2] * inv1, O[nt][3] * inv1);
    }
}

// ---------------------------------------------------------------------------
extern "C" void kernel_launch(void* const* d_in, const int* in_sizes, int n_in,
                              void* d_out, int out_size)
{
    const float* query  = (const float*)d_in[0];
    const float* key_in = (const float*)d_in[1];
    const float* value  = (const float*)d_in[2];
    const int*   mask   = (const int*)d_in[3];
    const float* Wq = (const float*)d_in[4];
    const float* bq = (const float*)d_in[5];
    const float* Wk = (const float*)d_in[6];
    const float* bk = (const float*)d_in[7];
    const float* Wv = (const float*)d_in[8];
    const float* bv = (const float*)d_in[9];
    const float* Wo = (const float*)d_in[10];
    const float* bo = (const float*)d_in[11];
    const float* syn = (const float*)d_in[12];
    const float* alpha_param = (const float*)d_in[13];
    float* out = (float*)d_out;

    __half *pq, *pk, *pv, *paoh, *psynh, *pqin, *pkin, *pvin, *pwq, *pwk, *pwv, *pwo;
    uint32_t *pmw;
    cudaGetSymbolAddress((void**)&pq, g_q);
    cudaGetSymbolAddress((void**)&pk, g_k);
    cudaGetSymbolAddress((void**)&pv, g_v);
    cudaGetSymbolAddress((void**)&paoh, g_aoh);
    cudaGetSymbolAddress((void**)&pmw, g_maskw);
    cudaGetSymbolAddress((void**)&psynh, g_synh);
    cudaGetSymbolAddress((void**)&pqin, g_qin);
    cudaGetSymbolAddress((void**)&pkin, g_kin);
    cudaGetSymbolAddress((void**)&pvin, g_vin);
    cudaGetSymbolAddress((void**)&pwq, g_wq);
    cudaGetSymbolAddress((void**)&pwk, g_wk);
    cudaGetSymbolAddress((void**)&pwv, g_wv);
    cudaGetSymbolAddress((void**)&pwo, g_wo);

    // Prep: 4 launches total
    pack_mask<<<(BB * SS * (SS / 32)) / 256, 256>>>(mask, pmw);
    syn_prep<<<(HH * SS * SS / 4) / 256, 256>>>(syn, alpha_param, psynh);
    conv_acts<<<dim3((BB * SS * DD) / 4 / 256, 3), 256>>>(query, key_in, value,
                                                          pqin, pkin, pvin);
    conv_w<<<dim3((DD * DD) / 4 / 256, 4), 256>>>(Wq, Wk, Wv, Wo,
                                                  pwq, pwk, pwv, pwo);

    dim3 gg(DD / 128, (BB * SS) / 128);   // (8, 64)
    const int gemm_smem = 3 * 2 * GSTAGE_H * (int)sizeof(__half);   // 61440
    cudaFuncSetAttribute(gemm_h,
                         cudaFuncAttributeMaxDynamicSharedMemorySize, gemm_smem);

    gemm_h<<<gg, 256, gemm_smem>>>(pqin, pwq, bq, pq, 1);
    gemm_h<<<gg, 256, gemm_smem>>>(pkin, pwk, bk, pk, 1);
    gemm_h<<<gg, 256, gemm_smem>>>(pvin, pwv, bv, pv, 1);

    attn_f16<<<dim3(SS / 128, BB * HH), 256>>>(
        pq, pk, pv, pmw, psynh, alpha_param, paoh);

    gemm_h<<<gg, 256, gemm_smem>>>(paoh, pwo, bo, out, 0);
}

// round 10
// speedup vs baseline: 6.3196x; 1.0965x over previous
#include <cuda_runtime.h>
#include <cuda_fp16.h>
#include <math.h>
#include <stdint.h>

#define BB 8
#define SS 1024
#define DD 1024
#define HH 16
#define HD 64

// Scratch (device globals: allocation-free rule workaround)
__device__ __half   g_q[(size_t)BB * SS * DD];
__device__ __half   g_k[(size_t)BB * SS * DD];
__device__ __half   g_v[(size_t)BB * SS * DD];
__device__ __half   g_aoh[(size_t)BB * SS * DD];
__device__ uint32_t g_maskw[(size_t)BB * SS * (SS / 32)];
__device__ __half   g_synh[(size_t)HH * SS * SS];
__device__ __half   g_qin[(size_t)BB * SS * DD];
__device__ __half   g_kin[(size_t)BB * SS * DD];
__device__ __half   g_vin[(size_t)BB * SS * DD];
__device__ __half   g_wq[(size_t)DD * DD];
__device__ __half   g_wk[(size_t)DD * DD];
__device__ __half   g_wv[(size_t)DD * DD];
__device__ __half   g_wo[(size_t)DD * DD];

__device__ __forceinline__ uint32_t smem_u32(const void* p) {
    uint32_t a;
    asm("{ .reg .u64 t; cvta.to.shared.u64 t, %1; cvt.u32.u64 %0, t; }" : "=r"(a) : "l"(p));
    return a;
}
__device__ __forceinline__ uint32_t f2h2(float lo, float hi) {
    __half2 h = __floats2half2_rn(lo, hi);
    return *(uint32_t*)&h;
}
__device__ __forceinline__ uint2 f4h(float4 t) {
    return make_uint2(f2h2(t.x, t.y), f2h2(t.z, t.w));
}

__device__ __forceinline__ void mma16(float* d, const uint32_t* a, const uint32_t* b) {
    asm volatile(
        "mma.sync.aligned.m16n8k16.row.col.f32.f16.f16.f32 "
        "{%0,%1,%2,%3}, {%4,%5,%6,%7}, {%8,%9}, {%0,%1,%2,%3};"
        : "+f"(d[0]), "+f"(d[1]), "+f"(d[2]), "+f"(d[3])
        : "r"(a[0]), "r"(a[1]), "r"(a[2]), "r"(a[3]), "r"(b[0]), "r"(b[1]));
}
__device__ __forceinline__ void ldsm_x4(uint32_t* r, uint32_t addr) {
    asm volatile("ldmatrix.sync.aligned.m8n8.x4.shared.b16 {%0,%1,%2,%3}, [%4];"
                 : "=r"(r[0]), "=r"(r[1]), "=r"(r[2]), "=r"(r[3]) : "r"(addr));
}
__device__ __forceinline__ void ldsm_x4t(uint32_t* r, uint32_t addr) {
    asm volatile("ldmatrix.sync.aligned.m8n8.x4.trans.shared.b16 {%0,%1,%2,%3}, [%4];"
                 : "=r"(r[0]), "=r"(r[1]), "=r"(r[2]), "=r"(r[3]) : "r"(addr));
}
__device__ __forceinline__ void cpa16(uint32_t dst, const void* src) {
    asm volatile("cp.async.cg.shared.global [%0], [%1], 16;"
                 :: "r"(dst), "l"(src) : "memory");
}
__device__ __forceinline__ void cpa_commit() {
    asm volatile("cp.async.commit_group;" ::: "memory");
}
template <int N> __device__ __forceinline__ void cpa_wait() {
    asm volatile("cp.async.wait_group %0;" :: "n"(N) : "memory");
}

// ---------------------------------------------------------------------------
// Prep kernels (4 float4 per thread for MLP)
// ---------------------------------------------------------------------------
__global__ __launch_bounds__(256) void pack_mask(const int* __restrict__ mask,
                                                 uint32_t* __restrict__ mw)
{
    const size_t w = (size_t)blockIdx.x * 256 + threadIdx.x;
    const int4* p = (const int4*)(mask + w * 32);
    uint32_t bits = 0;
#pragma unroll
    for (int i = 0; i < 8; i++) {
        int4 v = p[i];
        bits |= (v.x != 0 ? 1u : 0u) << (i * 4 + 0);
        bits |= (v.y != 0 ? 1u : 0u) << (i * 4 + 1);
        bits |= (v.z != 0 ? 1u : 0u) << (i * 4 + 2);
        bits |= (v.w != 0 ? 1u : 0u) << (i * 4 + 3);
    }
    mw[w] = bits;
}

__global__ __launch_bounds__(256) void syn_prep(const float* __restrict__ syn,
                                                const float* __restrict__ alpha_param,
                                                __half* __restrict__ out)
{
    const float alpha = 1.0f / (1.0f + __expf(-alpha_param[0]));
    const float beta2 = (1.0f - alpha) * 1.4426950408889634f;
    const size_t base = (size_t)blockIdx.x * 1024 + threadIdx.x;
    float4 t[4];
#pragma unroll
    for (int j = 0; j < 4; j++) t[j] = *(const float4*)(syn + (base + j * 256) * 4);
#pragma unroll
    for (int j = 0; j < 4; j++) {
        t[j].x *= beta2; t[j].y *= beta2; t[j].z *= beta2; t[j].w *= beta2;
        *(uint2*)(out + (base + j * 256) * 4) = f4h(t[j]);
    }
}

__global__ __launch_bounds__(256) void conv_acts(
    const float* __restrict__ q, const float* __restrict__ k, const float* __restrict__ v,
    __half* __restrict__ oq, __half* __restrict__ ok, __half* __restrict__ ov)
{
    const float* src = (blockIdx.y == 0) ? q : (blockIdx.y == 1) ? k : v;
    __half* dst = (blockIdx.y == 0) ? oq : (blockIdx.y == 1) ? ok : ov;
    const size_t base = (size_t)blockIdx.x * 1024 + threadIdx.x;
    float4 t[4];
#pragma unroll
    for (int j = 0; j < 4; j++) t[j] = *(const float4*)(src + (base + j * 256) * 4);
#pragma unroll
    for (int j = 0; j < 4; j++)
        *(uint2*)(dst + (base + j * 256) * 4) = f4h(t[j]);
}

__global__ __launch_bounds__(256) void conv_w(
    const float* __restrict__ wq, const float* __restrict__ wk,
    const float* __restrict__ wv, const float* __restrict__ wo,
    __half* __restrict__ oq, __half* __restrict__ ok,
    __half* __restrict__ ov, __half* __restrict__ oo)
{
    const float* src = (blockIdx.y == 0) ? wq : (blockIdx.y == 1) ? wk
                     : (blockIdx.y == 2) ? wv : wo;
    __half* dst = (blockIdx.y == 0) ? oq : (blockIdx.y == 1) ? ok
                : (blockIdx.y == 2) ? ov : oo;
    const size_t base = (size_t)blockIdx.x * 1024 + threadIdx.x;
    float4 t[4];
#pragma unroll
    for (int j = 0; j < 4; j++) t[j] = *(const float4*)(src + (base + j * 256) * 4);
#pragma unroll
    for (int j = 0; j < 4; j++)
        *(uint2*)(dst + (base + j * 256) * 4) = f4h(t[j]);
}

// ---------------------------------------------------------------------------
// GEMM (unchanged from R9): fp16 in, 3-stage cp.async, k-slice 32.
// ---------------------------------------------------------------------------
#define GSTRIDE 40
#define GSTAGE_H (128 * GSTRIDE)

__global__ __launch_bounds__(256, 2) void gemm_h(
    const __half* __restrict__ A, const __half* __restrict__ W,
    const float* __restrict__ bias, void* __restrict__ Cv, int head_layout)
{
    extern __shared__ __align__(16) __half smh[];
    const int tid  = threadIdx.x;
    const int lane = tid & 31;
    const int warp = tid >> 5;
    const int wm   = warp >> 2;
    const int wn   = warp & 3;
    const int lr   = lane >> 2;
    const int lc   = lane & 3;
    const int aRow = lane & 15;
    const int aK   = (lane >> 4) * 8;
    const int bRow16 = (lane >> 4) * 8 + (lane & 7);
    const int bCol   = ((lane >> 3) & 1) * 8;

    const int fr  = tid >> 2;
    const int fch = (tid & 3) * 8;

    const __half* Ab = A + (size_t)(blockIdx.y * 128) * DD;
    const __half* Wb = W + (size_t)(blockIdx.x * 128) * DD;

    const uint32_t base = smem_u32(smh);
    uint32_t sA[3], sW[3];
#pragma unroll
    for (int s = 0; s < 3; s++) {
        sA[s] = base + (uint32_t)(s * 2 * GSTAGE_H) * 2;
        sW[s] = base + (uint32_t)((s * 2 + 1) * GSTAGE_H) * 2;
    }
    const uint32_t d0 = (uint32_t)(fr * GSTRIDE + fch) * 2;
    const uint32_t d1 = (uint32_t)((fr + 64) * GSTRIDE + fch) * 2;

    float acc[4][4][4];
#pragma unroll
    for (int mt = 0; mt < 4; mt++)
#pragma unroll
        for (int nt = 0; nt < 4; nt++)
#pragma unroll
            for (int r = 0; r < 4; r++) acc[mt][nt][r] = 0.0f;

#define ISSUE(slice) { \
        int s_ = (slice) % 3; \
        cpa16(sA[s_] + d0, Ab + (size_t)fr        * DD + (slice) * 32 + fch); \
        cpa16(sA[s_] + d1, Ab + (size_t)(fr + 64) * DD + (slice) * 32 + fch); \
        cpa16(sW[s_] + d0, Wb + (size_t)fr        * DD + (slice) * 32 + fch); \
        cpa16(sW[s_] + d1, Wb + (size_t)(fr + 64) * DD + (slice) * 32 + fch); \
        cpa_commit(); }

    ISSUE(0);
    ISSUE(1);

    for (int kt = 0; kt < 32; kt++) {
        if (kt < 31) cpa_wait<1>(); else cpa_wait<0>();
        __syncthreads();
        if (kt + 2 < 32) ISSUE(kt + 2);

        const int s = kt % 3;
#pragma unroll
        for (int ks = 0; ks < 2; ks++) {
            uint32_t af[4][4], bf[4][2];
#pragma unroll
            for (int mt = 0; mt < 4; mt++)
                ldsm_x4(af[mt], sA[s] +
                        ((uint32_t)((wm * 64 + mt * 16 + aRow) * GSTRIDE + ks * 16 + aK) << 1));
#pragma unroll
            for (int p = 0; p < 2; p++) {
                uint32_t t4[4];
                ldsm_x4(t4, sW[s] +
                        ((uint32_t)((wn * 32 + p * 16 + bRow16) * GSTRIDE + ks * 16 + bCol) << 1));
                bf[p * 2][0] = t4[0]; bf[p * 2][1] = t4[1];
                bf[p * 2 + 1][0] = t4[2]; bf[p * 2 + 1][1] = t4[3];
            }
#pragma unroll
            for (int mt = 0; mt < 4; mt++)
#pragma unroll
                for (int nt = 0; nt < 4; nt++)
                    mma16(acc[mt][nt], af[mt], bf[nt]);
        }
    }
#undef ISSUE

#pragma unroll
    for (int mt = 0; mt < 4; mt++) {
#pragma unroll
        for (int nt = 0; nt < 4; nt++) {
            int m0 = blockIdx.y * 128 + wm * 64 + mt * 16 + lr;
            int n0 = blockIdx.x * 128 + wn * 32 + nt * 8 + 2 * lc;
            float bx = bias[n0], by = bias[n0 + 1];
            float v00 = acc[mt][nt][0] + bx, v01 = acc[mt][nt][1] + by;
            float v10 = acc[mt][nt][2] + bx, v11 = acc[mt][nt][3] + by;
            if (head_layout) {
                __half* C = (__half*)Cv;
                int hI = n0 >> 6, hd = n0 & 63;
                int bI0 = m0 >> 10, sI0 = m0 & 1023;
                int m1 = m0 + 8;
                int bI1 = m1 >> 10, sI1 = m1 & 1023;
                *(uint32_t*)(C + (((size_t)(bI0 * HH + hI) * SS + sI0) * HD + hd)) = f2h2(v00, v01);
                *(uint32_t*)(C + (((size_t)(bI1 * HH + hI) * SS + sI1) * HD + hd)) = f2h2(v10, v11);
            } else {
                float* C = (float*)Cv;
                *(float2*)(C + (size_t)m0 * DD + n0) = make_float2(v00, v01);
                *(float2*)(C + (size_t)(m0 + 8) * DD + n0) = make_float2(v10, v11);
            }
        }
    }
}

// ---------------------------------------------------------------------------
// Flash attention: cp.async KV staging, x4 ldmatrix fragments, register P.
// ---------------------------------------------------------------------------
__global__ __launch_bounds__(256, 2) void attn_f16(
    const __half* __restrict__ gq, const __half* __restrict__ gk,
    const __half* __restrict__ gv, const uint32_t* __restrict__ maskw,
    const __half* __restrict__ synh, const float* __restrict__ alpha_param,
    __half* __restrict__ out)
{
    __shared__ __align__(16) __half KV[4][64 * 72];   // K0, K1, V0, V1
    const uint32_t KsA[2] = { smem_u32(KV[0]), smem_u32(KV[1]) };
    const uint32_t VsA[2] = { smem_u32(KV[2]), smem_u32(KV[3]) };

    const int tid  = threadIdx.x;
    const int lane = tid & 31;
    const int warp = tid >> 5;
    const int lr   = lane >> 2;
    const int lc   = lane & 3;
    const int aRow = lane & 15;
    const int aK   = (lane >> 4) * 8;
    const int bRow16 = (lane >> 4) * 8 + (lane & 7);     // K x4 mapping
    const int bCol   = ((lane >> 3) & 1) * 8;
    const int vRow   = ((lane >> 3) & 1) * 8 + (lane & 7); // V x4t mapping
    const int vColH  = (lane >> 4) * 8;
    const int b = blockIdx.y >> 4;
    const int h = blockIdx.y & 15;
    const int qbase = blockIdx.x * 128;
    const int rb = warp * 16;

    const float alpha = 1.0f / (1.0f + __expf(-alpha_param[0]));
    const float sA2   = alpha * 0.125f * 1.4426950408889634f;

    const __half* qptr = gq + ((size_t)(b * HH + h) * SS + qbase) * HD;
    const __half* kptr = gk + (size_t)(b * HH + h) * SS * HD;
    const __half* vptr = gv + (size_t)(b * HH + h) * SS * HD;

    // cp.async fill geometry: 64x64 halves = 512 x 16B chunks; 2/thread/matrix
    const int c0 = tid * 2;
    const int fr0 = c0 >> 3, fc0 = (c0 & 7) * 8;
    const int fr1 = (c0 + 1) >> 3, fc1 = ((c0 + 1) & 7) * 8;

#define ISSUE_KV(i, buf) { \
        const __half* kp_ = kptr + (size_t)(i) * 64 * HD; \
        const __half* vp_ = vptr + (size_t)(i) * 64 * HD; \
        cpa16(KsA[buf] + (uint32_t)(fr0 * 72 + fc0) * 2, kp_ + (size_t)fr0 * HD + fc0); \
        cpa16(KsA[buf] + (uint32_t)(fr1 * 72 + fc1) * 2, kp_ + (size_t)fr1 * HD + fc1); \
        cpa16(VsA[buf] + (uint32_t)(fr0 * 72 + fc0) * 2, vp_ + (size_t)fr0 * HD + fc0); \
        cpa16(VsA[buf] + (uint32_t)(fr1 * 72 + fc1) * 2, vp_ + (size_t)fr1 * HD + fc1); \
        cpa_commit(); }

    // Stage Q (128x64) through KV[0]||KV[1], extract fragments
    {
        __half* Qstage = KV[0];
#pragma unroll
        for (int i = 0; i < 8; i++) {
            int id = tid + i * 256;
            int r  = id >> 4;
            int c4 = (id & 15) * 4;
            *(uint2*)&Qstage[r * 72 + c4] = *(const uint2*)(qptr + (size_t)r * HD + c4);
        }
    }
    __syncthreads();

    uint32_t qf[4][4];
#pragma unroll
    for (int kk = 0; kk < 4; kk++)
        ldsm_x4(qf[kk], KsA[0] + ((uint32_t)((rb + aRow) * 72 + kk * 16 + aK) << 1));
    __syncthreads();

    ISSUE_KV(0, 0);

    float O[8][4];
#pragma unroll
    for (int nt = 0; nt < 8; nt++)
#pragma unroll
        for (int r = 0; r < 4; r++) O[nt][r] = 0.0f;
    float m0r = -INFINITY, m1r = -INFINITY, l0 = 0.0f, l1 = 0.0f;

    const int qr0 = qbase + rb + lr;
    const int qr1 = qr0 + 8;
    const uint32_t* mw0 = maskw + ((size_t)b * SS + qr0) * 32;
    const uint32_t* mw1 = maskw + ((size_t)b * SS + qr1) * 32;
    const __half* sy0p = synh + ((size_t)h * SS + qr0) * SS;
    const __half* sy1p = synh + ((size_t)h * SS + qr1) * SS;

    int buf = 0;
    for (int it = 0; it < 16; it++) {
        const int kb = it * 64;
        cpa_wait<0>();
        __syncthreads();      // tile ready everywhere; prior iter fully done
        if (it < 15) ISSUE_KV(it + 1, buf ^ 1);

        // S = Q @ K^T  (x4 ldmatrix: two nt per LDSM)
        float sacc[8][4];
#pragma unroll
        for (int nt = 0; nt < 8; nt++)
            sacc[nt][0] = sacc[nt][1] = sacc[nt][2] = sacc[nt][3] = 0.0f;
#pragma unroll
        for (int p = 0; p < 4; p++) {
#pragma unroll
            for (int kk = 0; kk < 4; kk++) {
                uint32_t t4[4];
                ldsm_x4(t4, KsA[buf] +
                        ((uint32_t)((p * 16 + bRow16) * 72 + kk * 16 + bCol) << 1));
                mma16(sacc[p * 2],     qf[kk], t4);
                mma16(sacc[p * 2 + 1], qf[kk], t4 + 2);
            }
        }

        // Merge adapter + mask (log2 domain), running row max
        const uint32_t w0a = mw0[kb >> 5], w0b = mw0[(kb >> 5) + 1];
        const uint32_t w1a = mw1[kb >> 5], w1b = mw1[(kb >> 5) + 1];
        float mx0 = -INFINITY, mx1 = -INFINITY;
#pragma unroll
        for (int nt = 0; nt < 8; nt++) {
            const int pos = nt * 8 + 2 * lc;
            const int sh  = pos & 31;
            const uint32_t wr0 = (nt < 4) ? w0a : w0b;
            const uint32_t wr1 = (nt < 4) ? w1a : w1b;
            float2 sy0 = __half22float2(*(const __half2*)(sy0p + kb + pos));
            float2 sy1 = __half22float2(*(const __half2*)(sy1p + kb + pos));
            sacc[nt][0] = ((wr0 >> sh) & 1u)       ? fmaf(sacc[nt][0], sA2, sy0.x) : -1.0e9f;
            sacc[nt][1] = ((wr0 >> (sh + 1)) & 1u) ? fmaf(sacc[nt][1], sA2, sy0.y) : -1.0e9f;
            sacc[nt][2] = ((wr1 >> sh) & 1u)       ? fmaf(sacc[nt][2], sA2, sy1.x) : -1.0e9f;
            sacc[nt][3] = ((wr1 >> (sh + 1)) & 1u) ? fmaf(sacc[nt][3], sA2, sy1.y) : -1.0e9f;
            mx0 = fmaxf(mx0, fmaxf(sacc[nt][0], sacc[nt][1]));
            mx1 = fmaxf(mx1, fmaxf(sacc[nt][2], sacc[nt][3]));
        }
        mx0 = fmaxf(mx0, __shfl_xor_sync(0xffffffffu, mx0, 1));
        mx0 = fmaxf(mx0, __shfl_xor_sync(0xffffffffu, mx0, 2));
        mx1 = fmaxf(mx1, __shfl_xor_sync(0xffffffffu, mx1, 1));
        mx1 = fmaxf(mx1, __shfl_xor_sync(0xffffffffu, mx1, 2));

        float mn0 = fmaxf(m0r, mx0), mn1 = fmaxf(m1r, mx1);
        float sc0 = exp2f(m0r - mn0), sc1 = exp2f(m1r - mn1);
        m0r = mn0; m1r = mn1;

        uint32_t pf[4][4];
        float rs0 = 0.0f, rs1 = 0.0f;
#pragma unroll
        for (int nt = 0; nt < 8; nt++) {
            float p0 = exp2f(sacc[nt][0] - mn0);
            float p1 = exp2f(sacc[nt][1] - mn0);
            float p2 = exp2f(sacc[nt][2] - mn1);
            float p3 = exp2f(sacc[nt][3] - mn1);
            rs0 += p0 + p1;
            rs1 += p2 + p3;
            pf[nt >> 1][(nt & 1) * 2 + 0] = f2h2(p0, p1);
            pf[nt >> 1][(nt & 1) * 2 + 1] = f2h2(p2, p3);
        }
        rs0 += __shfl_xor_sync(0xffffffffu, rs0, 1);
        rs0 += __shfl_xor_sync(0xffffffffu, rs0, 2);
        rs1 += __shfl_xor_sync(0xffffffffu, rs1, 1);
        rs1 += __shfl_xor_sync(0xffffffffu, rs1, 2);
        l0 = l0 * sc0 + rs0;
        l1 = l1 * sc1 + rs1;

#pragma unroll
        for (int nt = 0; nt < 8; nt++) {
            O[nt][0] *= sc0; O[nt][1] *= sc0;
            O[nt][2] *= sc1; O[nt][3] *= sc1;
        }

        // O += P @ V   (x4.trans: two nt per LDSM)
#pragma unroll
        for (int j = 0; j < 4; j++) {
#pragma unroll
            for (int p = 0; p < 4; p++) {
                uint32_t t4[4];
                ldsm_x4t(t4, VsA[buf] +
                         ((uint32_t)((j * 16 + vRow) * 72 + p * 16 + vColH) << 1));
                mma16(O[p * 2],     pf[j], t4);
                mma16(O[p * 2 + 1], pf[j], t4 + 2);
            }
        }

        buf ^= 1;
    }
#undef ISSUE_KV

    float inv0 = 1.0f / l0, inv1 = 1.0f / l1;
    __half* o0 = out + ((size_t)b * SS + qr0) * DD + h * HD;
    __half* o1 = out + ((size_t)b * SS + qr1) * DD + h * HD;
#pragma unroll
    for (int nt = 0; nt < 8; nt++) {
        int c = nt * 8 + 2 * lc;
        *(uint32_t*)(o0 + c) = f2h2(O[nt][0] * inv0, O[nt][1] * inv0);
        *(uint32_t*)(o1 + c) = f2h2(O[nt][2] * inv1, O[nt][3] * inv1);
    }
}

// ---------------------------------------------------------------------------
extern "C" void kernel_launch(void* const* d_in, const int* in_sizes, int n_in,
                              void* d_out, int out_size)
{
    const float* query  = (const float*)d_in[0];
    const float* key_in = (const float*)d_in[1];
    const float* value  = (const float*)d_in[2];
    const int*   mask   = (const int*)d_in[3];
    const float* Wq = (const float*)d_in[4];
    const float* bq = (const float*)d_in[5];
    const float* Wk = (const float*)d_in[6];
    const float* bk = (const float*)d_in[7];
    const float* Wv = (const float*)d_in[8];
    const float* bv = (const float*)d_in[9];
    const float* Wo = (const float*)d_in[10];
    const float* bo = (const float*)d_in[11];
    const float* syn = (const float*)d_in[12];
    const float* alpha_param = (const float*)d_in[13];
    float* out = (float*)d_out;

    __half *pq, *pk, *pv, *paoh, *psynh, *pqin, *pkin, *pvin, *pwq, *pwk, *pwv, *pwo;
    uint32_t *pmw;
    cudaGetSymbolAddress((void**)&pq, g_q);
    cudaGetSymbolAddress((void**)&pk, g_k);
    cudaGetSymbolAddress((void**)&pv, g_v);
    cudaGetSymbolAddress((void**)&paoh, g_aoh);
    cudaGetSymbolAddress((void**)&pmw, g_maskw);
    cudaGetSymbolAddress((void**)&psynh, g_synh);
    cudaGetSymbolAddress((void**)&pqin, g_qin);
    cudaGetSymbolAddress((void**)&pkin, g_kin);
    cudaGetSymbolAddress((void**)&pvin, g_vin);
    cudaGetSymbolAddress((void**)&pwq, g_wq);
    cudaGetSymbolAddress((void**)&pwk, g_wk);
    cudaGetSymbolAddress((void**)&pwv, g_wv);
    cudaGetSymbolAddress((void**)&pwo, g_wo);

    // Prep
    pack_mask<<<(BB * SS * (SS / 32)) / 256, 256>>>(mask, pmw);
    syn_prep<<<(HH * SS * SS / 4) / 1024, 256>>>(syn, alpha_param, psynh);
    conv_acts<<<dim3((BB * SS * DD) / 4 / 1024, 3), 256>>>(query, key_in, value,
                                                           pqin, pkin, pvin);
    conv_w<<<dim3((DD * DD) / 4 / 1024, 4), 256>>>(Wq, Wk, Wv, Wo,
                                                   pwq, pwk, pwv, pwo);

    dim3 gg(DD / 128, (BB * SS) / 128);
    const int gemm_smem = 3 * 2 * GSTAGE_H * (int)sizeof(__half);   // 61440
    cudaFuncSetAttribute(gemm_h,
                         cudaFuncAttributeMaxDynamicSharedMemorySize, gemm_smem);

    gemm_h<<<gg, 256, gemm_smem>>>(pqin, pwq, bq, pq, 1);
    gemm_h<<<gg, 256, gemm_smem>>>(pkin, pwk, bk, pk, 1);
    gemm_h<<<gg, 256, gemm_smem>>>(pvin, pwv, bv, pv, 1);

    attn_f16<<<dim3(SS / 128, BB * HH), 256>>>(
        pq, pk, pv, pmw, psynh, alpha_param, paoh);

    gemm_h<<<gg, 256, gemm_smem>>>(paoh, pwo, bo, out, 0);
}

// round 11
// speedup vs baseline: 6.7026x; 1.0606x over previous
#include <cuda_runtime.h>
#include <cuda_fp16.h>
#include <math.h>
#include <stdint.h>

#define BB 8
#define SS 1024
#define DD 1024
#define HH 16
#define HD 64

// Scratch (device globals: allocation-free rule workaround)
__device__ __half   g_q[(size_t)BB * SS * DD];
__device__ __half   g_k[(size_t)BB * SS * DD];
__device__ __half   g_v[(size_t)BB * SS * DD];
__device__ __half   g_aoh[(size_t)BB * SS * DD];
__device__ uint32_t g_maskw[(size_t)BB * SS * (SS / 32)];
__device__ __half   g_synh[(size_t)HH * SS * SS];
__device__ __half   g_qin[(size_t)BB * SS * DD];
__device__ __half   g_kin[(size_t)BB * SS * DD];
__device__ __half   g_vin[(size_t)BB * SS * DD];
__device__ __half   g_wq[(size_t)DD * DD];
__device__ __half   g_wk[(size_t)DD * DD];
__device__ __half   g_wv[(size_t)DD * DD];
__device__ __half   g_wo[(size_t)DD * DD];

__device__ __forceinline__ uint32_t smem_u32(const void* p) {
    uint32_t a;
    asm("{ .reg .u64 t; cvta.to.shared.u64 t, %1; cvt.u32.u64 %0, t; }" : "=r"(a) : "l"(p));
    return a;
}
__device__ __forceinline__ uint32_t f2h2(float lo, float hi) {
    __half2 h = __floats2half2_rn(lo, hi);
    return *(uint32_t*)&h;
}
__device__ __forceinline__ uint2 f4h(float4 t) {
    return make_uint2(f2h2(t.x, t.y), f2h2(t.z, t.w));
}

__device__ __forceinline__ void mma16(float* d, const uint32_t* a, const uint32_t* b) {
    asm volatile(
        "mma.sync.aligned.m16n8k16.row.col.f32.f16.f16.f32 "
        "{%0,%1,%2,%3}, {%4,%5,%6,%7}, {%8,%9}, {%0,%1,%2,%3};"
        : "+f"(d[0]), "+f"(d[1]), "+f"(d[2]), "+f"(d[3])
        : "r"(a[0]), "r"(a[1]), "r"(a[2]), "r"(a[3]), "r"(b[0]), "r"(b[1]));
}
__device__ __forceinline__ void ldsm_x4(uint32_t* r, uint32_t addr) {
    asm volatile("ldmatrix.sync.aligned.m8n8.x4.shared.b16 {%0,%1,%2,%3}, [%4];"
                 : "=r"(r[0]), "=r"(r[1]), "=r"(r[2]), "=r"(r[3]) : "r"(addr));
}
__device__ __forceinline__ void ldsm_x4t(uint32_t* r, uint32_t addr) {
    asm volatile("ldmatrix.sync.aligned.m8n8.x4.trans.shared.b16 {%0,%1,%2,%3}, [%4];"
                 : "=r"(r[0]), "=r"(r[1]), "=r"(r[2]), "=r"(r[3]) : "r"(addr));
}
__device__ __forceinline__ void cpa16(uint32_t dst, const void* src) {
    asm volatile("cp.async.cg.shared.global [%0], [%1], 16;"
                 :: "r"(dst), "l"(src) : "memory");
}
__device__ __forceinline__ void cpa_commit() {
    asm volatile("cp.async.commit_group;" ::: "memory");
}
template <int N> __device__ __forceinline__ void cpa_wait() {
    asm volatile("cp.async.wait_group %0;" :: "n"(N) : "memory");
}

// ---------------------------------------------------------------------------
// Prep: pack mask (separate op) + one fused conversion kernel for 8 tensors.
// ---------------------------------------------------------------------------
__global__ __launch_bounds__(256) void pack_mask(const int* __restrict__ mask,
                                                 uint32_t* __restrict__ mw)
{
    const size_t w = (size_t)blockIdx.x * 256 + threadIdx.x;
    const int4* p = (const int4*)(mask + w * 32);
    uint32_t bits = 0;
#pragma unroll
    for (int i = 0; i < 8; i++) {
        int4 v = p[i];
        bits |= (v.x != 0 ? 1u : 0u) << (i * 4 + 0);
        bits |= (v.y != 0 ? 1u : 0u) << (i * 4 + 1);
        bits |= (v.z != 0 ? 1u : 0u) << (i * 4 + 2);
        bits |= (v.w != 0 ? 1u : 0u) << (i * 4 + 3);
    }
    mw[w] = bits;
}

// block quantum = 1024 float4.  Segment block counts:
// syn 4096 | q 2048 | k 2048 | v 2048 | wq 256 | wk 256 | wv 256 | wo 256
__global__ __launch_bounds__(256) void conv_all(
    const float* __restrict__ syn,
    const float* __restrict__ q, const float* __restrict__ k, const float* __restrict__ v,
    const float* __restrict__ wq, const float* __restrict__ wk,
    const float* __restrict__ wv, const float* __restrict__ wo,
    const float* __restrict__ alpha_param,
    __half* __restrict__ osyn,
    __half* __restrict__ oq, __half* __restrict__ ok, __half* __restrict__ ov,
    __half* __restrict__ owq, __half* __restrict__ owk,
    __half* __restrict__ owv, __half* __restrict__ owo)
{
    const int blk = blockIdx.x;
    const float* src;
    __half* dst;
    size_t off;
    bool scale = false;
    if (blk < 4096)       { src = syn; dst = osyn; off = (size_t)blk * 1024; scale = true; }
    else if (blk < 6144)  { src = q;   dst = oq;   off = (size_t)(blk - 4096) * 1024; }
    else if (blk < 8192)  { src = k;   dst = ok;   off = (size_t)(blk - 6144) * 1024; }
    else if (blk < 10240) { src = v;   dst = ov;   off = (size_t)(blk - 8192) * 1024; }
    else if (blk < 10496) { src = wq;  dst = owq;  off = (size_t)(blk - 10240) * 1024; }
    else if (blk < 10752) { src = wk;  dst = owk;  off = (size_t)(blk - 10496) * 1024; }
    else if (blk < 11008) { src = wv;  dst = owv;  off = (size_t)(blk - 10752) * 1024; }
    else                  { src = wo;  dst = owo;  off = (size_t)(blk - 11008) * 1024; }

    float mult = 1.0f;
    if (scale) {
        float alpha = 1.0f / (1.0f + __expf(-alpha_param[0]));
        mult = (1.0f - alpha) * 1.4426950408889634f;
    }

    const size_t base = off + threadIdx.x;
    float4 t[4];
#pragma unroll
    for (int j = 0; j < 4; j++) t[j] = *(const float4*)(src + (base + j * 256) * 4);
#pragma unroll
    for (int j = 0; j < 4; j++) {
        t[j].x *= mult; t[j].y *= mult; t[j].z *= mult; t[j].w *= mult;
        *(uint2*)(dst + (base + j * 256) * 4) = f4h(t[j]);
    }
}

// ---------------------------------------------------------------------------
// GEMM core: C = A[M,K] @ W[N,K]^T + bias.  fp16 in, 4-stage cp.async, k32.
// Block 128x128, 8 warps (2x4), warp tile 64x32, 2 CTAs/SM.
// ---------------------------------------------------------------------------
#define GSTRIDE 40
#define GSTAGE_H (128 * GSTRIDE)
#define GEMM_SMEM (4 * 2 * GSTAGE_H * 2)   // 81920 bytes

__device__ __forceinline__ void gemm_core(
    const __half* __restrict__ A, const __half* __restrict__ W,
    const float* __restrict__ bias, void* __restrict__ Cv, int head_layout,
    __half* smh, int bx, int by)
{
    const int tid  = threadIdx.x;
    const int lane = tid & 31;
    const int warp = tid >> 5;
    const int wm   = warp >> 2;
    const int wn   = warp & 3;
    const int lr   = lane >> 2;
    const int lc   = lane & 3;
    const int aRow = lane & 15;
    const int aK   = (lane >> 4) * 8;
    const int bRow16 = (lane >> 4) * 8 + (lane & 7);
    const int bCol   = ((lane >> 3) & 1) * 8;

    const int fr  = tid >> 2;
    const int fch = (tid & 3) * 8;

    const __half* Ab = A + (size_t)(by * 128) * DD;
    const __half* Wb = W + (size_t)(bx * 128) * DD;

    const uint32_t base = smem_u32(smh);
    uint32_t sA[4], sW[4];
#pragma unroll
    for (int s = 0; s < 4; s++) {
        sA[s] = base + (uint32_t)(s * 2 * GSTAGE_H) * 2;
        sW[s] = base + (uint32_t)((s * 2 + 1) * GSTAGE_H) * 2;
    }
    const uint32_t d0 = (uint32_t)(fr * GSTRIDE + fch) * 2;
    const uint32_t d1 = (uint32_t)((fr + 64) * GSTRIDE + fch) * 2;

    float acc[4][4][4];
#pragma unroll
    for (int mt = 0; mt < 4; mt++)
#pragma unroll
        for (int nt = 0; nt < 4; nt++)
#pragma unroll
            for (int r = 0; r < 4; r++) acc[mt][nt][r] = 0.0f;

#define ISSUE(slice) { \
        int s_ = (slice) & 3; \
        cpa16(sA[s_] + d0, Ab + (size_t)fr        * DD + (slice) * 32 + fch); \
        cpa16(sA[s_] + d1, Ab + (size_t)(fr + 64) * DD + (slice) * 32 + fch); \
        cpa16(sW[s_] + d0, Wb + (size_t)fr        * DD + (slice) * 32 + fch); \
        cpa16(sW[s_] + d1, Wb + (size_t)(fr + 64) * DD + (slice) * 32 + fch); \
        cpa_commit(); }

    ISSUE(0);
    ISSUE(1);
    ISSUE(2);

    for (int kt = 0; kt < 32; kt++) {
        if (kt <= 29)      cpa_wait<2>();
        else if (kt == 30) cpa_wait<1>();
        else               cpa_wait<0>();
        __syncthreads();
        if (kt + 3 < 32) ISSUE(kt + 3);

        const int s = kt & 3;
#pragma unroll
        for (int ks = 0; ks < 2; ks++) {
            uint32_t af[4][4], bf[4][2];
#pragma unroll
            for (int mt = 0; mt < 4; mt++)
                ldsm_x4(af[mt], sA[s] +
                        ((uint32_t)((wm * 64 + mt * 16 + aRow) * GSTRIDE + ks * 16 + aK) << 1));
#pragma unroll
            for (int p = 0; p < 2; p++) {
                uint32_t t4[4];
                ldsm_x4(t4, sW[s] +
                        ((uint32_t)((wn * 32 + p * 16 + bRow16) * GSTRIDE + ks * 16 + bCol) << 1));
                bf[p * 2][0] = t4[0]; bf[p * 2][1] = t4[1];
                bf[p * 2 + 1][0] = t4[2]; bf[p * 2 + 1][1] = t4[3];
            }
#pragma unroll
            for (int mt = 0; mt < 4; mt++)
#pragma unroll
                for (int nt = 0; nt < 4; nt++)
                    mma16(acc[mt][nt], af[mt], bf[nt]);
        }
    }
#undef ISSUE

#pragma unroll
    for (int mt = 0; mt < 4; mt++) {
#pragma unroll
        for (int nt = 0; nt < 4; nt++) {
            int m0 = by * 128 + wm * 64 + mt * 16 + lr;
            int n0 = bx * 128 + wn * 32 + nt * 8 + 2 * lc;
            float bxv = bias[n0], byv = bias[n0 + 1];
            float v00 = acc[mt][nt][0] + bxv, v01 = acc[mt][nt][1] + byv;
            float v10 = acc[mt][nt][2] + bxv, v11 = acc[mt][nt][3] + byv;
            if (head_layout) {
                __half* C = (__half*)Cv;
                int hI = n0 >> 6, hd = n0 & 63;
                int bI0 = m0 >> 10, sI0 = m0 & 1023;
                int m1 = m0 + 8;
                int bI1 = m1 >> 10, sI1 = m1 & 1023;
                *(uint32_t*)(C + (((size_t)(bI0 * HH + hI) * SS + sI0) * HD + hd)) = f2h2(v00, v01);
                *(uint32_t*)(C + (((size_t)(bI1 * HH + hI) * SS + sI1) * HD + hd)) = f2h2(v10, v11);
            } else {
                float* C = (float*)Cv;
                *(float2*)(C + (size_t)m0 * DD + n0) = make_float2(v00, v01);
                *(float2*)(C + (size_t)(m0 + 8) * DD + n0) = make_float2(v10, v11);
            }
        }
    }
}

// Merged Q/K/V projection: blockIdx.z selects tensor set.
__global__ __launch_bounds__(256, 2) void gemm_qkv(
    const __half* __restrict__ qin, const __half* __restrict__ kin,
    const __half* __restrict__ vin,
    const __half* __restrict__ wq, const __half* __restrict__ wk,
    const __half* __restrict__ wv,
    const float* __restrict__ bq, const float* __restrict__ bk,
    const float* __restrict__ bv,
    __half* __restrict__ oq, __half* __restrict__ ok, __half* __restrict__ ov)
{
    extern __shared__ __align__(16) __half smh[];
    const int z = blockIdx.z;
    const __half* A = (z == 0) ? qin : (z == 1) ? kin : vin;
    const __half* W = (z == 0) ? wq  : (z == 1) ? wk  : wv;
    const float* bias = (z == 0) ? bq : (z == 1) ? bk : bv;
    __half* C = (z == 0) ? oq : (z == 1) ? ok : ov;
    gemm_core(A, W, bias, C, 1, smh, blockIdx.x, blockIdx.y);
}

// Output projection (fp32 out).
__global__ __launch_bounds__(256, 2) void gemm_o(
    const __half* __restrict__ A, const __half* __restrict__ W,
    const float* __restrict__ bias, float* __restrict__ C)
{
    extern __shared__ __align__(16) __half smh[];
    gemm_core(A, W, bias, C, 0, smh, blockIdx.x, blockIdx.y);
}

// ---------------------------------------------------------------------------
// Flash attention (unchanged from R10)
// ---------------------------------------------------------------------------
__global__ __launch_bounds__(256, 2) void attn_f16(
    const __half* __restrict__ gq, const __half* __restrict__ gk,
    const __half* __restrict__ gv, const uint32_t* __restrict__ maskw,
    const __half* __restrict__ synh, const float* __restrict__ alpha_param,
    __half* __restrict__ out)
{
    __shared__ __align__(16) __half KV[4][64 * 72];
    const uint32_t KsA[2] = { smem_u32(KV[0]), smem_u32(KV[1]) };
    const uint32_t VsA[2] = { smem_u32(KV[2]), smem_u32(KV[3]) };

    const int tid  = threadIdx.x;
    const int lane = tid & 31;
    const int warp = tid >> 5;
    const int lr   = lane >> 2;
    const int lc   = lane & 3;
    const int aRow = lane & 15;
    const int aK   = (lane >> 4) * 8;
    const int bRow16 = (lane >> 4) * 8 + (lane & 7);
    const int bCol   = ((lane >> 3) & 1) * 8;
    const int vRow   = ((lane >> 3) & 1) * 8 + (lane & 7);
    const int vColH  = (lane >> 4) * 8;
    const int b = blockIdx.y >> 4;
    const int h = blockIdx.y & 15;
    const int qbase = blockIdx.x * 128;
    const int rb = warp * 16;

    const float alpha = 1.0f / (1.0f + __expf(-alpha_param[0]));
    const float sA2   = alpha * 0.125f * 1.4426950408889634f;

    const __half* qptr = gq + ((size_t)(b * HH + h) * SS + qbase) * HD;
    const __half* kptr = gk + (size_t)(b * HH + h) * SS * HD;
    const __half* vptr = gv + (size_t)(b * HH + h) * SS * HD;

    const int c0 = tid * 2;
    const int fr0 = c0 >> 3, fc0 = (c0 & 7) * 8;
    const int fr1 = (c0 + 1) >> 3, fc1 = ((c0 + 1) & 7) * 8;

#define ISSUE_KV(i, buf) { \
        const __half* kp_ = kptr + (size_t)(i) * 64 * HD; \
        const __half* vp_ = vptr + (size_t)(i) * 64 * HD; \
        cpa16(KsA[buf] + (uint32_t)(fr0 * 72 + fc0) * 2, kp_ + (size_t)fr0 * HD + fc0); \
        cpa16(KsA[buf] + (uint32_t)(fr1 * 72 + fc1) * 2, kp_ + (size_t)fr1 * HD + fc1); \
        cpa16(VsA[buf] + (uint32_t)(fr0 * 72 + fc0) * 2, vp_ + (size_t)fr0 * HD + fc0); \
        cpa16(VsA[buf] + (uint32_t)(fr1 * 72 + fc1) * 2, vp_ + (size_t)fr1 * HD + fc1); \
        cpa_commit(); }

    {
        __half* Qstage = KV[0];
#pragma unroll
        for (int i = 0; i < 8; i++) {
            int id = tid + i * 256;
            int r  = id >> 4;
            int c4 = (id & 15) * 4;
            *(uint2*)&Qstage[r * 72 + c4] = *(const uint2*)(qptr + (size_t)r * HD + c4);
        }
    }
    __syncthreads();

    uint32_t qf[4][4];
#pragma unroll
    for (int kk = 0; kk < 4; kk++)
        ldsm_x4(qf[kk], KsA[0] + ((uint32_t)((rb + aRow) * 72 + kk * 16 + aK) << 1));
    __syncthreads();

    ISSUE_KV(0, 0);

    float O[8][4];
#pragma unroll
    for (int nt = 0; nt < 8; nt++)
#pragma unroll
        for (int r = 0; r < 4; r++) O[nt][r] = 0.0f;
    float m0r = -INFINITY, m1r = -INFINITY, l0 = 0.0f, l1 = 0.0f;

    const int qr0 = qbase + rb + lr;
    const int qr1 = qr0 + 8;
    const uint32_t* mw0 = maskw + ((size_t)b * SS + qr0) * 32;
    const uint32_t* mw1 = maskw + ((size_t)b * SS + qr1) * 32;
    const __half* sy0p = synh + ((size_t)h * SS + qr0) * SS;
    const __half* sy1p = synh + ((size_t)h * SS + qr1) * SS;

    int buf = 0;
    for (int it = 0; it < 16; it++) {
        const int kb = it * 64;
        cpa_wait<0>();
        __syncthreads();
        if (it < 15) ISSUE_KV(it + 1, buf ^ 1);

        float sacc[8][4];
#pragma unroll
        for (int nt = 0; nt < 8; nt++)
            sacc[nt][0] = sacc[nt][1] = sacc[nt][2] = sacc[nt][3] = 0.0f;
#pragma unroll
        for (int p = 0; p < 4; p++) {
#pragma unroll
            for (int kk = 0; kk < 4; kk++) {
                uint32_t t4[4];
                ldsm_x4(t4, KsA[buf] +
                        ((uint32_t)((p * 16 + bRow16) * 72 + kk * 16 + bCol) << 1));
                mma16(sacc[p * 2],     qf[kk], t4);
                mma16(sacc[p * 2 + 1], qf[kk], t4 + 2);
            }
        }

        const uint32_t w0a = mw0[kb >> 5], w0b = mw0[(kb >> 5) + 1];
        const uint32_t w1a = mw1[kb >> 5], w1b = mw1[(kb >> 5) + 1];
        float mx0 = -INFINITY, mx1 = -INFINITY;
#pragma unroll
        for (int nt = 0; nt < 8; nt++) {
            const int pos = nt * 8 + 2 * lc;
            const int sh  = pos & 31;
            const uint32_t wr0 = (nt < 4) ? w0a : w0b;
            const uint32_t wr1 = (nt < 4) ? w1a : w1b;
            float2 sy0 = __half22float2(*(const __half2*)(sy0p + kb + pos));
            float2 sy1 = __half22float2(*(const __half2*)(sy1p + kb + pos));
            sacc[nt][0] = ((wr0 >> sh) & 1u)       ? fmaf(sacc[nt][0], sA2, sy0.x) : -1.0e9f;
            sacc[nt][1] = ((wr0 >> (sh + 1)) & 1u) ? fmaf(sacc[nt][1], sA2, sy0.y) : -1.0e9f;
            sacc[nt][2] = ((wr1 >> sh) & 1u)       ? fmaf(sacc[nt][2], sA2, sy1.x) : -1.0e9f;
            sacc[nt][3] = ((wr1 >> (sh + 1)) & 1u) ? fmaf(sacc[nt][3], sA2, sy1.y) : -1.0e9f;
            mx0 = fmaxf(mx0, fmaxf(sacc[nt][0], sacc[nt][1]));
            mx1 = fmaxf(mx1, fmaxf(sacc[nt][2], sacc[nt][3]));
        }
        mx0 = fmaxf(mx0, __shfl_xor_sync(0xffffffffu, mx0, 1));
        mx0 = fmaxf(mx0, __shfl_xor_sync(0xffffffffu, mx0, 2));
        mx1 = fmaxf(mx1, __shfl_xor_sync(0xffffffffu, mx1, 1));
        mx1 = fmaxf(mx1, __shfl_xor_sync(0xffffffffu, mx1, 2));

        float mn0 = fmaxf(m0r, mx0), mn1 = fmaxf(m1r, mx1);
        float sc0 = exp2f(m0r - mn0), sc1 = exp2f(m1r - mn1);
        m0r = mn0; m1r = mn1;

        uint32_t pf[4][4];
        float rs0 = 0.0f, rs1 = 0.0f;
#pragma unroll
        for (int nt = 0; nt < 8; nt++) {
            float p0 = exp2f(sacc[nt][0] - mn0);
            float p1 = exp2f(sacc[nt][1] - mn0);
            float p2 = exp2f(sacc[nt][2] - mn1);
            float p3 = exp2f(sacc[nt][3] - mn1);
            rs0 += p0 + p1;
            rs1 += p2 + p3;
            pf[nt >> 1][(nt & 1) * 2 + 0] = f2h2(p0, p1);
            pf[nt >> 1][(nt & 1) * 2 + 1] = f2h2(p2, p3);
        }
        rs0 += __shfl_xor_sync(0xffffffffu, rs0, 1);
        rs0 += __shfl_xor_sync(0xffffffffu, rs0, 2);
        rs1 += __shfl_xor_sync(0xffffffffu, rs1, 1);
        rs1 += __shfl_xor_sync(0xffffffffu, rs1, 2);
        l0 = l0 * sc0 + rs0;
        l1 = l1 * sc1 + rs1;

#pragma unroll
        for (int nt = 0; nt < 8; nt++) {
            O[nt][0] *= sc0; O[nt][1] *= sc0;
            O[nt][2] *= sc1; O[nt][3] *= sc1;
        }

#pragma unroll
        for (int j = 0; j < 4; j++) {
#pragma unroll
            for (int p = 0; p < 4; p++) {
                uint32_t t4[4];
                ldsm_x4t(t4, VsA[buf] +
                         ((uint32_t)((j * 16 + vRow) * 72 + p * 16 + vColH) << 1));
                mma16(O[p * 2],     pf[j], t4);
                mma16(O[p * 2 + 1], pf[j], t4 + 2);
            }
        }

        buf ^= 1;
    }
#undef ISSUE_KV

    float inv0 = 1.0f / l0, inv1 = 1.0f / l1;
    __half* o0 = out + ((size_t)b * SS + qr0) * DD + h * HD;
    __half* o1 = out + ((size_t)b * SS + qr1) * DD + h * HD;
#pragma unroll
    for (int nt = 0; nt < 8; nt++) {
        int c = nt * 8 + 2 * lc;
        *(uint32_t*)(o0 + c) = f2h2(O[nt][0] * inv0, O[nt][1] * inv0);
        *(uint32_t*)(o1 + c) = f2h2(O[nt][2] * inv1, O[nt][3] * inv1);
    }
}

// ---------------------------------------------------------------------------
extern "C" void kernel_launch(void* const* d_in, const int* in_sizes, int n_in,
                              void* d_out, int out_size)
{
    const float* query  = (const float*)d_in[0];
    const float* key_in = (const float*)d_in[1];
    const float* value  = (const float*)d_in[2];
    const int*   mask   = (const int*)d_in[3];
    const float* Wq = (const float*)d_in[4];
    const float* bq = (const float*)d_in[5];
    const float* Wk = (const float*)d_in[6];
    const float* bk = (const float*)d_in[7];
    const float* Wv = (const float*)d_in[8];
    const float* bv = (const float*)d_in[9];
    const float* Wo = (const float*)d_in[10];
    const float* bo = (const float*)d_in[11];
    const float* syn = (const float*)d_in[12];
    const float* alpha_param = (const float*)d_in[13];
    float* out = (float*)d_out;

    __half *pq, *pk, *pv, *paoh, *psynh, *pqin, *pkin, *pvin, *pwq, *pwk, *pwv, *pwo;
    uint32_t *pmw;
    cudaGetSymbolAddress((void**)&pq, g_q);
    cudaGetSymbolAddress((void**)&pk, g_k);
    cudaGetSymbolAddress((void**)&pv, g_v);
    cudaGetSymbolAddress((void**)&paoh, g_aoh);
    cudaGetSymbolAddress((void**)&pmw, g_maskw);
    cudaGetSymbolAddress((void**)&psynh, g_synh);
    cudaGetSymbolAddress((void**)&pqin, g_qin);
    cudaGetSymbolAddress((void**)&pkin, g_kin);
    cudaGetSymbolAddress((void**)&pvin, g_vin);
    cudaGetSymbolAddress((void**)&pwq, g_wq);
    cudaGetSymbolAddress((void**)&pwk, g_wk);
    cudaGetSymbolAddress((void**)&pwv, g_wv);
    cudaGetSymbolAddress((void**)&pwo, g_wo);

    // Prep: 2 launches
    pack_mask<<<(BB * SS * (SS / 32)) / 256, 256>>>(mask, pmw);
    conv_all<<<11264, 256>>>(syn, query, key_in, value, Wq, Wk, Wv, Wo,
                             alpha_param,
                             psynh, pqin, pkin, pvin, pwq, pwk, pwv, pwo);

    cudaFuncSetAttribute(gemm_qkv,
                         cudaFuncAttributeMaxDynamicSharedMemorySize, GEMM_SMEM);
    cudaFuncSetAttribute(gemm_o,
                         cudaFuncAttributeMaxDynamicSharedMemorySize, GEMM_SMEM);

    // Merged Q/K/V projections: one launch, 1536 CTAs
    gemm_qkv<<<dim3(DD / 128, (BB * SS) / 128, 3), 256, GEMM_SMEM>>>(
        pqin, pkin, pvin, pwq, pwk, pwv, bq, bk, bv, pq, pk, pv);

    attn_f16<<<dim3(SS / 128, BB * HH), 256>>>(
        pq, pk, pv, pmw, psynh, alpha_param, paoh);

    gemm_o<<<dim3(DD / 128, (BB * SS) / 128), 256, GEMM_SMEM>>>(
        paoh, pwo, bo, out);
}